// round 2
// baseline (speedup 1.0000x reference)
#include <cuda_runtime.h>
#include <math.h>

// ============================================================================
// HAN (2-layer heterogeneous GAT + semantic attention + MLP head), fp32.
// R2: MLP head collapsed algebraically: Wl1@Wl2@Wl3 precomputed on device,
//     final GEMM is 100K x 8 x 128 fused with sigmoid. Removes ~13.1 GF.
// ============================================================================

#define MAXNO 100096
#define MAXNA 50048
#define MAXE  500224

__device__ float  g_ho[MAXNO * 128];
__device__ float  g_ha[MAXNA * 128];
__device__ float  g_o0[MAXNO * 128];
__device__ float  g_o1[MAXNO * 128];
__device__ float  g_oa[MAXNA * 128];
__device__ float  g_res[MAXNO * 128];
__device__ float  g_elog[MAXE * 2];
__device__ float  g_m[MAXNO * 2];
__device__ float  g_s[MAXNO * 2];
__device__ float  g_pobj[4 * MAXNO * 2];
__device__ float  g_patt[2 * MAXNA * 2];
__device__ double g_score[2];
__device__ float  g_w[2];
// MLP collapse scratch
__device__ float  g_W12[128 * 128];
__device__ float  g_W123[128 * 8];
__device__ float  g_t1[128];
__device__ float  g_bfin[8];
__device__ float  g_zero[128];   // static zero-initialized, never written

// ---------------------------------------------------------------------------
// GEMM: C[M,N] = op(A)[M,K] @ W[K,N] + bias
// BM=128, BN=64, BK=16, 256 threads, 8x4 per-thread tile.
// ---------------------------------------------------------------------------
#define GBM 128
#define GBN 64
#define GBK 16

__global__ __launch_bounds__(256) void gemm_bias_kernel(
    const float* __restrict__ A, const float* __restrict__ W,
    const float* __restrict__ bias, float* __restrict__ C,
    int M, int N, int K, int reluIn)
{
    __shared__ float As[GBK][GBM];
    __shared__ float Bs[GBK][GBN];
    const int m0  = blockIdx.y * GBM;
    const int n0  = blockIdx.x * GBN;
    const int tid = threadIdx.x;
    const int ty  = tid >> 4;
    const int tx  = tid & 15;

    float acc[8][4];
#pragma unroll
    for (int i = 0; i < 8; i++)
#pragma unroll
        for (int j = 0; j < 4; j++) acc[i][j] = 0.f;

    for (int k0 = 0; k0 < K; k0 += GBK) {
#pragma unroll
        for (int it = 0; it < 2; it++) {
            int lin = tid + it * 256;
            int m   = lin >> 2;
            int kv  = (lin & 3) << 2;
            float4 v = make_float4(0.f, 0.f, 0.f, 0.f);
            if (m0 + m < M)
                v = *(const float4*)(A + (size_t)(m0 + m) * K + (k0 + kv));
            if (reluIn) {
                v.x = fmaxf(v.x, 0.f); v.y = fmaxf(v.y, 0.f);
                v.z = fmaxf(v.z, 0.f); v.w = fmaxf(v.w, 0.f);
            }
            As[kv + 0][m] = v.x; As[kv + 1][m] = v.y;
            As[kv + 2][m] = v.z; As[kv + 3][m] = v.w;
        }
        {
            int k  = tid >> 4;
            int nv = (tid & 15) << 2;
            float4 v = make_float4(0.f, 0.f, 0.f, 0.f);
            if (n0 + nv + 3 < N)
                v = *(const float4*)(W + (size_t)(k0 + k) * N + (n0 + nv));
            Bs[k][nv + 0] = v.x; Bs[k][nv + 1] = v.y;
            Bs[k][nv + 2] = v.z; Bs[k][nv + 3] = v.w;
        }
        __syncthreads();
#pragma unroll
        for (int k = 0; k < GBK; k++) {
            float4 a0 = *(const float4*)&As[k][ty * 8];
            float4 a1 = *(const float4*)&As[k][ty * 8 + 4];
            float4 b  = *(const float4*)&Bs[k][tx * 4];
            float a[8] = {a0.x, a0.y, a0.z, a0.w, a1.x, a1.y, a1.z, a1.w};
            float bb[4] = {b.x, b.y, b.z, b.w};
#pragma unroll
            for (int i = 0; i < 8; i++)
#pragma unroll
                for (int j = 0; j < 4; j++)
                    acc[i][j] += a[i] * bb[j];
        }
        __syncthreads();
    }
#pragma unroll
    for (int i = 0; i < 8; i++) {
        int m = m0 + ty * 8 + i;
        if (m >= M) continue;
#pragma unroll
        for (int j = 0; j < 4; j++) {
            int n = n0 + tx * 4 + j;
            if (n >= N) continue;
            C[(size_t)m * N + n] = acc[i][j] + bias[n];
        }
    }
}

// ---------------------------------------------------------------------------
// Semantic score GEMM: sum_{n,c} q[c]*tanh((relu(A)@Wk + bk)[n,c]) -> double
// ---------------------------------------------------------------------------
__global__ __launch_bounds__(256) void score_gemm_kernel(
    const float* __restrict__ A, const float* __restrict__ W,
    const float* __restrict__ bias, const float* __restrict__ q,
    int M, int N, int K, double* __restrict__ outScore)
{
    __shared__ float As[GBK][GBM];
    __shared__ float Bs[GBK][GBN];
    const int m0  = blockIdx.y * GBM;
    const int n0  = blockIdx.x * GBN;
    const int tid = threadIdx.x;
    const int ty  = tid >> 4;
    const int tx  = tid & 15;

    float acc[8][4];
#pragma unroll
    for (int i = 0; i < 8; i++)
#pragma unroll
        for (int j = 0; j < 4; j++) acc[i][j] = 0.f;

    for (int k0 = 0; k0 < K; k0 += GBK) {
#pragma unroll
        for (int it = 0; it < 2; it++) {
            int lin = tid + it * 256;
            int m   = lin >> 2;
            int kv  = (lin & 3) << 2;
            float4 v = make_float4(0.f, 0.f, 0.f, 0.f);
            if (m0 + m < M)
                v = *(const float4*)(A + (size_t)(m0 + m) * K + (k0 + kv));
            v.x = fmaxf(v.x, 0.f); v.y = fmaxf(v.y, 0.f);
            v.z = fmaxf(v.z, 0.f); v.w = fmaxf(v.w, 0.f);
            As[kv + 0][m] = v.x; As[kv + 1][m] = v.y;
            As[kv + 2][m] = v.z; As[kv + 3][m] = v.w;
        }
        {
            int k  = tid >> 4;
            int nv = (tid & 15) << 2;
            float4 v = make_float4(0.f, 0.f, 0.f, 0.f);
            if (n0 + nv + 3 < N)
                v = *(const float4*)(W + (size_t)(k0 + k) * N + (n0 + nv));
            Bs[k][nv + 0] = v.x; Bs[k][nv + 1] = v.y;
            Bs[k][nv + 2] = v.z; Bs[k][nv + 3] = v.w;
        }
        __syncthreads();
#pragma unroll
        for (int k = 0; k < GBK; k++) {
            float4 a0 = *(const float4*)&As[k][ty * 8];
            float4 a1 = *(const float4*)&As[k][ty * 8 + 4];
            float4 b  = *(const float4*)&Bs[k][tx * 4];
            float a[8] = {a0.x, a0.y, a0.z, a0.w, a1.x, a1.y, a1.z, a1.w};
            float bb[4] = {b.x, b.y, b.z, b.w};
#pragma unroll
            for (int i = 0; i < 8; i++)
#pragma unroll
                for (int j = 0; j < 4; j++)
                    acc[i][j] += a[i] * bb[j];
        }
        __syncthreads();
    }
    float local = 0.f;
#pragma unroll
    for (int i = 0; i < 8; i++) {
        int m = m0 + ty * 8 + i;
        if (m >= M) continue;
#pragma unroll
        for (int j = 0; j < 4; j++) {
            int n = n0 + tx * 4 + j;
            if (n >= N) continue;
            local += q[n] * tanhf(acc[i][j] + bias[n]);
        }
    }
    __shared__ float red[256];
    red[tid] = local;
    __syncthreads();
#pragma unroll
    for (int s2 = 128; s2 > 0; s2 >>= 1) {
        if (tid < s2) red[tid] += red[tid + s2];
        __syncthreads();
    }
    if (tid == 0) atomicAdd(outScore, (double)red[0]);
}

// ---------------------------------------------------------------------------
// Node projection (warp per node, <=4 attention vectors)
// ---------------------------------------------------------------------------
__global__ __launch_bounds__(256) void proj_kernel(
    const float* __restrict__ h, int n, int nv,
    const float* __restrict__ v0, const float* __restrict__ v1,
    const float* __restrict__ v2, const float* __restrict__ v3,
    float* __restrict__ out)
{
    int warp = (blockIdx.x * blockDim.x + threadIdx.x) >> 5;
    int lane = threadIdx.x & 31;
    if (warp >= n) return;
    const float* hr = h + (size_t)warp * 128;
    float h0 = hr[lane], h1 = hr[lane + 32], h2 = hr[lane + 64], h3 = hr[lane + 96];
    const float* vs[4] = {v0, v1, v2, v3};
#pragma unroll
    for (int v = 0; v < 4; v++) {
        if (v >= nv) break;
        const float* vv = vs[v];
        float p0 = h0 * vv[lane] + h1 * vv[lane + 32];
        float p1 = h2 * vv[lane + 64] + h3 * vv[lane + 96];
#pragma unroll
        for (int o = 16; o > 0; o >>= 1) {
            p0 += __shfl_xor_sync(0xffffffffu, p0, o);
            p1 += __shfl_xor_sync(0xffffffffu, p1, o);
        }
        if (lane == 0) {
            out[((size_t)v * n + warp) * 2 + 0] = p0;
            out[((size_t)v * n + warp) * 2 + 1] = p1;
        }
    }
}

// ---------------------------------------------------------------------------
// Segment init / edge passes
// ---------------------------------------------------------------------------
__global__ void init_seg_kernel(float* __restrict__ out, float* __restrict__ m,
                                float* __restrict__ s, int ndst)
{
    int i = blockIdx.x * blockDim.x + threadIdx.x;
    if (i < ndst * 128) out[i] = 0.f;
    if (i < ndst * 2) { m[i] = -INFINITY; s[i] = 0.f; }
}

__device__ __forceinline__ void atomicMaxFloat(float* addr, float val)
{
    if (val >= 0.f) atomicMax((int*)addr, __float_as_int(val));
    else            atomicMin((unsigned int*)addr, __float_as_uint(val));
}

__global__ __launch_bounds__(256) void edge_logits_kernel(
    const int* __restrict__ src, const int* __restrict__ dst, int E,
    const float* __restrict__ psrc, const float* __restrict__ pdst,
    float* __restrict__ elog, float* __restrict__ m)
{
    int e = blockIdx.x * blockDim.x + threadIdx.x;
    if (e >= E) return;
    int s = src[e], d = dst[e];
    float2 ps = *(const float2*)(psrc + 2 * (size_t)s);
    float2 pd = *(const float2*)(pdst + 2 * (size_t)d);
    float a0 = ps.x + pd.x; a0 = a0 > 0.f ? a0 : 0.2f * a0;
    float a1 = ps.y + pd.y; a1 = a1 > 0.f ? a1 : 0.2f * a1;
    *(float2*)(elog + 2 * (size_t)e) = make_float2(a0, a1);
    atomicMaxFloat(m + 2 * (size_t)d + 0, a0);
    atomicMaxFloat(m + 2 * (size_t)d + 1, a1);
}

__global__ __launch_bounds__(256) void edge_exp_kernel(
    const int* __restrict__ dst, int E, const float* __restrict__ m,
    float* __restrict__ elog, float* __restrict__ ssum)
{
    int e = blockIdx.x * blockDim.x + threadIdx.x;
    if (e >= E) return;
    int d = dst[e];
    float2 mv = *(const float2*)(m + 2 * (size_t)d);
    float2 ev = *(const float2*)(elog + 2 * (size_t)e);
    ev.x = expf(ev.x - mv.x);
    ev.y = expf(ev.y - mv.y);
    *(float2*)(elog + 2 * (size_t)e) = ev;
    atomicAdd(ssum + 2 * (size_t)d + 0, ev.x);
    atomicAdd(ssum + 2 * (size_t)d + 1, ev.y);
}

__global__ __launch_bounds__(256) void edge_aggregate_kernel(
    const int* __restrict__ src, const int* __restrict__ dst, int E,
    const float* __restrict__ elog, const float* __restrict__ ssum,
    const float* __restrict__ hsrc, float* __restrict__ out)
{
    int gw   = (blockIdx.x * blockDim.x + threadIdx.x) >> 5;
    int lane = threadIdx.x & 31;
    if (gw >= E) return;
    int s = src[gw], d = dst[gw];
    int head = lane >> 4;
    float el = elog[2 * (size_t)gw + head];
    float sv = ssum[2 * (size_t)d + head];
    float alpha = el / (sv + 1e-16f);
    float4 v = *(const float4*)(hsrc + (size_t)s * 128 + lane * 4);
    v.x *= alpha; v.y *= alpha; v.z *= alpha; v.w *= alpha;
    float* op = out + (size_t)d * 128 + lane * 4;
    asm volatile("red.global.add.v4.f32 [%0], {%1,%2,%3,%4};"
                 :: "l"(op), "f"(v.x), "f"(v.y), "f"(v.z), "f"(v.w)
                 : "memory");
}

// ---------------------------------------------------------------------------
// Semantic attention tail
// ---------------------------------------------------------------------------
__global__ void zero_score_kernel(double* sc) { sc[0] = 0.0; sc[1] = 0.0; }

__global__ void softmax2_kernel(const double* __restrict__ sc,
                                float* __restrict__ w, double invN)
{
    double s0 = sc[0] * invN, s1 = sc[1] * invN;
    double mx = s0 > s1 ? s0 : s1;
    double e0 = exp(s0 - mx), e1 = exp(s1 - mx);
    double sum = e0 + e1;
    w[0] = (float)(e0 / sum);
    w[1] = (float)(e1 / sum);
}

__global__ __launch_bounds__(256) void combine_kernel(
    const float* __restrict__ o0, const float* __restrict__ o1,
    const float* __restrict__ w, float* __restrict__ res, int tot)
{
    int i = blockIdx.x * blockDim.x + threadIdx.x;
    if (i >= tot) return;
    res[i] = w[0] * fmaxf(o0[i], 0.f) + w[1] * fmaxf(o1[i], 0.f);
}

// ---------------------------------------------------------------------------
// MLP collapse precompute kernels (tiny)
// ---------------------------------------------------------------------------
// t1[n] = sum_k bl1[k] * Wl2[k,n] + bl2[n]   (n<128, k<256)
__global__ void bias_t1_kernel(const float* __restrict__ bl1,
                               const float* __restrict__ Wl2,
                               const float* __restrict__ bl2,
                               float* __restrict__ t1)
{
    int n = threadIdx.x;
    float acc = bl2[n];
    for (int k = 0; k < 256; k++) acc += bl1[k] * Wl2[k * 128 + n];
    t1[n] = acc;
}

// W123[k,j] = sum_c W12[k,c] * Wl3[c,j]   (k<128, j<8, c<128)
__global__ void w123_kernel(const float* __restrict__ W12,
                            const float* __restrict__ Wl3,
                            float* __restrict__ W123)
{
    int idx = blockIdx.x * blockDim.x + threadIdx.x;   // 1024 threads
    if (idx >= 128 * 8) return;
    int k = idx >> 3, j = idx & 7;
    float acc = 0.f;
    for (int c = 0; c < 128; c++) acc += W12[k * 128 + c] * Wl3[c * 8 + j];
    W123[idx] = acc;
}

// bfin[j] = sum_c t1[c] * Wl3[c,j] + bl3[j]
__global__ void bias_fin_kernel(const float* __restrict__ t1,
                                const float* __restrict__ Wl3,
                                const float* __restrict__ bl3,
                                float* __restrict__ bfin)
{
    int j = threadIdx.x;   // 8 threads
    float acc = bl3[j];
    for (int c = 0; c < 128; c++) acc += t1[c] * Wl3[c * 8 + j];
    bfin[j] = acc;
}

// out[row,j] = sigmoid(res[row,:] @ W123[:,j] + bfin[j])
__global__ __launch_bounds__(256) void mlp_final_kernel(
    const float* __restrict__ res, const float* __restrict__ W123,
    const float* __restrict__ bfin, float* __restrict__ out, int No)
{
    __shared__ float Ws[128 * 8];
    __shared__ float bs[8];
    for (int i = threadIdx.x; i < 128 * 8; i += blockDim.x) Ws[i] = W123[i];
    if (threadIdx.x < 8) bs[threadIdx.x] = bfin[threadIdx.x];
    __syncthreads();
    int gid = blockIdx.x * blockDim.x + threadIdx.x;
    int row = gid >> 3, j = gid & 7;
    if (row >= No) return;
    const float* r = res + (size_t)row * 128;
    float acc = 0.f;
#pragma unroll
    for (int k = 0; k < 128; k += 4) {
        float4 v = *(const float4*)(r + k);
        acc += v.x * Ws[(k + 0) * 8 + j];
        acc += v.y * Ws[(k + 1) * 8 + j];
        acc += v.z * Ws[(k + 2) * 8 + j];
        acc += v.w * Ws[(k + 3) * 8 + j];
    }
    float x = acc + bs[j];
    out[(size_t)row * 8 + j] = 1.f / (1.f + expf(-x));
}

// ---------------------------------------------------------------------------
// Host orchestration
// ---------------------------------------------------------------------------
static inline int ceil_div(int a, int b) { return (a + b - 1) / b; }

extern "C" void kernel_launch(void* const* d_in, const int* in_sizes, int n_in,
                              void* d_out, int out_size)
{
    const float* xo  = (const float*)d_in[0];
    const float* xa  = (const float*)d_in[1];
    const int*   eoo = (const int*)d_in[2];
    const int*   eoa = (const int*)d_in[3];
    const int*   eao = (const int*)d_in[4];
    const int No  = in_sizes[0] / 128;
    const int Na  = in_sizes[1] / 128;
    const int Eoo = in_sizes[2] / 2;
    const int Eoa = in_sizes[3] / 2;
    const int Eao = in_sizes[4] / 2;

    float *ho, *ha, *o0, *o1, *oa, *res, *elog, *m, *s, *pobj, *patt, *w;
    float *W12, *W123, *t1, *bfin, *zero;
    double* score;
    cudaGetSymbolAddress((void**)&ho,    g_ho);
    cudaGetSymbolAddress((void**)&ha,    g_ha);
    cudaGetSymbolAddress((void**)&o0,    g_o0);
    cudaGetSymbolAddress((void**)&o1,    g_o1);
    cudaGetSymbolAddress((void**)&oa,    g_oa);
    cudaGetSymbolAddress((void**)&res,   g_res);
    cudaGetSymbolAddress((void**)&elog,  g_elog);
    cudaGetSymbolAddress((void**)&m,     g_m);
    cudaGetSymbolAddress((void**)&s,     g_s);
    cudaGetSymbolAddress((void**)&pobj,  g_pobj);
    cudaGetSymbolAddress((void**)&patt,  g_patt);
    cudaGetSymbolAddress((void**)&score, g_score);
    cudaGetSymbolAddress((void**)&w,     g_w);
    cudaGetSymbolAddress((void**)&W12,   g_W12);
    cudaGetSymbolAddress((void**)&W123,  g_W123);
    cudaGetSymbolAddress((void**)&t1,    g_t1);
    cudaGetSymbolAddress((void**)&bfin,  g_bfin);
    cudaGetSymbolAddress((void**)&zero,  g_zero);

    const float* Wl1 = (const float*)d_in[23];
    const float* bl1 = (const float*)d_in[24];
    const float* Wl2 = (const float*)d_in[25];
    const float* bl2 = (const float*)d_in[26];
    const float* Wl3 = (const float*)d_in[27];
    const float* bl3 = (const float*)d_in[28];

    dim3 gemmBlk(256);

    // --- MLP weight collapse (independent of pipeline; launch first) ---
    gemm_bias_kernel<<<dim3(ceil_div(128, GBN), 1), gemmBlk>>>(
        Wl1, Wl2, zero, W12, 128, 128, 256, 0);
    bias_t1_kernel<<<1, 128>>>(bl1, Wl2, bl2, t1);
    w123_kernel<<<1, 1024>>>(W12, Wl3, W123);
    bias_fin_kernel<<<1, 8>>>(t1, Wl3, bl3, bfin);

    for (int layer = 0; layer < 2; layer++) {
        const int base = 5 + 9 * layer;
        const float* Wo   = (const float*)d_in[base + 0];
        const float* bo   = (const float*)d_in[base + 1];
        const float* Wa   = (const float*)d_in[base + 2];
        const float* ba   = (const float*)d_in[base + 3];
        const float* asrc = (const float*)d_in[base + 4];
        const float* adst = (const float*)d_in[base + 5];
        const float* Wk   = (const float*)d_in[base + 6];
        const float* bk   = (const float*)d_in[base + 7];
        const float* q    = (const float*)d_in[base + 8];

        const float* Ain_o = (layer == 0) ? xo : res;
        const float* Ain_a = (layer == 0) ? xa : oa;
        int reluA = (layer == 0) ? 0 : 1;

        gemm_bias_kernel<<<dim3(ceil_div(128, GBN), ceil_div(No, GBM)), gemmBlk>>>(
            Ain_o, Wo, bo, ho, No, 128, 128, 0);
        gemm_bias_kernel<<<dim3(ceil_div(128, GBN), ceil_div(Na, GBM)), gemmBlk>>>(
            Ain_a, Wa, ba, ha, Na, 128, 128, reluA);

        proj_kernel<<<ceil_div(No * 32, 256), 256>>>(
            ho, No, 4, asrc + 0, asrc + 128, adst + 0, adst + 256, pobj);
        proj_kernel<<<ceil_div(Na * 32, 256), 256>>>(
            ha, Na, 2, asrc + 256, adst + 128, asrc, asrc, patt);

        // --- oo: object -> object (metapath 0) ---
        {
            const int* esrc = eoo; const int* edst = eoo + Eoo;
            init_seg_kernel<<<ceil_div(No * 128, 256), 256>>>(o0, m, s, No);
            edge_logits_kernel<<<ceil_div(Eoo, 256), 256>>>(
                esrc, edst, Eoo, pobj + 0, pobj + (size_t)2 * No * 2, elog, m);
            edge_exp_kernel<<<ceil_div(Eoo, 256), 256>>>(edst, Eoo, m, elog, s);
            edge_aggregate_kernel<<<ceil_div(Eoo * 32, 256), 256>>>(
                esrc, edst, Eoo, elog, s, ho, o0);
        }
        // --- oa: object -> attribute (only layer 1's result is ever used) ---
        if (layer == 0) {
            const int* esrc = eoa; const int* edst = eoa + Eoa;
            init_seg_kernel<<<ceil_div(Na * 128, 256), 256>>>(oa, m, s, Na);
            edge_logits_kernel<<<ceil_div(Eoa, 256), 256>>>(
                esrc, edst, Eoa, pobj + (size_t)1 * No * 2, patt + (size_t)1 * Na * 2, elog, m);
            edge_exp_kernel<<<ceil_div(Eoa, 256), 256>>>(edst, Eoa, m, elog, s);
            edge_aggregate_kernel<<<ceil_div(Eoa * 32, 256), 256>>>(
                esrc, edst, Eoa, elog, s, ho, oa);
        }
        // --- ao: attribute -> object (metapath 1) ---
        {
            const int* esrc = eao; const int* edst = eao + Eao;
            init_seg_kernel<<<ceil_div(No * 128, 256), 256>>>(o1, m, s, No);
            edge_logits_kernel<<<ceil_div(Eao, 256), 256>>>(
                esrc, edst, Eao, patt + 0, pobj + (size_t)3 * No * 2, elog, m);
            edge_exp_kernel<<<ceil_div(Eao, 256), 256>>>(edst, Eao, m, elog, s);
            edge_aggregate_kernel<<<ceil_div(Eao * 32, 256), 256>>>(
                esrc, edst, Eao, elog, s, ha, o1);
        }

        zero_score_kernel<<<1, 1>>>(score);
        score_gemm_kernel<<<dim3(ceil_div(128, GBN), ceil_div(No, GBM)), gemmBlk>>>(
            o0, Wk, bk, q, No, 128, 128, score + 0);
        score_gemm_kernel<<<dim3(ceil_div(128, GBN), ceil_div(No, GBM)), gemmBlk>>>(
            o1, Wk, bk, q, No, 128, 128, score + 1);
        softmax2_kernel<<<1, 1>>>(score, w, 1.0 / (double)No);
        combine_kernel<<<ceil_div(No * 128, 256), 256>>>(o0, o1, w, res, No * 128);
    }

    // --- collapsed MLP head: out = sigmoid(res @ W123 + bfin) ---
    mlp_final_kernel<<<ceil_div(No * 8, 256), 256>>>(
        res, W123, bfin, (float*)d_out, No);
}

// round 5
// speedup vs baseline: 1.4871x; 1.4871x over previous
#include <cuda_runtime.h>
#include <math.h>
#include <stdint.h>

// ============================================================================
// HAN: 2-layer heterogeneous GAT + semantic attention + collapsed MLP head.
// R5 (= R4 resubmit after infra failure): GEMMs on tensor cores via base-PTX
// mma.sync (m16n8k8 tf32) — tcgen05 unavailable (harness targets base sm_103).
//   - feature transforms: 3-pass hi/lo tf32 split (near-fp32)
//   - score GEMMs: single-pass tf32 (rna-rounded)
// ============================================================================

#define MAXNO 100096
#define MAXNA 50048
#define MAXE  500224

__device__ float  g_ho[MAXNO * 128];
__device__ float  g_ha[MAXNA * 128];
__device__ float  g_o0[MAXNO * 128];
__device__ float  g_o1[MAXNO * 128];
__device__ float  g_oa[MAXNA * 128];
__device__ float  g_res[MAXNO * 128];
__device__ float  g_elog[MAXE * 2];
__device__ float  g_m[MAXNO * 2];
__device__ float  g_s[MAXNO * 2];
__device__ float  g_pobj[4 * MAXNO * 2];
__device__ float  g_patt[2 * MAXNA * 2];
__device__ double g_score[2];
__device__ float  g_w[2];
__device__ float  g_W123[128 * 8];
__device__ float  g_bfin[8];

// ---------------------------------------------------------------------------
// mma.sync helpers
// ---------------------------------------------------------------------------
__device__ __forceinline__ void mma8(float* c,
                                     uint32_t a0, uint32_t a1, uint32_t a2, uint32_t a3,
                                     uint32_t b0, uint32_t b1)
{
    asm volatile(
        "mma.sync.aligned.m16n8k8.row.col.f32.tf32.tf32.f32 "
        "{%0,%1,%2,%3}, {%4,%5,%6,%7}, {%8,%9}, {%0,%1,%2,%3};"
        : "+f"(c[0]), "+f"(c[1]), "+f"(c[2]), "+f"(c[3])
        : "r"(a0), "r"(a1), "r"(a2), "r"(a3), "r"(b0), "r"(b1));
}

__device__ __forceinline__ uint32_t to_tf32(float x) {
    uint32_t r;
    asm("cvt.rna.tf32.f32 %0, %1;" : "=r"(r) : "f"(x));
    return r;
}
__device__ __forceinline__ float tf32_hi(float x) {
    return __uint_as_float(__float_as_uint(x) & 0xffffe000u);
}

// ---------------------------------------------------------------------------
// mma_feat: C[M,128] = op(A)[M,128] @ W[128,128] + bias, 3-pass tf32 split.
// 256 threads = 8 warps; warp w computes rows [16w,16w+16) of a 128-row tile,
// all 128 columns. K chunked by 32. smem rotation: k' = (k + 4*(row&7)) & 31.
// ---------------------------------------------------------------------------
__global__ __launch_bounds__(256) void mma_feat_kernel(
    const float* __restrict__ A, const float* __restrict__ W,
    const float* __restrict__ bias, float* __restrict__ C,
    int M, int reluIn)
{
    extern __shared__ float2 fsm[];          // [0,4096) A, [4096,8192) B
    float2* Asm = fsm;
    float2* Bsm = fsm + 4096;
    const int tid  = threadIdx.x;
    const int w    = tid >> 5, lane = tid & 31;
    const int gid  = lane >> 2, tig = lane & 3;
    const int m0   = blockIdx.x * 128;

    float acc[16][4];
#pragma unroll
    for (int i = 0; i < 16; i++)
#pragma unroll
        for (int j = 0; j < 4; j++) acc[i][j] = 0.f;

    for (int kc = 0; kc < 128; kc += 32) {
        // load A chunk [128 rows x 32 k], split hi/lo
        for (int i = tid; i < 1024; i += 256) {
            int r  = i >> 3;
            int c4 = (i & 7) << 2;
            float4 v = make_float4(0.f, 0.f, 0.f, 0.f);
            if (m0 + r < M)
                v = *(const float4*)(A + (size_t)(m0 + r) * 128 + kc + c4);
            if (reluIn) {
                v.x = fmaxf(v.x, 0.f); v.y = fmaxf(v.y, 0.f);
                v.z = fmaxf(v.z, 0.f); v.w = fmaxf(v.w, 0.f);
            }
            float e[4] = {v.x, v.y, v.z, v.w};
            int rot = (r & 7) << 2;
#pragma unroll
            for (int j = 0; j < 4; j++) {
                float hi = tf32_hi(e[j]);
                float lo = __uint_as_float(to_tf32(e[j] - hi));
                Asm[r * 32 + (((c4 + j) + rot) & 31)] = make_float2(hi, lo);
            }
        }
        // load B chunk: Bt[n][k] = W[kc+k][n], split hi/lo
        for (int i = tid; i < 4096; i += 256) {
            int n = i & 127, k = i >> 7;
            float x = W[(size_t)(kc + k) * 128 + n];
            float hi = tf32_hi(x);
            float lo = __uint_as_float(to_tf32(x - hi));
            Bsm[n * 32 + ((k + ((n & 7) << 2)) & 31)] = make_float2(hi, lo);
        }
        __syncthreads();

#pragma unroll
        for (int ks = 0; ks < 4; ks++) {
            int k0 = ks * 8;
            int ra = w * 16 + gid;
            int rot = gid << 2;                      // (ra&7)==gid, ((ra+8)&7)==gid
            float2 A0 = Asm[ra * 32 + ((k0 + tig + rot) & 31)];
            float2 A1 = Asm[(ra + 8) * 32 + ((k0 + tig + rot) & 31)];
            float2 A2 = Asm[ra * 32 + ((k0 + tig + 4 + rot) & 31)];
            float2 A3 = Asm[(ra + 8) * 32 + ((k0 + tig + 4 + rot) & 31)];
            uint32_t ah0 = __float_as_uint(A0.x), ah1 = __float_as_uint(A1.x);
            uint32_t ah2 = __float_as_uint(A2.x), ah3 = __float_as_uint(A3.x);
            uint32_t al0 = __float_as_uint(A0.y), al1 = __float_as_uint(A1.y);
            uint32_t al2 = __float_as_uint(A2.y), al3 = __float_as_uint(A3.y);
#pragma unroll
            for (int nt = 0; nt < 16; nt++) {
                int n = nt * 8 + gid;
                float2 B0 = Bsm[n * 32 + ((k0 + tig + rot) & 31)];
                float2 B1 = Bsm[n * 32 + ((k0 + tig + 4 + rot) & 31)];
                uint32_t bh0 = __float_as_uint(B0.x), bh1 = __float_as_uint(B1.x);
                uint32_t bl0 = __float_as_uint(B0.y), bl1 = __float_as_uint(B1.y);
                mma8(acc[nt], ah0, ah1, ah2, ah3, bh0, bh1);
                mma8(acc[nt], ah0, ah1, ah2, ah3, bl0, bl1);
                mma8(acc[nt], al0, al1, al2, al3, bh0, bh1);
            }
        }
        __syncthreads();
    }

    // epilogue
    int r0 = m0 + w * 16 + gid;
#pragma unroll
    for (int nt = 0; nt < 16; nt++) {
        int col = nt * 8 + (tig << 1);
        float2 b2 = *(const float2*)(bias + col);
        if (r0 < M) {
            float2 o = make_float2(acc[nt][0] + b2.x, acc[nt][1] + b2.y);
            *(float2*)(C + (size_t)r0 * 128 + col) = o;
        }
        if (r0 + 8 < M) {
            float2 o = make_float2(acc[nt][2] + b2.x, acc[nt][3] + b2.y);
            *(float2*)(C + (size_t)(r0 + 8) * 128 + col) = o;
        }
    }
}

// ---------------------------------------------------------------------------
// mma_score: outScore += sum_{m,n} q[n] * tanh((relu(A) @ Wk + bk)[m,n])
// single-pass tf32, same tiling.
// ---------------------------------------------------------------------------
__global__ __launch_bounds__(256) void mma_score_kernel(
    const float* __restrict__ A, const float* __restrict__ W,
    const float* __restrict__ bias, const float* __restrict__ q,
    int M, double* __restrict__ outScore)
{
    __shared__ uint32_t As[128 * 32];
    __shared__ uint32_t Bs[128 * 32];
    __shared__ float red[8];
    const int tid = threadIdx.x;
    const int w   = tid >> 5, lane = tid & 31;
    const int gid = lane >> 2, tig = lane & 3;
    const int m0  = blockIdx.x * 128;

    float acc[16][4];
#pragma unroll
    for (int i = 0; i < 16; i++)
#pragma unroll
        for (int j = 0; j < 4; j++) acc[i][j] = 0.f;

    for (int kc = 0; kc < 128; kc += 32) {
        for (int i = tid; i < 1024; i += 256) {
            int r  = i >> 3;
            int c4 = (i & 7) << 2;
            float4 v = make_float4(0.f, 0.f, 0.f, 0.f);
            if (m0 + r < M)
                v = *(const float4*)(A + (size_t)(m0 + r) * 128 + kc + c4);
            float e[4] = {fmaxf(v.x, 0.f), fmaxf(v.y, 0.f),
                          fmaxf(v.z, 0.f), fmaxf(v.w, 0.f)};
            int rot = (r & 7) << 2;
#pragma unroll
            for (int j = 0; j < 4; j++)
                As[r * 32 + (((c4 + j) + rot) & 31)] = to_tf32(e[j]);
        }
        for (int i = tid; i < 4096; i += 256) {
            int n = i & 127, k = i >> 7;
            Bs[n * 32 + ((k + ((n & 7) << 2)) & 31)] =
                to_tf32(W[(size_t)(kc + k) * 128 + n]);
        }
        __syncthreads();

#pragma unroll
        for (int ks = 0; ks < 4; ks++) {
            int k0 = ks * 8;
            int ra = w * 16 + gid;
            int rot = gid << 2;
            uint32_t a0 = As[ra * 32 + ((k0 + tig + rot) & 31)];
            uint32_t a1 = As[(ra + 8) * 32 + ((k0 + tig + rot) & 31)];
            uint32_t a2 = As[ra * 32 + ((k0 + tig + 4 + rot) & 31)];
            uint32_t a3 = As[(ra + 8) * 32 + ((k0 + tig + 4 + rot) & 31)];
#pragma unroll
            for (int nt = 0; nt < 16; nt++) {
                int n = nt * 8 + gid;
                uint32_t b0 = Bs[n * 32 + ((k0 + tig + rot) & 31)];
                uint32_t b1 = Bs[n * 32 + ((k0 + tig + 4 + rot) & 31)];
                mma8(acc[nt], a0, a1, a2, a3, b0, b1);
            }
        }
        __syncthreads();
    }

    float local = 0.f;
    int r0 = m0 + w * 16 + gid;
#pragma unroll
    for (int nt = 0; nt < 16; nt++) {
        int col = nt * 8 + (tig << 1);
        float2 b2 = *(const float2*)(bias + col);
        float2 q2 = *(const float2*)(q + col);
        if (r0 < M) {
            local += q2.x * tanhf(acc[nt][0] + b2.x);
            local += q2.y * tanhf(acc[nt][1] + b2.y);
        }
        if (r0 + 8 < M) {
            local += q2.x * tanhf(acc[nt][2] + b2.x);
            local += q2.y * tanhf(acc[nt][3] + b2.y);
        }
    }
#pragma unroll
    for (int o = 16; o > 0; o >>= 1)
        local += __shfl_xor_sync(0xffffffffu, local, o);
    if (lane == 0) red[w] = local;
    __syncthreads();
    if (tid == 0) {
        double s = 0.0;
        for (int i = 0; i < 8; i++) s += (double)red[i];
        atomicAdd(outScore, s);
    }
}

// ---------------------------------------------------------------------------
// Node projection (warp per node, <=4 attention vectors)
// ---------------------------------------------------------------------------
__global__ __launch_bounds__(256) void proj_kernel(
    const float* __restrict__ h, int n, int nv,
    const float* __restrict__ v0, const float* __restrict__ v1,
    const float* __restrict__ v2, const float* __restrict__ v3,
    float* __restrict__ out)
{
    int warp = (blockIdx.x * blockDim.x + threadIdx.x) >> 5;
    int lane = threadIdx.x & 31;
    if (warp >= n) return;
    const float* hr = h + (size_t)warp * 128;
    float h0 = hr[lane], h1 = hr[lane + 32], h2 = hr[lane + 64], h3 = hr[lane + 96];
    const float* vs[4] = {v0, v1, v2, v3};
#pragma unroll
    for (int v = 0; v < 4; v++) {
        if (v >= nv) break;
        const float* vv = vs[v];
        float p0 = h0 * vv[lane] + h1 * vv[lane + 32];
        float p1 = h2 * vv[lane + 64] + h3 * vv[lane + 96];
#pragma unroll
        for (int o = 16; o > 0; o >>= 1) {
            p0 += __shfl_xor_sync(0xffffffffu, p0, o);
            p1 += __shfl_xor_sync(0xffffffffu, p1, o);
        }
        if (lane == 0) {
            out[((size_t)v * n + warp) * 2 + 0] = p0;
            out[((size_t)v * n + warp) * 2 + 1] = p1;
        }
    }
}

// ---------------------------------------------------------------------------
// Segment init / edge passes
// ---------------------------------------------------------------------------
__global__ void init_seg_kernel(float* __restrict__ out, float* __restrict__ m,
                                float* __restrict__ s, int ndst)
{
    int i = blockIdx.x * blockDim.x + threadIdx.x;
    if (i < ndst * 128) out[i] = 0.f;
    if (i < ndst * 2) { m[i] = -INFINITY; s[i] = 0.f; }
}

__device__ __forceinline__ void atomicMaxFloat(float* addr, float val)
{
    if (val >= 0.f) atomicMax((int*)addr, __float_as_int(val));
    else            atomicMin((unsigned int*)addr, __float_as_uint(val));
}

__global__ __launch_bounds__(256) void edge_logits_kernel(
    const int* __restrict__ src, const int* __restrict__ dst, int E,
    const float* __restrict__ psrc, const float* __restrict__ pdst,
    float* __restrict__ elog, float* __restrict__ m)
{
    int e = blockIdx.x * blockDim.x + threadIdx.x;
    if (e >= E) return;
    int s = src[e], d = dst[e];
    float2 ps = *(const float2*)(psrc + 2 * (size_t)s);
    float2 pd = *(const float2*)(pdst + 2 * (size_t)d);
    float a0 = ps.x + pd.x; a0 = a0 > 0.f ? a0 : 0.2f * a0;
    float a1 = ps.y + pd.y; a1 = a1 > 0.f ? a1 : 0.2f * a1;
    *(float2*)(elog + 2 * (size_t)e) = make_float2(a0, a1);
    atomicMaxFloat(m + 2 * (size_t)d + 0, a0);
    atomicMaxFloat(m + 2 * (size_t)d + 1, a1);
}

__global__ __launch_bounds__(256) void edge_exp_kernel(
    const int* __restrict__ dst, int E, const float* __restrict__ m,
    float* __restrict__ elog, float* __restrict__ ssum)
{
    int e = blockIdx.x * blockDim.x + threadIdx.x;
    if (e >= E) return;
    int d = dst[e];
    float2 mv = *(const float2*)(m + 2 * (size_t)d);
    float2 ev = *(const float2*)(elog + 2 * (size_t)e);
    ev.x = expf(ev.x - mv.x);
    ev.y = expf(ev.y - mv.y);
    *(float2*)(elog + 2 * (size_t)e) = ev;
    atomicAdd(ssum + 2 * (size_t)d + 0, ev.x);
    atomicAdd(ssum + 2 * (size_t)d + 1, ev.y);
}

__global__ __launch_bounds__(256) void edge_aggregate_kernel(
    const int* __restrict__ src, const int* __restrict__ dst, int E,
    const float* __restrict__ elog, const float* __restrict__ ssum,
    const float* __restrict__ hsrc, float* __restrict__ out)
{
    int gw   = (blockIdx.x * blockDim.x + threadIdx.x) >> 5;
    int lane = threadIdx.x & 31;
    if (gw >= E) return;
    int s = src[gw], d = dst[gw];
    int head = lane >> 4;
    float el = elog[2 * (size_t)gw + head];
    float sv = ssum[2 * (size_t)d + head];
    float alpha = el / (sv + 1e-16f);
    float4 v = *(const float4*)(hsrc + (size_t)s * 128 + lane * 4);
    v.x *= alpha; v.y *= alpha; v.z *= alpha; v.w *= alpha;
    float* op = out + (size_t)d * 128 + lane * 4;
    asm volatile("red.global.add.v4.f32 [%0], {%1,%2,%3,%4};"
                 :: "l"(op), "f"(v.x), "f"(v.y), "f"(v.z), "f"(v.w)
                 : "memory");
}

// ---------------------------------------------------------------------------
// Semantic attention tail
// ---------------------------------------------------------------------------
__global__ void zero_score_kernel(double* sc) { sc[0] = 0.0; sc[1] = 0.0; }

__global__ void softmax2_kernel(const double* __restrict__ sc,
                                float* __restrict__ w, double invN)
{
    double s0 = sc[0] * invN, s1 = sc[1] * invN;
    double mx = s0 > s1 ? s0 : s1;
    double e0 = exp(s0 - mx), e1 = exp(s1 - mx);
    double sum = e0 + e1;
    w[0] = (float)(e0 / sum);
    w[1] = (float)(e1 / sum);
}

__global__ __launch_bounds__(256) void combine_kernel(
    const float* __restrict__ o0, const float* __restrict__ o1,
    const float* __restrict__ w, float* __restrict__ res, int tot)
{
    int i = blockIdx.x * blockDim.x + threadIdx.x;
    if (i >= tot) return;
    res[i] = w[0] * fmaxf(o0[i], 0.f) + w[1] * fmaxf(o1[i], 0.f);
}

// ---------------------------------------------------------------------------
// MLP weight collapse (single kernel)
// ---------------------------------------------------------------------------
__global__ __launch_bounds__(256) void precompute_kernel(
    const float* __restrict__ Wl1, const float* __restrict__ bl1,
    const float* __restrict__ Wl2, const float* __restrict__ bl2,
    const float* __restrict__ Wl3, const float* __restrict__ bl3,
    float* __restrict__ W123, float* __restrict__ bfin)
{
    __shared__ float W23[256 * 8];
    __shared__ float t1s[128];
    int tid = threadIdx.x;
    for (int i = tid; i < 2048; i += 256) {
        int r = i >> 3, j = i & 7;
        float a = 0.f;
        for (int c = 0; c < 128; c++) a += Wl2[r * 128 + c] * Wl3[c * 8 + j];
        W23[i] = a;
    }
    for (int n = tid; n < 128; n += 256) {
        float a = bl2[n];
        for (int k = 0; k < 256; k++) a += bl1[k] * Wl2[k * 128 + n];
        t1s[n] = a;
    }
    __syncthreads();
    for (int i = tid; i < 1024; i += 256) {
        int k = i >> 3, j = i & 7;
        float a = 0.f;
        for (int r = 0; r < 256; r++) a += Wl1[k * 256 + r] * W23[r * 8 + j];
        W123[i] = a;
    }
    if (tid < 8) {
        float a = bl3[tid];
        for (int c = 0; c < 128; c++) a += t1s[c] * Wl3[c * 8 + tid];
        bfin[tid] = a;
    }
}

__global__ __launch_bounds__(256) void mlp_final_kernel(
    const float* __restrict__ res, const float* __restrict__ W123,
    const float* __restrict__ bfin, float* __restrict__ out, int No)
{
    __shared__ float Ws[128 * 8];
    __shared__ float bs[8];
    for (int i = threadIdx.x; i < 128 * 8; i += blockDim.x) Ws[i] = W123[i];
    if (threadIdx.x < 8) bs[threadIdx.x] = bfin[threadIdx.x];
    __syncthreads();
    int gid = blockIdx.x * blockDim.x + threadIdx.x;
    int row = gid >> 3, j = gid & 7;
    if (row >= No) return;
    const float* r = res + (size_t)row * 128;
    float acc = 0.f;
#pragma unroll
    for (int k = 0; k < 128; k += 4) {
        float4 v = *(const float4*)(r + k);
        acc += v.x * Ws[(k + 0) * 8 + j];
        acc += v.y * Ws[(k + 1) * 8 + j];
        acc += v.z * Ws[(k + 2) * 8 + j];
        acc += v.w * Ws[(k + 3) * 8 + j];
    }
    float x = acc + bs[j];
    out[(size_t)row * 8 + j] = 1.f / (1.f + expf(-x));
}

// ---------------------------------------------------------------------------
// Host orchestration
// ---------------------------------------------------------------------------
static inline int ceil_div(int a, int b) { return (a + b - 1) / b; }

extern "C" void kernel_launch(void* const* d_in, const int* in_sizes, int n_in,
                              void* d_out, int out_size)
{
    const float* xo  = (const float*)d_in[0];
    const float* xa  = (const float*)d_in[1];
    const int*   eoo = (const int*)d_in[2];
    const int*   eoa = (const int*)d_in[3];
    const int*   eao = (const int*)d_in[4];
    const int No  = in_sizes[0] / 128;
    const int Na  = in_sizes[1] / 128;
    const int Eoo = in_sizes[2] / 2;
    const int Eoa = in_sizes[3] / 2;
    const int Eao = in_sizes[4] / 2;

    float *ho, *ha, *o0, *o1, *oa, *res, *elog, *m, *s, *pobj, *patt, *w;
    float *W123, *bfin;
    double* score;
    cudaGetSymbolAddress((void**)&ho,    g_ho);
    cudaGetSymbolAddress((void**)&ha,    g_ha);
    cudaGetSymbolAddress((void**)&o0,    g_o0);
    cudaGetSymbolAddress((void**)&o1,    g_o1);
    cudaGetSymbolAddress((void**)&oa,    g_oa);
    cudaGetSymbolAddress((void**)&res,   g_res);
    cudaGetSymbolAddress((void**)&elog,  g_elog);
    cudaGetSymbolAddress((void**)&m,     g_m);
    cudaGetSymbolAddress((void**)&s,     g_s);
    cudaGetSymbolAddress((void**)&pobj,  g_pobj);
    cudaGetSymbolAddress((void**)&patt,  g_patt);
    cudaGetSymbolAddress((void**)&score, g_score);
    cudaGetSymbolAddress((void**)&w,     g_w);
    cudaGetSymbolAddress((void**)&W123,  g_W123);
    cudaGetSymbolAddress((void**)&bfin,  g_bfin);

    const int FEAT_SMEM = 65536;
    cudaFuncSetAttribute(mma_feat_kernel,
                         cudaFuncAttributeMaxDynamicSharedMemorySize, FEAT_SMEM);

    const int tilesNo = ceil_div(No, 128);
    const int tilesNa = ceil_div(Na, 128);

    precompute_kernel<<<1, 256>>>(
        (const float*)d_in[23], (const float*)d_in[24], (const float*)d_in[25],
        (const float*)d_in[26], (const float*)d_in[27], (const float*)d_in[28],
        W123, bfin);

    for (int layer = 0; layer < 2; layer++) {
        const int base = 5 + 9 * layer;
        const float* Wo   = (const float*)d_in[base + 0];
        const float* bo   = (const float*)d_in[base + 1];
        const float* Wa   = (const float*)d_in[base + 2];
        const float* ba   = (const float*)d_in[base + 3];
        const float* asrc = (const float*)d_in[base + 4];
        const float* adst = (const float*)d_in[base + 5];
        const float* Wk   = (const float*)d_in[base + 6];
        const float* bk   = (const float*)d_in[base + 7];
        const float* q    = (const float*)d_in[base + 8];

        const float* Ain_o = (layer == 0) ? xo : res;
        const float* Ain_a = (layer == 0) ? xa : oa;
        int reluA = (layer == 0) ? 0 : 1;

        mma_feat_kernel<<<tilesNo, 256, FEAT_SMEM>>>(Ain_o, Wo, bo, ho, No, 0);
        mma_feat_kernel<<<tilesNa, 256, FEAT_SMEM>>>(Ain_a, Wa, ba, ha, Na, reluA);

        proj_kernel<<<ceil_div(No * 32, 256), 256>>>(
            ho, No, 4, asrc + 0, asrc + 128, adst + 0, adst + 256, pobj);
        proj_kernel<<<ceil_div(Na * 32, 256), 256>>>(
            ha, Na, 2, asrc + 256, adst + 128, asrc, asrc, patt);

        // --- oo: object -> object (metapath 0) ---
        {
            const int* esrc = eoo; const int* edst = eoo + Eoo;
            init_seg_kernel<<<ceil_div(No * 128, 256), 256>>>(o0, m, s, No);
            edge_logits_kernel<<<ceil_div(Eoo, 256), 256>>>(
                esrc, edst, Eoo, pobj + 0, pobj + (size_t)2 * No * 2, elog, m);
            edge_exp_kernel<<<ceil_div(Eoo, 256), 256>>>(edst, Eoo, m, elog, s);
            edge_aggregate_kernel<<<ceil_div(Eoo * 32, 256), 256>>>(
                esrc, edst, Eoo, elog, s, ho, o0);
        }
        // --- oa: object -> attribute (layer-1 result only is used) ---
        if (layer == 0) {
            const int* esrc = eoa; const int* edst = eoa + Eoa;
            init_seg_kernel<<<ceil_div(Na * 128, 256), 256>>>(oa, m, s, Na);
            edge_logits_kernel<<<ceil_div(Eoa, 256), 256>>>(
                esrc, edst, Eoa, pobj + (size_t)1 * No * 2, patt + (size_t)1 * Na * 2, elog, m);
            edge_exp_kernel<<<ceil_div(Eoa, 256), 256>>>(edst, Eoa, m, elog, s);
            edge_aggregate_kernel<<<ceil_div(Eoa * 32, 256), 256>>>(
                esrc, edst, Eoa, elog, s, ho, oa);
        }
        // --- ao: attribute -> object (metapath 1) ---
        {
            const int* esrc = eao; const int* edst = eao + Eao;
            init_seg_kernel<<<ceil_div(No * 128, 256), 256>>>(o1, m, s, No);
            edge_logits_kernel<<<ceil_div(Eao, 256), 256>>>(
                esrc, edst, Eao, patt + 0, pobj + (size_t)3 * No * 2, elog, m);
            edge_exp_kernel<<<ceil_div(Eao, 256), 256>>>(edst, Eao, m, elog, s);
            edge_aggregate_kernel<<<ceil_div(Eao * 32, 256), 256>>>(
                esrc, edst, Eao, elog, s, ha, o1);
        }

        zero_score_kernel<<<1, 1>>>(score);
        mma_score_kernel<<<tilesNo, 256>>>(o0, Wk, bk, q, No, score + 0);
        mma_score_kernel<<<tilesNo, 256>>>(o1, Wk, bk, q, No, score + 1);
        softmax2_kernel<<<1, 1>>>(score, w, 1.0 / (double)No);
        combine_kernel<<<ceil_div(No * 128, 256), 256>>>(o0, o1, w, res, No * 128);
    }

    mlp_final_kernel<<<ceil_div(No * 8, 256), 256>>>(
        res, W123, bfin, (float*)d_out, No);
}

// round 6
// speedup vs baseline: 1.6660x; 1.1203x over previous
#include <cuda_runtime.h>
#include <math.h>
#include <stdint.h>

// ============================================================================
// HAN: 2-layer heterogeneous GAT + semantic attention + collapsed MLP head.
// R6: - segment softmax without max pass (shift-invariance; logits bounded)
//     - node projections fused into feature-GEMM epilogue
//     - semantic combine fused into consumers (no res buffer, no combine pass)
//     - both score GEMMs in one launch (grid.y = 2)
// GEMMs: base-PTX mma.sync m16n8k8 tf32; feature = 3-pass hi/lo split.
// ============================================================================

#define MAXNO 100096
#define MAXNA 50048
#define MAXE  500224

__device__ float  g_ho[MAXNO * 128];
__device__ float  g_ha[MAXNA * 128];
__device__ float  g_o0[MAXNO * 128];
__device__ float  g_o1[MAXNO * 128];
__device__ float  g_oa[MAXNA * 128];
__device__ float  g_elog[MAXE * 2];
__device__ float  g_s[MAXNO * 2];
__device__ float  g_pobj[4 * MAXNO * 2];
__device__ float  g_patt[2 * MAXNA * 2];
__device__ double g_score[2];
__device__ float  g_w[2];
__device__ float  g_W123[128 * 8];
__device__ float  g_bfin[8];

// ---------------------------------------------------------------------------
// mma.sync helpers
// ---------------------------------------------------------------------------
__device__ __forceinline__ void mma8(float* c,
                                     uint32_t a0, uint32_t a1, uint32_t a2, uint32_t a3,
                                     uint32_t b0, uint32_t b1)
{
    asm volatile(
        "mma.sync.aligned.m16n8k8.row.col.f32.tf32.tf32.f32 "
        "{%0,%1,%2,%3}, {%4,%5,%6,%7}, {%8,%9}, {%0,%1,%2,%3};"
        : "+f"(c[0]), "+f"(c[1]), "+f"(c[2]), "+f"(c[3])
        : "r"(a0), "r"(a1), "r"(a2), "r"(a3), "r"(b0), "r"(b1));
}

__device__ __forceinline__ uint32_t to_tf32(float x) {
    uint32_t r;
    asm("cvt.rna.tf32.f32 %0, %1;" : "=r"(r) : "f"(x));
    return r;
}
__device__ __forceinline__ float tf32_hi(float x) {
    return __uint_as_float(__float_as_uint(x) & 0xffffe000u);
}

// ---------------------------------------------------------------------------
// mma_feat: C[M,128] = op(A)[M,128] @ W[128,128] + bias, 3-pass tf32 split,
// with node projections fused into the epilogue.
// mode: 0 = plain A, 1 = relu(A), 2 = A := w0*relu(A)+w1*relu(A2)
// 256 threads = 8 warps; warp w computes rows [16w,16w+16); K chunked by 32.
// smem rotation: k' = (k + 4*(row&7)) & 31.
// ---------------------------------------------------------------------------
__global__ __launch_bounds__(256) void mma_feat_kernel(
    const float* __restrict__ A, const float* __restrict__ A2,
    const float* __restrict__ wbuf, const float* __restrict__ W,
    const float* __restrict__ bias, float* __restrict__ C, int M, int mode,
    int nv, const float* __restrict__ v0, const float* __restrict__ v1,
    const float* __restrict__ v2, const float* __restrict__ v3,
    float* __restrict__ projOut)
{
    extern __shared__ float2 fsm[];          // [0,4096) A, [4096,8192) B
    float2* Asm = fsm;
    float2* Bsm = fsm + 4096;
    const int tid  = threadIdx.x;
    const int w    = tid >> 5, lane = tid & 31;
    const int gid  = lane >> 2, tig = lane & 3;
    const int m0   = blockIdx.x * 128;

    float cw0 = 0.f, cw1 = 0.f;
    if (mode == 2) { cw0 = wbuf[0]; cw1 = wbuf[1]; }

    float acc[16][4];
#pragma unroll
    for (int i = 0; i < 16; i++)
#pragma unroll
        for (int j = 0; j < 4; j++) acc[i][j] = 0.f;

    for (int kc = 0; kc < 128; kc += 32) {
        // load A chunk [128 rows x 32 k], split hi/lo
        for (int i = tid; i < 1024; i += 256) {
            int r  = i >> 3;
            int c4 = (i & 7) << 2;
            float4 v = make_float4(0.f, 0.f, 0.f, 0.f);
            if (m0 + r < M) {
                v = *(const float4*)(A + (size_t)(m0 + r) * 128 + kc + c4);
                if (mode == 1) {
                    v.x = fmaxf(v.x, 0.f); v.y = fmaxf(v.y, 0.f);
                    v.z = fmaxf(v.z, 0.f); v.w = fmaxf(v.w, 0.f);
                } else if (mode == 2) {
                    float4 u = *(const float4*)(A2 + (size_t)(m0 + r) * 128 + kc + c4);
                    v.x = cw0 * fmaxf(v.x, 0.f) + cw1 * fmaxf(u.x, 0.f);
                    v.y = cw0 * fmaxf(v.y, 0.f) + cw1 * fmaxf(u.y, 0.f);
                    v.z = cw0 * fmaxf(v.z, 0.f) + cw1 * fmaxf(u.z, 0.f);
                    v.w = cw0 * fmaxf(v.w, 0.f) + cw1 * fmaxf(u.w, 0.f);
                }
            }
            float e[4] = {v.x, v.y, v.z, v.w};
            int rot = (r & 7) << 2;
#pragma unroll
            for (int j = 0; j < 4; j++) {
                float hi = tf32_hi(e[j]);
                float lo = __uint_as_float(to_tf32(e[j] - hi));
                Asm[r * 32 + (((c4 + j) + rot) & 31)] = make_float2(hi, lo);
            }
        }
        // load B chunk: Bt[n][k] = W[kc+k][n], split hi/lo
        for (int i = tid; i < 4096; i += 256) {
            int n = i & 127, k = i >> 7;
            float x = W[(size_t)(kc + k) * 128 + n];
            float hi = tf32_hi(x);
            float lo = __uint_as_float(to_tf32(x - hi));
            Bsm[n * 32 + ((k + ((n & 7) << 2)) & 31)] = make_float2(hi, lo);
        }
        __syncthreads();

#pragma unroll
        for (int ks = 0; ks < 4; ks++) {
            int k0 = ks * 8;
            int ra = w * 16 + gid;
            int rot = gid << 2;
            float2 A0 = Asm[ra * 32 + ((k0 + tig + rot) & 31)];
            float2 A1 = Asm[(ra + 8) * 32 + ((k0 + tig + rot) & 31)];
            float2 A2r = Asm[ra * 32 + ((k0 + tig + 4 + rot) & 31)];
            float2 A3 = Asm[(ra + 8) * 32 + ((k0 + tig + 4 + rot) & 31)];
            uint32_t ah0 = __float_as_uint(A0.x), ah1 = __float_as_uint(A1.x);
            uint32_t ah2 = __float_as_uint(A2r.x), ah3 = __float_as_uint(A3.x);
            uint32_t al0 = __float_as_uint(A0.y), al1 = __float_as_uint(A1.y);
            uint32_t al2 = __float_as_uint(A2r.y), al3 = __float_as_uint(A3.y);
#pragma unroll
            for (int nt = 0; nt < 16; nt++) {
                int n = nt * 8 + gid;
                float2 B0 = Bsm[n * 32 + ((k0 + tig + rot) & 31)];
                float2 B1 = Bsm[n * 32 + ((k0 + tig + 4 + rot) & 31)];
                uint32_t bh0 = __float_as_uint(B0.x), bh1 = __float_as_uint(B1.x);
                uint32_t bl0 = __float_as_uint(B0.y), bl1 = __float_as_uint(B1.y);
                mma8(acc[nt], ah0, ah1, ah2, ah3, bh0, bh1);
                mma8(acc[nt], ah0, ah1, ah2, ah3, bl0, bl1);
                mma8(acc[nt], al0, al1, al2, al3, bh0, bh1);
            }
        }
        __syncthreads();
    }

    // ---- epilogue: bias, store, fused projections ----
    int r0 = m0 + w * 16 + gid;
#pragma unroll
    for (int nt = 0; nt < 16; nt++) {
        int col = nt * 8 + (tig << 1);
        float2 b2 = *(const float2*)(bias + col);
        acc[nt][0] += b2.x; acc[nt][1] += b2.y;
        acc[nt][2] += b2.x; acc[nt][3] += b2.y;
        if (r0 < M)
            *(float2*)(C + (size_t)r0 * 128 + col) = make_float2(acc[nt][0], acc[nt][1]);
        if (r0 + 8 < M)
            *(float2*)(C + (size_t)(r0 + 8) * 128 + col) = make_float2(acc[nt][2], acc[nt][3]);
    }

    // projections: p[v][0]=row0 h0, [1]=row0 h1, [2]=row1 h0, [3]=row1 h1
    {
        float p[4][4];
#pragma unroll
        for (int v = 0; v < 4; v++)
#pragma unroll
            for (int j = 0; j < 4; j++) p[v][j] = 0.f;
        const float* vs[4] = {v0, v1, v2, v3};
#pragma unroll
        for (int v = 0; v < 4; v++) {
            if (v >= nv) break;
            const float* vv = vs[v];
#pragma unroll
            for (int nt = 0; nt < 16; nt++) {
                int col = nt * 8 + (tig << 1);
                float2 vvc = *(const float2*)(vv + col);
                int hh = (nt < 8) ? 0 : 1;
                p[v][hh]     += acc[nt][0] * vvc.x + acc[nt][1] * vvc.y;
                p[v][hh + 2] += acc[nt][2] * vvc.x + acc[nt][3] * vvc.y;
            }
#pragma unroll
            for (int j = 0; j < 4; j++) {
                p[v][j] += __shfl_xor_sync(0xffffffffu, p[v][j], 1);
                p[v][j] += __shfl_xor_sync(0xffffffffu, p[v][j], 2);
            }
        }
        if (tig == 0) {
#pragma unroll
            for (int v = 0; v < 4; v++) {
                if (v >= nv) break;
                if (r0 < M)
                    *(float2*)(projOut + ((size_t)v * M + r0) * 2) =
                        make_float2(p[v][0], p[v][1]);
                if (r0 + 8 < M)
                    *(float2*)(projOut + ((size_t)v * M + r0 + 8) * 2) =
                        make_float2(p[v][2], p[v][3]);
            }
        }
    }
}

// ---------------------------------------------------------------------------
// mma_score: score[blockIdx.y] += sum q[n]*tanh((relu(A_y)@Wk + bk)[m,n])
// single-pass tf32; grid = (tiles, 2); A_y = y==0 ? o0 : o1.
// ---------------------------------------------------------------------------
__global__ __launch_bounds__(256) void mma_score_kernel(
    const float* __restrict__ Aa, const float* __restrict__ Ab,
    const float* __restrict__ W, const float* __restrict__ bias,
    const float* __restrict__ q, int M, double* __restrict__ outScore)
{
    __shared__ uint32_t As[128 * 32];
    __shared__ uint32_t Bs[128 * 32];
    __shared__ float red[8];
    const float* A = (blockIdx.y == 0) ? Aa : Ab;
    const int tid = threadIdx.x;
    const int w   = tid >> 5, lane = tid & 31;
    const int gid = lane >> 2, tig = lane & 3;
    const int m0  = blockIdx.x * 128;

    float acc[16][4];
#pragma unroll
    for (int i = 0; i < 16; i++)
#pragma unroll
        for (int j = 0; j < 4; j++) acc[i][j] = 0.f;

    for (int kc = 0; kc < 128; kc += 32) {
        for (int i = tid; i < 1024; i += 256) {
            int r  = i >> 3;
            int c4 = (i & 7) << 2;
            float4 v = make_float4(0.f, 0.f, 0.f, 0.f);
            if (m0 + r < M)
                v = *(const float4*)(A + (size_t)(m0 + r) * 128 + kc + c4);
            float e[4] = {fmaxf(v.x, 0.f), fmaxf(v.y, 0.f),
                          fmaxf(v.z, 0.f), fmaxf(v.w, 0.f)};
            int rot = (r & 7) << 2;
#pragma unroll
            for (int j = 0; j < 4; j++)
                As[r * 32 + (((c4 + j) + rot) & 31)] = to_tf32(e[j]);
        }
        for (int i = tid; i < 4096; i += 256) {
            int n = i & 127, k = i >> 7;
            Bs[n * 32 + ((k + ((n & 7) << 2)) & 31)] =
                to_tf32(W[(size_t)(kc + k) * 128 + n]);
        }
        __syncthreads();

#pragma unroll
        for (int ks = 0; ks < 4; ks++) {
            int k0 = ks * 8;
            int ra = w * 16 + gid;
            int rot = gid << 2;
            uint32_t a0 = As[ra * 32 + ((k0 + tig + rot) & 31)];
            uint32_t a1 = As[(ra + 8) * 32 + ((k0 + tig + rot) & 31)];
            uint32_t a2 = As[ra * 32 + ((k0 + tig + 4 + rot) & 31)];
            uint32_t a3 = As[(ra + 8) * 32 + ((k0 + tig + 4 + rot) & 31)];
#pragma unroll
            for (int nt = 0; nt < 16; nt++) {
                int n = nt * 8 + gid;
                uint32_t b0 = Bs[n * 32 + ((k0 + tig + rot) & 31)];
                uint32_t b1 = Bs[n * 32 + ((k0 + tig + 4 + rot) & 31)];
                mma8(acc[nt], a0, a1, a2, a3, b0, b1);
            }
        }
        __syncthreads();
    }

    float local = 0.f;
    int r0 = m0 + w * 16 + gid;
#pragma unroll
    for (int nt = 0; nt < 16; nt++) {
        int col = nt * 8 + (tig << 1);
        float2 b2 = *(const float2*)(bias + col);
        float2 q2 = *(const float2*)(q + col);
        if (r0 < M) {
            local += q2.x * tanhf(acc[nt][0] + b2.x);
            local += q2.y * tanhf(acc[nt][1] + b2.y);
        }
        if (r0 + 8 < M) {
            local += q2.x * tanhf(acc[nt][2] + b2.x);
            local += q2.y * tanhf(acc[nt][3] + b2.y);
        }
    }
#pragma unroll
    for (int o = 16; o > 0; o >>= 1)
        local += __shfl_xor_sync(0xffffffffu, local, o);
    if (lane == 0) red[w] = local;
    __syncthreads();
    if (tid == 0) {
        double s = 0.0;
        for (int i = 0; i < 8; i++) s += (double)red[i];
        atomicAdd(outScore + blockIdx.y, s);
    }
}

// ---------------------------------------------------------------------------
// Segment init / edge passes (2-pass softmax: exp w/o max shift)
// ---------------------------------------------------------------------------
__global__ void init_seg_kernel(float* __restrict__ out, float* __restrict__ s,
                                int ndst)
{
    int i = blockIdx.x * blockDim.x + threadIdx.x;
    if (i < ndst * 128) out[i] = 0.f;
    if (i < ndst * 2) s[i] = 0.f;
}

// pass1: e = exp(leaky_relu(psrc[src]+pdst[dst])), store, segment-sum
__global__ __launch_bounds__(256) void edge_pass1_kernel(
    const int* __restrict__ src, const int* __restrict__ dst, int E,
    const float* __restrict__ psrc, const float* __restrict__ pdst,
    float* __restrict__ elog, float* __restrict__ ssum)
{
    int e = blockIdx.x * blockDim.x + threadIdx.x;
    if (e >= E) return;
    int s = src[e], d = dst[e];
    float2 ps = *(const float2*)(psrc + 2 * (size_t)s);
    float2 pd = *(const float2*)(pdst + 2 * (size_t)d);
    float a0 = ps.x + pd.x; a0 = a0 > 0.f ? a0 : 0.2f * a0;
    float a1 = ps.y + pd.y; a1 = a1 > 0.f ? a1 : 0.2f * a1;
    float e0 = expf(a0), e1 = expf(a1);
    *(float2*)(elog + 2 * (size_t)e) = make_float2(e0, e1);
    atomicAdd(ssum + 2 * (size_t)d + 0, e0);
    atomicAdd(ssum + 2 * (size_t)d + 1, e1);
}

// pass2: out[dst] += h_src[src] * e/(s+1e-16)  (warp per edge, red.v4)
__global__ __launch_bounds__(256) void edge_aggregate_kernel(
    const int* __restrict__ src, const int* __restrict__ dst, int E,
    const float* __restrict__ elog, const float* __restrict__ ssum,
    const float* __restrict__ hsrc, float* __restrict__ out)
{
    int gw   = (blockIdx.x * blockDim.x + threadIdx.x) >> 5;
    int lane = threadIdx.x & 31;
    if (gw >= E) return;
    int s = src[gw], d = dst[gw];
    int head = lane >> 4;
    float el = elog[2 * (size_t)gw + head];
    float sv = ssum[2 * (size_t)d + head];
    float alpha = el / (sv + 1e-16f);
    float4 v = *(const float4*)(hsrc + (size_t)s * 128 + lane * 4);
    v.x *= alpha; v.y *= alpha; v.z *= alpha; v.w *= alpha;
    float* op = out + (size_t)d * 128 + lane * 4;
    asm volatile("red.global.add.v4.f32 [%0], {%1,%2,%3,%4};"
                 :: "l"(op), "f"(v.x), "f"(v.y), "f"(v.z), "f"(v.w)
                 : "memory");
}

// ---------------------------------------------------------------------------
// Semantic attention tail
// ---------------------------------------------------------------------------
__global__ void zero_score_kernel(double* sc) { sc[0] = 0.0; sc[1] = 0.0; }

__global__ void softmax2_kernel(const double* __restrict__ sc,
                                float* __restrict__ w, double invN)
{
    double s0 = sc[0] * invN, s1 = sc[1] * invN;
    double mx = s0 > s1 ? s0 : s1;
    double e0 = exp(s0 - mx), e1 = exp(s1 - mx);
    double sum = e0 + e1;
    w[0] = (float)(e0 / sum);
    w[1] = (float)(e1 / sum);
}

// ---------------------------------------------------------------------------
// MLP weight collapse (single kernel)
// ---------------------------------------------------------------------------
__global__ __launch_bounds__(256) void precompute_kernel(
    const float* __restrict__ Wl1, const float* __restrict__ bl1,
    const float* __restrict__ Wl2, const float* __restrict__ bl2,
    const float* __restrict__ Wl3, const float* __restrict__ bl3,
    float* __restrict__ W123, float* __restrict__ bfin)
{
    __shared__ float W23[256 * 8];
    __shared__ float t1s[128];
    int tid = threadIdx.x;
    for (int i = tid; i < 2048; i += 256) {
        int r = i >> 3, j = i & 7;
        float a = 0.f;
        for (int c = 0; c < 128; c++) a += Wl2[r * 128 + c] * Wl3[c * 8 + j];
        W23[i] = a;
    }
    for (int n = tid; n < 128; n += 256) {
        float a = bl2[n];
        for (int k = 0; k < 256; k++) a += bl1[k] * Wl2[k * 128 + n];
        t1s[n] = a;
    }
    __syncthreads();
    for (int i = tid; i < 1024; i += 256) {
        int k = i >> 3, j = i & 7;
        float a = 0.f;
        for (int r = 0; r < 256; r++) a += Wl1[k * 256 + r] * W23[r * 8 + j];
        W123[i] = a;
    }
    if (tid < 8) {
        float a = bl3[tid];
        for (int c = 0; c < 128; c++) a += t1s[c] * Wl3[c * 8 + tid];
        bfin[tid] = a;
    }
}

// out[row,j] = sigmoid((w0*relu(o0)+w1*relu(o1))[row,:] @ W123[:,j] + bfin[j])
__global__ __launch_bounds__(256) void mlp_final_kernel(
    const float* __restrict__ o0, const float* __restrict__ o1,
    const float* __restrict__ wbuf, const float* __restrict__ W123,
    const float* __restrict__ bfin, float* __restrict__ out, int No)
{
    __shared__ float Ws[128 * 8];
    __shared__ float bs[8];
    for (int i = threadIdx.x; i < 128 * 8; i += blockDim.x) Ws[i] = W123[i];
    if (threadIdx.x < 8) bs[threadIdx.x] = bfin[threadIdx.x];
    __syncthreads();
    float w0 = wbuf[0], w1 = wbuf[1];
    int gid = blockIdx.x * blockDim.x + threadIdx.x;
    int row = gid >> 3, j = gid & 7;
    if (row >= No) return;
    const float* r0 = o0 + (size_t)row * 128;
    const float* r1 = o1 + (size_t)row * 128;
    float acc = 0.f;
#pragma unroll
    for (int k = 0; k < 128; k += 4) {
        float4 a = *(const float4*)(r0 + k);
        float4 b = *(const float4*)(r1 + k);
        float x0 = w0 * fmaxf(a.x, 0.f) + w1 * fmaxf(b.x, 0.f);
        float x1 = w0 * fmaxf(a.y, 0.f) + w1 * fmaxf(b.y, 0.f);
        float x2 = w0 * fmaxf(a.z, 0.f) + w1 * fmaxf(b.z, 0.f);
        float x3 = w0 * fmaxf(a.w, 0.f) + w1 * fmaxf(b.w, 0.f);
        acc += x0 * Ws[(k + 0) * 8 + j];
        acc += x1 * Ws[(k + 1) * 8 + j];
        acc += x2 * Ws[(k + 2) * 8 + j];
        acc += x3 * Ws[(k + 3) * 8 + j];
    }
    float x = acc + bs[j];
    out[(size_t)row * 8 + j] = 1.f / (1.f + expf(-x));
}

// ---------------------------------------------------------------------------
// Host orchestration
// ---------------------------------------------------------------------------
static inline int ceil_div(int a, int b) { return (a + b - 1) / b; }

extern "C" void kernel_launch(void* const* d_in, const int* in_sizes, int n_in,
                              void* d_out, int out_size)
{
    const float* xo  = (const float*)d_in[0];
    const float* xa  = (const float*)d_in[1];
    const int*   eoo = (const int*)d_in[2];
    const int*   eoa = (const int*)d_in[3];
    const int*   eao = (const int*)d_in[4];
    const int No  = in_sizes[0] / 128;
    const int Na  = in_sizes[1] / 128;
    const int Eoo = in_sizes[2] / 2;
    const int Eoa = in_sizes[3] / 2;
    const int Eao = in_sizes[4] / 2;

    float *ho, *ha, *o0, *o1, *oa, *elog, *s, *pobj, *patt, *w;
    float *W123, *bfin;
    double* score;
    cudaGetSymbolAddress((void**)&ho,    g_ho);
    cudaGetSymbolAddress((void**)&ha,    g_ha);
    cudaGetSymbolAddress((void**)&o0,    g_o0);
    cudaGetSymbolAddress((void**)&o1,    g_o1);
    cudaGetSymbolAddress((void**)&oa,    g_oa);
    cudaGetSymbolAddress((void**)&elog,  g_elog);
    cudaGetSymbolAddress((void**)&s,     g_s);
    cudaGetSymbolAddress((void**)&pobj,  g_pobj);
    cudaGetSymbolAddress((void**)&patt,  g_patt);
    cudaGetSymbolAddress((void**)&score, g_score);
    cudaGetSymbolAddress((void**)&w,     g_w);
    cudaGetSymbolAddress((void**)&W123,  g_W123);
    cudaGetSymbolAddress((void**)&bfin,  g_bfin);

    const int FEAT_SMEM = 65536;
    cudaFuncSetAttribute(mma_feat_kernel,
                         cudaFuncAttributeMaxDynamicSharedMemorySize, FEAT_SMEM);

    const int tilesNo = ceil_div(No, 128);
    const int tilesNa = ceil_div(Na, 128);

    precompute_kernel<<<1, 256>>>(
        (const float*)d_in[23], (const float*)d_in[24], (const float*)d_in[25],
        (const float*)d_in[26], (const float*)d_in[27], (const float*)d_in[28],
        W123, bfin);

    for (int layer = 0; layer < 2; layer++) {
        const int base = 5 + 9 * layer;
        const float* Wo   = (const float*)d_in[base + 0];
        const float* bo   = (const float*)d_in[base + 1];
        const float* Wa   = (const float*)d_in[base + 2];
        const float* ba   = (const float*)d_in[base + 3];
        const float* asrc = (const float*)d_in[base + 4];
        const float* adst = (const float*)d_in[base + 5];
        const float* Wk   = (const float*)d_in[base + 6];
        const float* bk   = (const float*)d_in[base + 7];
        const float* q    = (const float*)d_in[base + 8];

        // feature transforms + fused projections
        if (layer == 0) {
            mma_feat_kernel<<<tilesNo, 256, FEAT_SMEM>>>(
                xo, xo, w, Wo, bo, ho, No, 0,
                4, asrc + 0, asrc + 128, adst + 0, adst + 256, pobj);
            mma_feat_kernel<<<tilesNa, 256, FEAT_SMEM>>>(
                xa, xa, w, Wa, ba, ha, Na, 0,
                2, asrc + 256, adst + 128, asrc, asrc, patt);
        } else {
            // object input = w0*relu(o0)+w1*relu(o1); attribute input = relu(oa)
            mma_feat_kernel<<<tilesNo, 256, FEAT_SMEM>>>(
                o0, o1, w, Wo, bo, ho, No, 2,
                4, asrc + 0, asrc + 128, adst + 0, adst + 256, pobj);
            mma_feat_kernel<<<tilesNa, 256, FEAT_SMEM>>>(
                oa, oa, w, Wa, ba, ha, Na, 1,
                2, asrc + 256, adst + 128, asrc, asrc, patt);
        }

        // --- oo: object -> object (metapath 0) ---
        {
            const int* esrc = eoo; const int* edst = eoo + Eoo;
            init_seg_kernel<<<ceil_div(No * 128, 256), 256>>>(o0, s, No);
            edge_pass1_kernel<<<ceil_div(Eoo, 256), 256>>>(
                esrc, edst, Eoo, pobj + 0, pobj + (size_t)2 * No * 2, elog, s);
            edge_aggregate_kernel<<<ceil_div(Eoo * 32, 256), 256>>>(
                esrc, edst, Eoo, elog, s, ho, o0);
        }
        // --- oa: object -> attribute (layer-1 result only is used) ---
        if (layer == 0) {
            const int* esrc = eoa; const int* edst = eoa + Eoa;
            init_seg_kernel<<<ceil_div(Na * 128, 256), 256>>>(oa, s, Na);
            edge_pass1_kernel<<<ceil_div(Eoa, 256), 256>>>(
                esrc, edst, Eoa, pobj + (size_t)1 * No * 2, patt + (size_t)1 * Na * 2,
                elog, s);
            edge_aggregate_kernel<<<ceil_div(Eoa * 32, 256), 256>>>(
                esrc, edst, Eoa, elog, s, ho, oa);
        }
        // --- ao: attribute -> object (metapath 1) ---
        {
            const int* esrc = eao; const int* edst = eao + Eao;
            init_seg_kernel<<<ceil_div(No * 128, 256), 256>>>(o1, s, No);
            edge_pass1_kernel<<<ceil_div(Eao, 256), 256>>>(
                esrc, edst, Eao, patt + 0, pobj + (size_t)3 * No * 2, elog, s);
            edge_aggregate_kernel<<<ceil_div(Eao * 32, 256), 256>>>(
                esrc, edst, Eao, elog, s, ha, o1);
        }

        zero_score_kernel<<<1, 1>>>(score);
        mma_score_kernel<<<dim3(tilesNo, 2), 256>>>(o0, o1, Wk, bk, q, No, score);
        softmax2_kernel<<<1, 1>>>(score, w, 1.0 / (double)No);
    }

    mlp_final_kernel<<<ceil_div(No * 8, 256), 256>>>(
        o0, o1, w, W123, bfin, (float*)d_out, No);
}

// round 8
// speedup vs baseline: 1.6715x; 1.0033x over previous
#include <cuda_runtime.h>
#include <math.h>
#include <stdint.h>

// ============================================================================
// HAN: 2-layer heterogeneous GAT + semantic attention + collapsed MLP head.
// R7: - zero-init via cudaMemsetAsync (graph-capturable) instead of kernels
//     - edge passes batched across edge types via grid.y (per-type elog/ssum)
//     - else identical to R6 (tf32 mma.sync 3-pass feat GEMM + fused proj,
//       2-pass max-free segment softmax, fused combine, collapsed MLP)
// ============================================================================

#define MAXNO 100096
#define MAXNA 50048
#define MAXE  500224

__device__ float  g_ho[MAXNO * 128];
__device__ float  g_ha[MAXNA * 128];
__device__ float  g_o0[MAXNO * 128];
__device__ float  g_o1[MAXNO * 128];
__device__ float  g_oa[MAXNA * 128];
__device__ float  g_elog[3 * MAXE * 2];
__device__ float  g_s[3 * MAXNO * 2];
__device__ float  g_pobj[4 * MAXNO * 2];
__device__ float  g_patt[2 * MAXNA * 2];
__device__ double g_score[2];
__device__ float  g_w[2];
__device__ float  g_W123[128 * 8];
__device__ float  g_bfin[8];

struct EdgeBatch {
    const int*   src[3];
    const int*   dst[3];
    const float* psrc[3];
    const float* pdst[3];
    float*       elog[3];
    float*       ssum[3];
    const float* hsrc[3];
    float*       outp[3];
    int          E[3];
};

// ---------------------------------------------------------------------------
// mma.sync helpers
// ---------------------------------------------------------------------------
__device__ __forceinline__ void mma8(float* c,
                                     uint32_t a0, uint32_t a1, uint32_t a2, uint32_t a3,
                                     uint32_t b0, uint32_t b1)
{
    asm volatile(
        "mma.sync.aligned.m16n8k8.row.col.f32.tf32.tf32.f32 "
        "{%0,%1,%2,%3}, {%4,%5,%6,%7}, {%8,%9}, {%0,%1,%2,%3};"
        : "+f"(c[0]), "+f"(c[1]), "+f"(c[2]), "+f"(c[3])
        : "r"(a0), "r"(a1), "r"(a2), "r"(a3), "r"(b0), "r"(b1));
}

__device__ __forceinline__ uint32_t to_tf32(float x) {
    uint32_t r;
    asm("cvt.rna.tf32.f32 %0, %1;" : "=r"(r) : "f"(x));
    return r;
}
__device__ __forceinline__ float tf32_hi(float x) {
    return __uint_as_float(__float_as_uint(x) & 0xffffe000u);
}

// ---------------------------------------------------------------------------
// mma_feat: C[M,128] = op(A)[M,128] @ W[128,128] + bias, 3-pass tf32 split,
// with node projections fused into the epilogue.
// mode: 0 = plain A, 1 = relu(A), 2 = A := w0*relu(A)+w1*relu(A2)
// ---------------------------------------------------------------------------
__global__ __launch_bounds__(256) void mma_feat_kernel(
    const float* __restrict__ A, const float* __restrict__ A2,
    const float* __restrict__ wbuf, const float* __restrict__ W,
    const float* __restrict__ bias, float* __restrict__ C, int M, int mode,
    int nv, const float* __restrict__ v0, const float* __restrict__ v1,
    const float* __restrict__ v2, const float* __restrict__ v3,
    float* __restrict__ projOut)
{
    extern __shared__ float2 fsm[];          // [0,4096) A, [4096,8192) B
    float2* Asm = fsm;
    float2* Bsm = fsm + 4096;
    const int tid  = threadIdx.x;
    const int w    = tid >> 5, lane = tid & 31;
    const int gid  = lane >> 2, tig = lane & 3;
    const int m0   = blockIdx.x * 128;

    float cw0 = 0.f, cw1 = 0.f;
    if (mode == 2) { cw0 = wbuf[0]; cw1 = wbuf[1]; }

    float acc[16][4];
#pragma unroll
    for (int i = 0; i < 16; i++)
#pragma unroll
        for (int j = 0; j < 4; j++) acc[i][j] = 0.f;

    for (int kc = 0; kc < 128; kc += 32) {
        for (int i = tid; i < 1024; i += 256) {
            int r  = i >> 3;
            int c4 = (i & 7) << 2;
            float4 v = make_float4(0.f, 0.f, 0.f, 0.f);
            if (m0 + r < M) {
                v = *(const float4*)(A + (size_t)(m0 + r) * 128 + kc + c4);
                if (mode == 1) {
                    v.x = fmaxf(v.x, 0.f); v.y = fmaxf(v.y, 0.f);
                    v.z = fmaxf(v.z, 0.f); v.w = fmaxf(v.w, 0.f);
                } else if (mode == 2) {
                    float4 u = *(const float4*)(A2 + (size_t)(m0 + r) * 128 + kc + c4);
                    v.x = cw0 * fmaxf(v.x, 0.f) + cw1 * fmaxf(u.x, 0.f);
                    v.y = cw0 * fmaxf(v.y, 0.f) + cw1 * fmaxf(u.y, 0.f);
                    v.z = cw0 * fmaxf(v.z, 0.f) + cw1 * fmaxf(u.z, 0.f);
                    v.w = cw0 * fmaxf(v.w, 0.f) + cw1 * fmaxf(u.w, 0.f);
                }
            }
            float e[4] = {v.x, v.y, v.z, v.w};
            int rot = (r & 7) << 2;
#pragma unroll
            for (int j = 0; j < 4; j++) {
                float hi = tf32_hi(e[j]);
                float lo = __uint_as_float(to_tf32(e[j] - hi));
                Asm[r * 32 + (((c4 + j) + rot) & 31)] = make_float2(hi, lo);
            }
        }
        for (int i = tid; i < 4096; i += 256) {
            int n = i & 127, k = i >> 7;
            float x = W[(size_t)(kc + k) * 128 + n];
            float hi = tf32_hi(x);
            float lo = __uint_as_float(to_tf32(x - hi));
            Bsm[n * 32 + ((k + ((n & 7) << 2)) & 31)] = make_float2(hi, lo);
        }
        __syncthreads();

#pragma unroll
        for (int ks = 0; ks < 4; ks++) {
            int k0 = ks * 8;
            int ra = w * 16 + gid;
            int rot = gid << 2;
            float2 A0 = Asm[ra * 32 + ((k0 + tig + rot) & 31)];
            float2 A1 = Asm[(ra + 8) * 32 + ((k0 + tig + rot) & 31)];
            float2 A2r = Asm[ra * 32 + ((k0 + tig + 4 + rot) & 31)];
            float2 A3 = Asm[(ra + 8) * 32 + ((k0 + tig + 4 + rot) & 31)];
            uint32_t ah0 = __float_as_uint(A0.x), ah1 = __float_as_uint(A1.x);
            uint32_t ah2 = __float_as_uint(A2r.x), ah3 = __float_as_uint(A3.x);
            uint32_t al0 = __float_as_uint(A0.y), al1 = __float_as_uint(A1.y);
            uint32_t al2 = __float_as_uint(A2r.y), al3 = __float_as_uint(A3.y);
#pragma unroll
            for (int nt = 0; nt < 16; nt++) {
                int n = nt * 8 + gid;
                float2 B0 = Bsm[n * 32 + ((k0 + tig + rot) & 31)];
                float2 B1 = Bsm[n * 32 + ((k0 + tig + 4 + rot) & 31)];
                uint32_t bh0 = __float_as_uint(B0.x), bh1 = __float_as_uint(B1.x);
                uint32_t bl0 = __float_as_uint(B0.y), bl1 = __float_as_uint(B1.y);
                mma8(acc[nt], ah0, ah1, ah2, ah3, bh0, bh1);
                mma8(acc[nt], ah0, ah1, ah2, ah3, bl0, bl1);
                mma8(acc[nt], al0, al1, al2, al3, bh0, bh1);
            }
        }
        __syncthreads();
    }

    int r0 = m0 + w * 16 + gid;
#pragma unroll
    for (int nt = 0; nt < 16; nt++) {
        int col = nt * 8 + (tig << 1);
        float2 b2 = *(const float2*)(bias + col);
        acc[nt][0] += b2.x; acc[nt][1] += b2.y;
        acc[nt][2] += b2.x; acc[nt][3] += b2.y;
        if (r0 < M)
            *(float2*)(C + (size_t)r0 * 128 + col) = make_float2(acc[nt][0], acc[nt][1]);
        if (r0 + 8 < M)
            *(float2*)(C + (size_t)(r0 + 8) * 128 + col) = make_float2(acc[nt][2], acc[nt][3]);
    }

    {
        float p[4][4];
#pragma unroll
        for (int v = 0; v < 4; v++)
#pragma unroll
            for (int j = 0; j < 4; j++) p[v][j] = 0.f;
        const float* vs[4] = {v0, v1, v2, v3};
#pragma unroll
        for (int v = 0; v < 4; v++) {
            if (v >= nv) break;
            const float* vv = vs[v];
#pragma unroll
            for (int nt = 0; nt < 16; nt++) {
                int col = nt * 8 + (tig << 1);
                float2 vvc = *(const float2*)(vv + col);
                int hh = (nt < 8) ? 0 : 1;
                p[v][hh]     += acc[nt][0] * vvc.x + acc[nt][1] * vvc.y;
                p[v][hh + 2] += acc[nt][2] * vvc.x + acc[nt][3] * vvc.y;
            }
#pragma unroll
            for (int j = 0; j < 4; j++) {
                p[v][j] += __shfl_xor_sync(0xffffffffu, p[v][j], 1);
                p[v][j] += __shfl_xor_sync(0xffffffffu, p[v][j], 2);
            }
        }
        if (tig == 0) {
#pragma unroll
            for (int v = 0; v < 4; v++) {
                if (v >= nv) break;
                if (r0 < M)
                    *(float2*)(projOut + ((size_t)v * M + r0) * 2) =
                        make_float2(p[v][0], p[v][1]);
                if (r0 + 8 < M)
                    *(float2*)(projOut + ((size_t)v * M + r0 + 8) * 2) =
                        make_float2(p[v][2], p[v][3]);
            }
        }
    }
}

// ---------------------------------------------------------------------------
// mma_score: score[blockIdx.y] += sum q[n]*tanh((relu(A_y)@Wk + bk)[m,n])
// ---------------------------------------------------------------------------
__global__ __launch_bounds__(256) void mma_score_kernel(
    const float* __restrict__ Aa, const float* __restrict__ Ab,
    const float* __restrict__ W, const float* __restrict__ bias,
    const float* __restrict__ q, int M, double* __restrict__ outScore)
{
    __shared__ uint32_t As[128 * 32];
    __shared__ uint32_t Bs[128 * 32];
    __shared__ float red[8];
    const float* A = (blockIdx.y == 0) ? Aa : Ab;
    const int tid = threadIdx.x;
    const int w   = tid >> 5, lane = tid & 31;
    const int gid = lane >> 2, tig = lane & 3;
    const int m0  = blockIdx.x * 128;

    float acc[16][4];
#pragma unroll
    for (int i = 0; i < 16; i++)
#pragma unroll
        for (int j = 0; j < 4; j++) acc[i][j] = 0.f;

    for (int kc = 0; kc < 128; kc += 32) {
        for (int i = tid; i < 1024; i += 256) {
            int r  = i >> 3;
            int c4 = (i & 7) << 2;
            float4 v = make_float4(0.f, 0.f, 0.f, 0.f);
            if (m0 + r < M)
                v = *(const float4*)(A + (size_t)(m0 + r) * 128 + kc + c4);
            float e[4] = {fmaxf(v.x, 0.f), fmaxf(v.y, 0.f),
                          fmaxf(v.z, 0.f), fmaxf(v.w, 0.f)};
            int rot = (r & 7) << 2;
#pragma unroll
            for (int j = 0; j < 4; j++)
                As[r * 32 + (((c4 + j) + rot) & 31)] = to_tf32(e[j]);
        }
        for (int i = tid; i < 4096; i += 256) {
            int n = i & 127, k = i >> 7;
            Bs[n * 32 + ((k + ((n & 7) << 2)) & 31)] =
                to_tf32(W[(size_t)(kc + k) * 128 + n]);
        }
        __syncthreads();

#pragma unroll
        for (int ks = 0; ks < 4; ks++) {
            int k0 = ks * 8;
            int ra = w * 16 + gid;
            int rot = gid << 2;
            uint32_t a0 = As[ra * 32 + ((k0 + tig + rot) & 31)];
            uint32_t a1 = As[(ra + 8) * 32 + ((k0 + tig + rot) & 31)];
            uint32_t a2 = As[ra * 32 + ((k0 + tig + 4 + rot) & 31)];
            uint32_t a3 = As[(ra + 8) * 32 + ((k0 + tig + 4 + rot) & 31)];
#pragma unroll
            for (int nt = 0; nt < 16; nt++) {
                int n = nt * 8 + gid;
                uint32_t b0 = Bs[n * 32 + ((k0 + tig + rot) & 31)];
                uint32_t b1 = Bs[n * 32 + ((k0 + tig + 4 + rot) & 31)];
                mma8(acc[nt], a0, a1, a2, a3, b0, b1);
            }
        }
        __syncthreads();
    }

    float local = 0.f;
    int r0 = m0 + w * 16 + gid;
#pragma unroll
    for (int nt = 0; nt < 16; nt++) {
        int col = nt * 8 + (tig << 1);
        float2 b2 = *(const float2*)(bias + col);
        float2 q2 = *(const float2*)(q + col);
        if (r0 < M) {
            local += q2.x * tanhf(acc[nt][0] + b2.x);
            local += q2.y * tanhf(acc[nt][1] + b2.y);
        }
        if (r0 + 8 < M) {
            local += q2.x * tanhf(acc[nt][2] + b2.x);
            local += q2.y * tanhf(acc[nt][3] + b2.y);
        }
    }
#pragma unroll
    for (int o = 16; o > 0; o >>= 1)
        local += __shfl_xor_sync(0xffffffffu, local, o);
    if (lane == 0) red[w] = local;
    __syncthreads();
    if (tid == 0) {
        double s = 0.0;
        for (int i = 0; i < 8; i++) s += (double)red[i];
        atomicAdd(outScore + blockIdx.y, s);
    }
}

// ---------------------------------------------------------------------------
// Batched edge passes (grid.y selects edge type)
// ---------------------------------------------------------------------------
__global__ __launch_bounds__(256) void edge_pass1_kernel(EdgeBatch eb)
{
    int t = blockIdx.y;
    int e = blockIdx.x * blockDim.x + threadIdx.x;
    if (e >= eb.E[t]) return;
    const int* src = eb.src[t];
    const int* dst = eb.dst[t];
    int s = src[e], d = dst[e];
    float2 ps = *(const float2*)(eb.psrc[t] + 2 * (size_t)s);
    float2 pd = *(const float2*)(eb.pdst[t] + 2 * (size_t)d);
    float a0 = ps.x + pd.x; a0 = a0 > 0.f ? a0 : 0.2f * a0;
    float a1 = ps.y + pd.y; a1 = a1 > 0.f ? a1 : 0.2f * a1;
    float e0 = expf(a0), e1 = expf(a1);
    *(float2*)(eb.elog[t] + 2 * (size_t)e) = make_float2(e0, e1);
    atomicAdd(eb.ssum[t] + 2 * (size_t)d + 0, e0);
    atomicAdd(eb.ssum[t] + 2 * (size_t)d + 1, e1);
}

__global__ __launch_bounds__(256) void edge_aggregate_kernel(EdgeBatch eb)
{
    int t = blockIdx.y;
    int gw   = (blockIdx.x * blockDim.x + threadIdx.x) >> 5;
    int lane = threadIdx.x & 31;
    if (gw >= eb.E[t]) return;
    int s = eb.src[t][gw], d = eb.dst[t][gw];
    int head = lane >> 4;
    float el = eb.elog[t][2 * (size_t)gw + head];
    float sv = eb.ssum[t][2 * (size_t)d + head];
    float alpha = el / (sv + 1e-16f);
    float4 v = *(const float4*)(eb.hsrc[t] + (size_t)s * 128 + lane * 4);
    v.x *= alpha; v.y *= alpha; v.z *= alpha; v.w *= alpha;
    float* op = eb.outp[t] + (size_t)d * 128 + lane * 4;
    asm volatile("red.global.add.v4.f32 [%0], {%1,%2,%3,%4};"
                 :: "l"(op), "f"(v.x), "f"(v.y), "f"(v.z), "f"(v.w)
                 : "memory");
}

// ---------------------------------------------------------------------------
// Semantic attention tail + MLP
// ---------------------------------------------------------------------------
__global__ void softmax2_kernel(const double* __restrict__ sc,
                                float* __restrict__ w, double invN)
{
    double s0 = sc[0] * invN, s1 = sc[1] * invN;
    double mx = s0 > s1 ? s0 : s1;
    double e0 = exp(s0 - mx), e1 = exp(s1 - mx);
    double sum = e0 + e1;
    w[0] = (float)(e0 / sum);
    w[1] = (float)(e1 / sum);
}

__global__ __launch_bounds__(256) void precompute_kernel(
    const float* __restrict__ Wl1, const float* __restrict__ bl1,
    const float* __restrict__ Wl2, const float* __restrict__ bl2,
    const float* __restrict__ Wl3, const float* __restrict__ bl3,
    float* __restrict__ W123, float* __restrict__ bfin)
{
    __shared__ float W23[256 * 8];
    __shared__ float t1s[128];
    int tid = threadIdx.x;
    for (int i = tid; i < 2048; i += 256) {
        int r = i >> 3, j = i & 7;
        float a = 0.f;
        for (int c = 0; c < 128; c++) a += Wl2[r * 128 + c] * Wl3[c * 8 + j];
        W23[i] = a;
    }
    for (int n = tid; n < 128; n += 256) {
        float a = bl2[n];
        for (int k = 0; k < 256; k++) a += bl1[k] * Wl2[k * 128 + n];
        t1s[n] = a;
    }
    __syncthreads();
    for (int i = tid; i < 1024; i += 256) {
        int k = i >> 3, j = i & 7;
        float a = 0.f;
        for (int r = 0; r < 256; r++) a += Wl1[k * 256 + r] * W23[r * 8 + j];
        W123[i] = a;
    }
    if (tid < 8) {
        float a = bl3[tid];
        for (int c = 0; c < 128; c++) a += t1s[c] * Wl3[c * 8 + tid];
        bfin[tid] = a;
    }
}

__global__ __launch_bounds__(256) void mlp_final_kernel(
    const float* __restrict__ o0, const float* __restrict__ o1,
    const float* __restrict__ wbuf, const float* __restrict__ W123,
    const float* __restrict__ bfin, float* __restrict__ out, int No)
{
    __shared__ float Ws[128 * 8];
    __shared__ float bs[8];
    for (int i = threadIdx.x; i < 128 * 8; i += blockDim.x) Ws[i] = W123[i];
    if (threadIdx.x < 8) bs[threadIdx.x] = bfin[threadIdx.x];
    __syncthreads();
    float w0 = wbuf[0], w1 = wbuf[1];
    int gid = blockIdx.x * blockDim.x + threadIdx.x;
    int row = gid >> 3, j = gid & 7;
    if (row >= No) return;
    const float* r0 = o0 + (size_t)row * 128;
    const float* r1 = o1 + (size_t)row * 128;
    float acc = 0.f;
#pragma unroll
    for (int k = 0; k < 128; k += 4) {
        float4 a = *(const float4*)(r0 + k);
        float4 b = *(const float4*)(r1 + k);
        float x0 = w0 * fmaxf(a.x, 0.f) + w1 * fmaxf(b.x, 0.f);
        float x1 = w0 * fmaxf(a.y, 0.f) + w1 * fmaxf(b.y, 0.f);
        float x2 = w0 * fmaxf(a.z, 0.f) + w1 * fmaxf(b.z, 0.f);
        float x3 = w0 * fmaxf(a.w, 0.f) + w1 * fmaxf(b.w, 0.f);
        acc += x0 * Ws[(k + 0) * 8 + j];
        acc += x1 * Ws[(k + 1) * 8 + j];
        acc += x2 * Ws[(k + 2) * 8 + j];
        acc += x3 * Ws[(k + 3) * 8 + j];
    }
    float x = acc + bs[j];
    out[(size_t)row * 8 + j] = 1.f / (1.f + expf(-x));
}

// ---------------------------------------------------------------------------
// Host orchestration
// ---------------------------------------------------------------------------
static inline int ceil_div(int a, int b) { return (a + b - 1) / b; }

extern "C" void kernel_launch(void* const* d_in, const int* in_sizes, int n_in,
                              void* d_out, int out_size)
{
    const float* xo  = (const float*)d_in[0];
    const float* xa  = (const float*)d_in[1];
    const int*   eoo = (const int*)d_in[2];
    const int*   eoa = (const int*)d_in[3];
    const int*   eao = (const int*)d_in[4];
    const int No  = in_sizes[0] / 128;
    const int Na  = in_sizes[1] / 128;
    const int Eoo = in_sizes[2] / 2;
    const int Eoa = in_sizes[3] / 2;
    const int Eao = in_sizes[4] / 2;

    float *ho, *ha, *o0, *o1, *oa, *elog, *s, *pobj, *patt, *w;
    float *W123, *bfin;
    double* score;
    cudaGetSymbolAddress((void**)&ho,    g_ho);
    cudaGetSymbolAddress((void**)&ha,    g_ha);
    cudaGetSymbolAddress((void**)&o0,    g_o0);
    cudaGetSymbolAddress((void**)&o1,    g_o1);
    cudaGetSymbolAddress((void**)&oa,    g_oa);
    cudaGetSymbolAddress((void**)&elog,  g_elog);
    cudaGetSymbolAddress((void**)&s,     g_s);
    cudaGetSymbolAddress((void**)&pobj,  g_pobj);
    cudaGetSymbolAddress((void**)&patt,  g_patt);
    cudaGetSymbolAddress((void**)&score, g_score);
    cudaGetSymbolAddress((void**)&w,     g_w);
    cudaGetSymbolAddress((void**)&W123,  g_W123);
    cudaGetSymbolAddress((void**)&bfin,  g_bfin);

    const int FEAT_SMEM = 65536;
    cudaFuncSetAttribute(mma_feat_kernel,
                         cudaFuncAttributeMaxDynamicSharedMemorySize, FEAT_SMEM);

    const int tilesNo = ceil_div(No, 128);
    const int tilesNa = ceil_div(Na, 128);

    precompute_kernel<<<1, 256>>>(
        (const float*)d_in[23], (const float*)d_in[24], (const float*)d_in[25],
        (const float*)d_in[26], (const float*)d_in[27], (const float*)d_in[28],
        W123, bfin);

    for (int layer = 0; layer < 2; layer++) {
        const int base = 5 + 9 * layer;
        const float* Wo   = (const float*)d_in[base + 0];
        const float* bo   = (const float*)d_in[base + 1];
        const float* Wa   = (const float*)d_in[base + 2];
        const float* ba   = (const float*)d_in[base + 3];
        const float* asrc = (const float*)d_in[base + 4];
        const float* adst = (const float*)d_in[base + 5];
        const float* Wk   = (const float*)d_in[base + 6];
        const float* bk   = (const float*)d_in[base + 7];
        const float* q    = (const float*)d_in[base + 8];

        // feature transforms + fused projections (read o0/o1/oa of prev layer)
        if (layer == 0) {
            mma_feat_kernel<<<tilesNo, 256, FEAT_SMEM>>>(
                xo, xo, w, Wo, bo, ho, No, 0,
                4, asrc + 0, asrc + 128, adst + 0, adst + 256, pobj);
            mma_feat_kernel<<<tilesNa, 256, FEAT_SMEM>>>(
                xa, xa, w, Wa, ba, ha, Na, 0,
                2, asrc + 256, adst + 128, asrc, asrc, patt);
        } else {
            mma_feat_kernel<<<tilesNo, 256, FEAT_SMEM>>>(
                o0, o1, w, Wo, bo, ho, No, 2,
                4, asrc + 0, asrc + 128, adst + 0, adst + 256, pobj);
            mma_feat_kernel<<<tilesNa, 256, FEAT_SMEM>>>(
                oa, oa, w, Wa, ba, ha, Na, 1,
                2, asrc + 256, adst + 128, asrc, asrc, patt);
        }

        const int ntypes = (layer == 0) ? 3 : 2;

        // zero accumulators + segment sums AFTER feat kernels consumed them
        cudaMemsetAsync(o0, 0, (size_t)No * 128 * sizeof(float));
        cudaMemsetAsync(o1, 0, (size_t)No * 128 * sizeof(float));
        if (layer == 0)
            cudaMemsetAsync(oa, 0, (size_t)Na * 128 * sizeof(float));
        cudaMemsetAsync(s, 0, (size_t)ntypes * MAXNO * 2 * sizeof(float));

        EdgeBatch eb;
        // type 0: oo (object->object, metapath 0)
        eb.src[0] = eoo; eb.dst[0] = eoo + Eoo; eb.E[0] = Eoo;
        eb.psrc[0] = pobj + 0; eb.pdst[0] = pobj + (size_t)2 * No * 2;
        eb.elog[0] = elog; eb.ssum[0] = s;
        eb.hsrc[0] = ho; eb.outp[0] = o0;
        // type 1: ao (attribute->object, metapath 1)
        eb.src[1] = eao; eb.dst[1] = eao + Eao; eb.E[1] = Eao;
        eb.psrc[1] = patt + 0; eb.pdst[1] = pobj + (size_t)3 * No * 2;
        eb.elog[1] = elog + (size_t)MAXE * 2; eb.ssum[1] = s + (size_t)MAXNO * 2;
        eb.hsrc[1] = ha; eb.outp[1] = o1;
        // type 2: oa (object->attribute), layer 0 only
        eb.src[2] = eoa; eb.dst[2] = eoa + Eoa; eb.E[2] = (layer == 0) ? Eoa : 0;
        eb.psrc[2] = pobj + (size_t)1 * No * 2; eb.pdst[2] = patt + (size_t)1 * Na * 2;
        eb.elog[2] = elog + (size_t)2 * MAXE * 2; eb.ssum[2] = s + (size_t)2 * MAXNO * 2;
        eb.hsrc[2] = ho; eb.outp[2] = oa;

        int maxE = Eoo > Eao ? Eoo : Eao;
        if (ntypes == 3 && Eoa > maxE) maxE = Eoa;
        edge_pass1_kernel<<<dim3(ceil_div(maxE, 256), ntypes), 256>>>(eb);
        edge_aggregate_kernel<<<dim3(ceil_div(maxE * 32, 256), ntypes), 256>>>(eb);

        cudaMemsetAsync(score, 0, 2 * sizeof(double));
        mma_score_kernel<<<dim3(tilesNo, 2), 256>>>(o0, o1, Wk, bk, q, No, score);
        softmax2_kernel<<<1, 1>>>(score, w, 1.0 / (double)No);
    }

    mlp_final_kernel<<<ceil_div(No * 8, 256), 256>>>(
        o0, o1, w, W123, bfin, (float*)d_out, No);
}

// round 9
// speedup vs baseline: 1.6888x; 1.0103x over previous
#include <cuda_runtime.h>
#include <math.h>
#include <stdint.h>

// ============================================================================
// HAN: 2-layer heterogeneous GAT + semantic attention + collapsed MLP head.
// R9: GEMM warps retiled 16x128 -> 32x64 (2 m-tiles share B frags): smem
//     crossbar traffic per MMA cut 1.5x, now at tensor floor. Projection
//     epilogue simplifies (head == colgroup, no cross-warp reduce).
// Else identical to R7/R8.
// ============================================================================

#define MAXNO 100096
#define MAXNA 50048
#define MAXE  500224

__device__ float  g_ho[MAXNO * 128];
__device__ float  g_ha[MAXNA * 128];
__device__ float  g_o0[MAXNO * 128];
__device__ float  g_o1[MAXNO * 128];
__device__ float  g_oa[MAXNA * 128];
__device__ float  g_elog[3 * MAXE * 2];
__device__ float  g_s[3 * MAXNO * 2];
__device__ float  g_pobj[4 * MAXNO * 2];
__device__ float  g_patt[2 * MAXNA * 2];
__device__ double g_score[2];
__device__ float  g_w[2];
__device__ float  g_W123[128 * 8];
__device__ float  g_bfin[8];

struct EdgeBatch {
    const int*   src[3];
    const int*   dst[3];
    const float* psrc[3];
    const float* pdst[3];
    float*       elog[3];
    float*       ssum[3];
    const float* hsrc[3];
    float*       outp[3];
    int          E[3];
};

// ---------------------------------------------------------------------------
// mma.sync helpers
// ---------------------------------------------------------------------------
__device__ __forceinline__ void mma8(float* c,
                                     uint32_t a0, uint32_t a1, uint32_t a2, uint32_t a3,
                                     uint32_t b0, uint32_t b1)
{
    asm volatile(
        "mma.sync.aligned.m16n8k8.row.col.f32.tf32.tf32.f32 "
        "{%0,%1,%2,%3}, {%4,%5,%6,%7}, {%8,%9}, {%0,%1,%2,%3};"
        : "+f"(c[0]), "+f"(c[1]), "+f"(c[2]), "+f"(c[3])
        : "r"(a0), "r"(a1), "r"(a2), "r"(a3), "r"(b0), "r"(b1));
}

__device__ __forceinline__ uint32_t to_tf32(float x) {
    uint32_t r;
    asm("cvt.rna.tf32.f32 %0, %1;" : "=r"(r) : "f"(x));
    return r;
}
__device__ __forceinline__ float tf32_hi(float x) {
    return __uint_as_float(__float_as_uint(x) & 0xffffe000u);
}

// ---------------------------------------------------------------------------
// mma_feat: C[M,128] = op(A)[M,128] @ W[128,128] + bias, 3-pass tf32 split,
// node projections fused into epilogue.
// 8 warps: warp w -> rowgroup rw=w>>1 (rows [32rw,32rw+32)), colgroup cw=w&1
// (cols [64cw, 64cw+64)). head(cw) projection computed fully in-warp.
// mode: 0 = plain A, 1 = relu(A), 2 = A := w0*relu(A)+w1*relu(A2)
// ---------------------------------------------------------------------------
__global__ __launch_bounds__(256) void mma_feat_kernel(
    const float* __restrict__ A, const float* __restrict__ A2,
    const float* __restrict__ wbuf, const float* __restrict__ W,
    const float* __restrict__ bias, float* __restrict__ C, int M, int mode,
    int nv, const float* __restrict__ v0, const float* __restrict__ v1,
    const float* __restrict__ v2, const float* __restrict__ v3,
    float* __restrict__ projOut)
{
    extern __shared__ float2 fsm[];          // [0,4096) A, [4096,8192) B
    float2* Asm = fsm;
    float2* Bsm = fsm + 4096;
    const int tid  = threadIdx.x;
    const int w    = tid >> 5, lane = tid & 31;
    const int gid  = lane >> 2, tig = lane & 3;
    const int rw   = w >> 1, cw = w & 1;
    const int m0   = blockIdx.x * 128;

    float cw0 = 0.f, cw1 = 0.f;
    if (mode == 2) { cw0 = wbuf[0]; cw1 = wbuf[1]; }

    float acc[2][8][4];
#pragma unroll
    for (int mt = 0; mt < 2; mt++)
#pragma unroll
        for (int i = 0; i < 8; i++)
#pragma unroll
            for (int j = 0; j < 4; j++) acc[mt][i][j] = 0.f;

    for (int kc = 0; kc < 128; kc += 32) {
        for (int i = tid; i < 1024; i += 256) {
            int r  = i >> 3;
            int c4 = (i & 7) << 2;
            float4 v = make_float4(0.f, 0.f, 0.f, 0.f);
            if (m0 + r < M) {
                v = *(const float4*)(A + (size_t)(m0 + r) * 128 + kc + c4);
                if (mode == 1) {
                    v.x = fmaxf(v.x, 0.f); v.y = fmaxf(v.y, 0.f);
                    v.z = fmaxf(v.z, 0.f); v.w = fmaxf(v.w, 0.f);
                } else if (mode == 2) {
                    float4 u = *(const float4*)(A2 + (size_t)(m0 + r) * 128 + kc + c4);
                    v.x = cw0 * fmaxf(v.x, 0.f) + cw1 * fmaxf(u.x, 0.f);
                    v.y = cw0 * fmaxf(v.y, 0.f) + cw1 * fmaxf(u.y, 0.f);
                    v.z = cw0 * fmaxf(v.z, 0.f) + cw1 * fmaxf(u.z, 0.f);
                    v.w = cw0 * fmaxf(v.w, 0.f) + cw1 * fmaxf(u.w, 0.f);
                }
            }
            float e[4] = {v.x, v.y, v.z, v.w};
            int rot = (r & 7) << 2;
#pragma unroll
            for (int j = 0; j < 4; j++) {
                float hi = tf32_hi(e[j]);
                float lo = __uint_as_float(to_tf32(e[j] - hi));
                Asm[r * 32 + (((c4 + j) + rot) & 31)] = make_float2(hi, lo);
            }
        }
        for (int i = tid; i < 4096; i += 256) {
            int n = i & 127, k = i >> 7;
            float x = W[(size_t)(kc + k) * 128 + n];
            float hi = tf32_hi(x);
            float lo = __uint_as_float(to_tf32(x - hi));
            Bsm[n * 32 + ((k + ((n & 7) << 2)) & 31)] = make_float2(hi, lo);
        }
        __syncthreads();

#pragma unroll
        for (int ks = 0; ks < 4; ks++) {
            int k0 = ks * 8;
            int rot = gid << 2;
            uint32_t ah[2][4], al[2][4];
#pragma unroll
            for (int mt = 0; mt < 2; mt++) {
                int ra = rw * 32 + mt * 16 + gid;
                float2 A0 = Asm[ra * 32 + ((k0 + tig + rot) & 31)];
                float2 A1 = Asm[(ra + 8) * 32 + ((k0 + tig + rot) & 31)];
                float2 A2r = Asm[ra * 32 + ((k0 + tig + 4 + rot) & 31)];
                float2 A3 = Asm[(ra + 8) * 32 + ((k0 + tig + 4 + rot) & 31)];
                ah[mt][0] = __float_as_uint(A0.x); al[mt][0] = __float_as_uint(A0.y);
                ah[mt][1] = __float_as_uint(A1.x); al[mt][1] = __float_as_uint(A1.y);
                ah[mt][2] = __float_as_uint(A2r.x); al[mt][2] = __float_as_uint(A2r.y);
                ah[mt][3] = __float_as_uint(A3.x); al[mt][3] = __float_as_uint(A3.y);
            }
#pragma unroll
            for (int nt = 0; nt < 8; nt++) {
                int n = cw * 64 + nt * 8 + gid;
                float2 B0 = Bsm[n * 32 + ((k0 + tig + rot) & 31)];
                float2 B1 = Bsm[n * 32 + ((k0 + tig + 4 + rot) & 31)];
                uint32_t bh0 = __float_as_uint(B0.x), bh1 = __float_as_uint(B1.x);
                uint32_t bl0 = __float_as_uint(B0.y), bl1 = __float_as_uint(B1.y);
#pragma unroll
                for (int mt = 0; mt < 2; mt++) {
                    mma8(acc[mt][nt], ah[mt][0], ah[mt][1], ah[mt][2], ah[mt][3], bh0, bh1);
                    mma8(acc[mt][nt], ah[mt][0], ah[mt][1], ah[mt][2], ah[mt][3], bl0, bl1);
                    mma8(acc[mt][nt], al[mt][0], al[mt][1], al[mt][2], al[mt][3], bh0, bh1);
                }
            }
        }
        __syncthreads();
    }

    // ---- epilogue: bias + store ----
    int r0 = m0 + rw * 32 + gid;
#pragma unroll
    for (int mt = 0; mt < 2; mt++) {
        int rA = r0 + mt * 16;
#pragma unroll
        for (int nt = 0; nt < 8; nt++) {
            int col = cw * 64 + nt * 8 + (tig << 1);
            float2 b2 = *(const float2*)(bias + col);
            acc[mt][nt][0] += b2.x; acc[mt][nt][1] += b2.y;
            acc[mt][nt][2] += b2.x; acc[mt][nt][3] += b2.y;
            if (rA < M)
                *(float2*)(C + (size_t)rA * 128 + col) =
                    make_float2(acc[mt][nt][0], acc[mt][nt][1]);
            if (rA + 8 < M)
                *(float2*)(C + (size_t)(rA + 8) * 128 + col) =
                    make_float2(acc[mt][nt][2], acc[mt][nt][3]);
        }
    }

    // ---- fused projections: this warp's cols == head cw entirely ----
    {
        const float* vs[4] = {v0, v1, v2, v3};
#pragma unroll
        for (int v = 0; v < 4; v++) {
            if (v >= nv) break;
            const float* vv = vs[v];
            float p[4] = {0.f, 0.f, 0.f, 0.f};   // rows r0, r0+8, r0+16, r0+24
#pragma unroll
            for (int mt = 0; mt < 2; mt++)
#pragma unroll
                for (int nt = 0; nt < 8; nt++) {
                    int col = cw * 64 + nt * 8 + (tig << 1);
                    float2 vvc = *(const float2*)(vv + col);
                    p[2 * mt + 0] += acc[mt][nt][0] * vvc.x + acc[mt][nt][1] * vvc.y;
                    p[2 * mt + 1] += acc[mt][nt][2] * vvc.x + acc[mt][nt][3] * vvc.y;
                }
#pragma unroll
            for (int j = 0; j < 4; j++) {
                p[j] += __shfl_xor_sync(0xffffffffu, p[j], 1);
                p[j] += __shfl_xor_sync(0xffffffffu, p[j], 2);
            }
            if (tig == 0) {
#pragma unroll
                for (int j = 0; j < 4; j++) {
                    int row = r0 + j * 8;
                    if (row < M)
                        projOut[((size_t)v * M + row) * 2 + cw] = p[j];
                }
            }
        }
    }
}

// ---------------------------------------------------------------------------
// mma_score: score[blockIdx.y] += sum q[n]*tanh((relu(A_y)@Wk + bk)[m,n])
// same 32x64 warp tiling, single-pass tf32.
// ---------------------------------------------------------------------------
__global__ __launch_bounds__(256) void mma_score_kernel(
    const float* __restrict__ Aa, const float* __restrict__ Ab,
    const float* __restrict__ W, const float* __restrict__ bias,
    const float* __restrict__ q, int M, double* __restrict__ outScore)
{
    __shared__ uint32_t As[128 * 32];
    __shared__ uint32_t Bs[128 * 32];
    __shared__ float red[8];
    const float* A = (blockIdx.y == 0) ? Aa : Ab;
    const int tid = threadIdx.x;
    const int w   = tid >> 5, lane = tid & 31;
    const int gid = lane >> 2, tig = lane & 3;
    const int rw  = w >> 1, cw = w & 1;
    const int m0  = blockIdx.x * 128;

    float acc[2][8][4];
#pragma unroll
    for (int mt = 0; mt < 2; mt++)
#pragma unroll
        for (int i = 0; i < 8; i++)
#pragma unroll
            for (int j = 0; j < 4; j++) acc[mt][i][j] = 0.f;

    for (int kc = 0; kc < 128; kc += 32) {
        for (int i = tid; i < 1024; i += 256) {
            int r  = i >> 3;
            int c4 = (i & 7) << 2;
            float4 v = make_float4(0.f, 0.f, 0.f, 0.f);
            if (m0 + r < M)
                v = *(const float4*)(A + (size_t)(m0 + r) * 128 + kc + c4);
            float e[4] = {fmaxf(v.x, 0.f), fmaxf(v.y, 0.f),
                          fmaxf(v.z, 0.f), fmaxf(v.w, 0.f)};
            int rot = (r & 7) << 2;
#pragma unroll
            for (int j = 0; j < 4; j++)
                As[r * 32 + (((c4 + j) + rot) & 31)] = to_tf32(e[j]);
        }
        for (int i = tid; i < 4096; i += 256) {
            int n = i & 127, k = i >> 7;
            Bs[n * 32 + ((k + ((n & 7) << 2)) & 31)] =
                to_tf32(W[(size_t)(kc + k) * 128 + n]);
        }
        __syncthreads();

#pragma unroll
        for (int ks = 0; ks < 4; ks++) {
            int k0 = ks * 8;
            int rot = gid << 2;
            uint32_t a[2][4];
#pragma unroll
            for (int mt = 0; mt < 2; mt++) {
                int ra = rw * 32 + mt * 16 + gid;
                a[mt][0] = As[ra * 32 + ((k0 + tig + rot) & 31)];
                a[mt][1] = As[(ra + 8) * 32 + ((k0 + tig + rot) & 31)];
                a[mt][2] = As[ra * 32 + ((k0 + tig + 4 + rot) & 31)];
                a[mt][3] = As[(ra + 8) * 32 + ((k0 + tig + 4 + rot) & 31)];
            }
#pragma unroll
            for (int nt = 0; nt < 8; nt++) {
                int n = cw * 64 + nt * 8 + gid;
                uint32_t b0 = Bs[n * 32 + ((k0 + tig + rot) & 31)];
                uint32_t b1 = Bs[n * 32 + ((k0 + tig + 4 + rot) & 31)];
#pragma unroll
                for (int mt = 0; mt < 2; mt++)
                    mma8(acc[mt][nt], a[mt][0], a[mt][1], a[mt][2], a[mt][3], b0, b1);
            }
        }
        __syncthreads();
    }

    float local = 0.f;
    int r0 = m0 + rw * 32 + gid;
#pragma unroll
    for (int mt = 0; mt < 2; mt++) {
        int rA = r0 + mt * 16;
#pragma unroll
        for (int nt = 0; nt < 8; nt++) {
            int col = cw * 64 + nt * 8 + (tig << 1);
            float2 b2 = *(const float2*)(bias + col);
            float2 q2 = *(const float2*)(q + col);
            if (rA < M) {
                local += q2.x * tanhf(acc[mt][nt][0] + b2.x);
                local += q2.y * tanhf(acc[mt][nt][1] + b2.y);
            }
            if (rA + 8 < M) {
                local += q2.x * tanhf(acc[mt][nt][2] + b2.x);
                local += q2.y * tanhf(acc[mt][nt][3] + b2.y);
            }
        }
    }
#pragma unroll
    for (int o = 16; o > 0; o >>= 1)
        local += __shfl_xor_sync(0xffffffffu, local, o);
    if (lane == 0) red[w] = local;
    __syncthreads();
    if (tid == 0) {
        double s = 0.0;
        for (int i = 0; i < 8; i++) s += (double)red[i];
        atomicAdd(outScore + blockIdx.y, s);
    }
}

// ---------------------------------------------------------------------------
// Batched edge passes (grid.y selects edge type)
// ---------------------------------------------------------------------------
__global__ __launch_bounds__(256) void edge_pass1_kernel(EdgeBatch eb)
{
    int t = blockIdx.y;
    int e = blockIdx.x * blockDim.x + threadIdx.x;
    if (e >= eb.E[t]) return;
    int s = eb.src[t][e], d = eb.dst[t][e];
    float2 ps = *(const float2*)(eb.psrc[t] + 2 * (size_t)s);
    float2 pd = *(const float2*)(eb.pdst[t] + 2 * (size_t)d);
    float a0 = ps.x + pd.x; a0 = a0 > 0.f ? a0 : 0.2f * a0;
    float a1 = ps.y + pd.y; a1 = a1 > 0.f ? a1 : 0.2f * a1;
    float e0 = expf(a0), e1 = expf(a1);
    *(float2*)(eb.elog[t] + 2 * (size_t)e) = make_float2(e0, e1);
    atomicAdd(eb.ssum[t] + 2 * (size_t)d + 0, e0);
    atomicAdd(eb.ssum[t] + 2 * (size_t)d + 1, e1);
}

__global__ __launch_bounds__(256) void edge_aggregate_kernel(EdgeBatch eb)
{
    int t = blockIdx.y;
    int gw   = (blockIdx.x * blockDim.x + threadIdx.x) >> 5;
    int lane = threadIdx.x & 31;
    if (gw >= eb.E[t]) return;
    int s = eb.src[t][gw], d = eb.dst[t][gw];
    int head = lane >> 4;
    float el = eb.elog[t][2 * (size_t)gw + head];
    float sv = eb.ssum[t][2 * (size_t)d + head];
    float alpha = el / (sv + 1e-16f);
    float4 v = *(const float4*)(eb.hsrc[t] + (size_t)s * 128 + lane * 4);
    v.x *= alpha; v.y *= alpha; v.z *= alpha; v.w *= alpha;
    float* op = eb.outp[t] + (size_t)d * 128 + lane * 4;
    asm volatile("red.global.add.v4.f32 [%0], {%1,%2,%3,%4};"
                 :: "l"(op), "f"(v.x), "f"(v.y), "f"(v.z), "f"(v.w)
                 : "memory");
}

// ---------------------------------------------------------------------------
// Semantic attention tail + MLP
// ---------------------------------------------------------------------------
__global__ void softmax2_kernel(const double* __restrict__ sc,
                                float* __restrict__ w, double invN)
{
    double s0 = sc[0] * invN, s1 = sc[1] * invN;
    double mx = s0 > s1 ? s0 : s1;
    double e0 = exp(s0 - mx), e1 = exp(s1 - mx);
    double sum = e0 + e1;
    w[0] = (float)(e0 / sum);
    w[1] = (float)(e1 / sum);
}

__global__ __launch_bounds__(256) void precompute_kernel(
    const float* __restrict__ Wl1, const float* __restrict__ bl1,
    const float* __restrict__ Wl2, const float* __restrict__ bl2,
    const float* __restrict__ Wl3, const float* __restrict__ bl3,
    float* __restrict__ W123, float* __restrict__ bfin)
{
    __shared__ float W23[256 * 8];
    __shared__ float t1s[128];
    int tid = threadIdx.x;
    for (int i = tid; i < 2048; i += 256) {
        int r = i >> 3, j = i & 7;
        float a = 0.f;
        for (int c = 0; c < 128; c++) a += Wl2[r * 128 + c] * Wl3[c * 8 + j];
        W23[i] = a;
    }
    for (int n = tid; n < 128; n += 256) {
        float a = bl2[n];
        for (int k = 0; k < 256; k++) a += bl1[k] * Wl2[k * 128 + n];
        t1s[n] = a;
    }
    __syncthreads();
    for (int i = tid; i < 1024; i += 256) {
        int k = i >> 3, j = i & 7;
        float a = 0.f;
        for (int r = 0; r < 256; r++) a += Wl1[k * 256 + r] * W23[r * 8 + j];
        W123[i] = a;
    }
    if (tid < 8) {
        float a = bl3[tid];
        for (int c = 0; c < 128; c++) a += t1s[c] * Wl3[c * 8 + tid];
        bfin[tid] = a;
    }
}

__global__ __launch_bounds__(256) void mlp_final_kernel(
    const float* __restrict__ o0, const float* __restrict__ o1,
    const float* __restrict__ wbuf, const float* __restrict__ W123,
    const float* __restrict__ bfin, float* __restrict__ out, int No)
{
    __shared__ float Ws[128 * 8];
    __shared__ float bs[8];
    for (int i = threadIdx.x; i < 128 * 8; i += blockDim.x) Ws[i] = W123[i];
    if (threadIdx.x < 8) bs[threadIdx.x] = bfin[threadIdx.x];
    __syncthreads();
    float w0 = wbuf[0], w1 = wbuf[1];
    int gid = blockIdx.x * blockDim.x + threadIdx.x;
    int row = gid >> 3, j = gid & 7;
    if (row >= No) return;
    const float* r0 = o0 + (size_t)row * 128;
    const float* r1 = o1 + (size_t)row * 128;
    float acc = 0.f;
#pragma unroll
    for (int k = 0; k < 128; k += 4) {
        float4 a = *(const float4*)(r0 + k);
        float4 b = *(const float4*)(r1 + k);
        float x0 = w0 * fmaxf(a.x, 0.f) + w1 * fmaxf(b.x, 0.f);
        float x1 = w0 * fmaxf(a.y, 0.f) + w1 * fmaxf(b.y, 0.f);
        float x2 = w0 * fmaxf(a.z, 0.f) + w1 * fmaxf(b.z, 0.f);
        float x3 = w0 * fmaxf(a.w, 0.f) + w1 * fmaxf(b.w, 0.f);
        acc += x0 * Ws[(k + 0) * 8 + j];
        acc += x1 * Ws[(k + 1) * 8 + j];
        acc += x2 * Ws[(k + 2) * 8 + j];
        acc += x3 * Ws[(k + 3) * 8 + j];
    }
    float x = acc + bs[j];
    out[(size_t)row * 8 + j] = 1.f / (1.f + expf(-x));
}

// ---------------------------------------------------------------------------
// Host orchestration
// ---------------------------------------------------------------------------
static inline int ceil_div(int a, int b) { return (a + b - 1) / b; }

extern "C" void kernel_launch(void* const* d_in, const int* in_sizes, int n_in,
                              void* d_out, int out_size)
{
    const float* xo  = (const float*)d_in[0];
    const float* xa  = (const float*)d_in[1];
    const int*   eoo = (const int*)d_in[2];
    const int*   eoa = (const int*)d_in[3];
    const int*   eao = (const int*)d_in[4];
    const int No  = in_sizes[0] / 128;
    const int Na  = in_sizes[1] / 128;
    const int Eoo = in_sizes[2] / 2;
    const int Eoa = in_sizes[3] / 2;
    const int Eao = in_sizes[4] / 2;

    float *ho, *ha, *o0, *o1, *oa, *elog, *s, *pobj, *patt, *w;
    float *W123, *bfin;
    double* score;
    cudaGetSymbolAddress((void**)&ho,    g_ho);
    cudaGetSymbolAddress((void**)&ha,    g_ha);
    cudaGetSymbolAddress((void**)&o0,    g_o0);
    cudaGetSymbolAddress((void**)&o1,    g_o1);
    cudaGetSymbolAddress((void**)&oa,    g_oa);
    cudaGetSymbolAddress((void**)&elog,  g_elog);
    cudaGetSymbolAddress((void**)&s,     g_s);
    cudaGetSymbolAddress((void**)&pobj,  g_pobj);
    cudaGetSymbolAddress((void**)&patt,  g_patt);
    cudaGetSymbolAddress((void**)&score, g_score);
    cudaGetSymbolAddress((void**)&w,     g_w);
    cudaGetSymbolAddress((void**)&W123,  g_W123);
    cudaGetSymbolAddress((void**)&bfin,  g_bfin);

    const int FEAT_SMEM = 65536;
    cudaFuncSetAttribute(mma_feat_kernel,
                         cudaFuncAttributeMaxDynamicSharedMemorySize, FEAT_SMEM);

    const int tilesNo = ceil_div(No, 128);
    const int tilesNa = ceil_div(Na, 128);

    precompute_kernel<<<1, 256>>>(
        (const float*)d_in[23], (const float*)d_in[24], (const float*)d_in[25],
        (const float*)d_in[26], (const float*)d_in[27], (const float*)d_in[28],
        W123, bfin);

    for (int layer = 0; layer < 2; layer++) {
        const int base = 5 + 9 * layer;
        const float* Wo   = (const float*)d_in[base + 0];
        const float* bo   = (const float*)d_in[base + 1];
        const float* Wa   = (const float*)d_in[base + 2];
        const float* ba   = (const float*)d_in[base + 3];
        const float* asrc = (const float*)d_in[base + 4];
        const float* adst = (const float*)d_in[base + 5];
        const float* Wk   = (const float*)d_in[base + 6];
        const float* bk   = (const float*)d_in[base + 7];
        const float* q    = (const float*)d_in[base + 8];

        if (layer == 0) {
            mma_feat_kernel<<<tilesNo, 256, FEAT_SMEM>>>(
                xo, xo, w, Wo, bo, ho, No, 0,
                4, asrc + 0, asrc + 128, adst + 0, adst + 256, pobj);
            mma_feat_kernel<<<tilesNa, 256, FEAT_SMEM>>>(
                xa, xa, w, Wa, ba, ha, Na, 0,
                2, asrc + 256, adst + 128, asrc, asrc, patt);
        } else {
            mma_feat_kernel<<<tilesNo, 256, FEAT_SMEM>>>(
                o0, o1, w, Wo, bo, ho, No, 2,
                4, asrc + 0, asrc + 128, adst + 0, adst + 256, pobj);
            mma_feat_kernel<<<tilesNa, 256, FEAT_SMEM>>>(
                oa, oa, w, Wa, ba, ha, Na, 1,
                2, asrc + 256, adst + 128, asrc, asrc, patt);
        }

        const int ntypes = (layer == 0) ? 3 : 2;

        cudaMemsetAsync(o0, 0, (size_t)No * 128 * sizeof(float));
        cudaMemsetAsync(o1, 0, (size_t)No * 128 * sizeof(float));
        if (layer == 0)
            cudaMemsetAsync(oa, 0, (size_t)Na * 128 * sizeof(float));
        cudaMemsetAsync(s, 0, (size_t)ntypes * MAXNO * 2 * sizeof(float));

        EdgeBatch eb;
        eb.src[0] = eoo; eb.dst[0] = eoo + Eoo; eb.E[0] = Eoo;
        eb.psrc[0] = pobj + 0; eb.pdst[0] = pobj + (size_t)2 * No * 2;
        eb.elog[0] = elog; eb.ssum[0] = s;
        eb.hsrc[0] = ho; eb.outp[0] = o0;
        eb.src[1] = eao; eb.dst[1] = eao + Eao; eb.E[1] = Eao;
        eb.psrc[1] = patt + 0; eb.pdst[1] = pobj + (size_t)3 * No * 2;
        eb.elog[1] = elog + (size_t)MAXE * 2; eb.ssum[1] = s + (size_t)MAXNO * 2;
        eb.hsrc[1] = ha; eb.outp[1] = o1;
        eb.src[2] = eoa; eb.dst[2] = eoa + Eoa; eb.E[2] = (layer == 0) ? Eoa : 0;
        eb.psrc[2] = pobj + (size_t)1 * No * 2; eb.pdst[2] = patt + (size_t)1 * Na * 2;
        eb.elog[2] = elog + (size_t)2 * MAXE * 2; eb.ssum[2] = s + (size_t)2 * MAXNO * 2;
        eb.hsrc[2] = ho; eb.outp[2] = oa;

        int maxE = Eoo > Eao ? Eoo : Eao;
        if (ntypes == 3 && Eoa > maxE) maxE = Eoa;
        edge_pass1_kernel<<<dim3(ceil_div(maxE, 256), ntypes), 256>>>(eb);
        edge_aggregate_kernel<<<dim3(ceil_div(maxE * 32, 256), ntypes), 256>>>(eb);

        cudaMemsetAsync(score, 0, 2 * sizeof(double));
        mma_score_kernel<<<dim3(tilesNo, 2), 256>>>(o0, o1, Wk, bk, q, No, score);
        softmax2_kernel<<<1, 1>>>(score, w, 1.0 / (double)No);
    }

    mlp_final_kernel<<<ceil_div(No * 8, 256), 256>>>(
        o0, o1, w, W123, bfin, (float*)d_out, No);
}

// round 10
// speedup vs baseline: 2.0755x; 1.2290x over previous
#include <cuda_runtime.h>
#include <math.h>
#include <stdint.h>

// ============================================================================
// HAN: 2-layer heterogeneous GAT + semantic attention + collapsed MLP head.
// R10: edge aggregation CSR-ized. dst lists are launch-constant -> build CSR
//      once (hist + scan + scatter), then ONE warp-per-dst-node kernel per
//      layer does denominator + weighted gather + single coalesced store.
//      Removes: elog buffer, ssum atomics, output memsets, red.v4 write amp.
// GEMMs unchanged from R9 (tf32 mma.sync, 32x64 warp tile, fused projections).
// ============================================================================

#define MAXNO 100096
#define MAXNA 50048
#define MAXE  500224
#define NBMAX 128          // scan blocks (1024 elems each) >= ceil(MAXNO/1024)

__device__ float  g_ho[MAXNO * 128];
__device__ float  g_ha[MAXNA * 128];
__device__ float  g_o0[MAXNO * 128];
__device__ float  g_o1[MAXNO * 128];
__device__ float  g_oa[MAXNA * 128];
__device__ float  g_pobj[4 * MAXNO * 2];
__device__ float  g_patt[2 * MAXNA * 2];
__device__ double g_score[2];
__device__ float  g_w[2];
__device__ float  g_W123[128 * 8];
__device__ float  g_bfin[8];
// CSR scratch
__device__ int    g_cnt[3 * MAXNO];
__device__ int    g_rowptr[3 * (MAXNO + 1)];
__device__ int    g_csrc[3 * MAXE];
__device__ int    g_bsum[3 * NBMAX];

struct CsrBatch {
    const int*   csrc[3];
    const int*   rowptr[3];
    const float* psrc[3];
    const float* pdst[3];
    const float* hsrc[3];
    float*       outp[3];
    int          N[3];
};

// ---------------------------------------------------------------------------
// mma.sync helpers
// ---------------------------------------------------------------------------
__device__ __forceinline__ void mma8(float* c,
                                     uint32_t a0, uint32_t a1, uint32_t a2, uint32_t a3,
                                     uint32_t b0, uint32_t b1)
{
    asm volatile(
        "mma.sync.aligned.m16n8k8.row.col.f32.tf32.tf32.f32 "
        "{%0,%1,%2,%3}, {%4,%5,%6,%7}, {%8,%9}, {%0,%1,%2,%3};"
        : "+f"(c[0]), "+f"(c[1]), "+f"(c[2]), "+f"(c[3])
        : "r"(a0), "r"(a1), "r"(a2), "r"(a3), "r"(b0), "r"(b1));
}

__device__ __forceinline__ uint32_t to_tf32(float x) {
    uint32_t r;
    asm("cvt.rna.tf32.f32 %0, %1;" : "=r"(r) : "f"(x));
    return r;
}
__device__ __forceinline__ float tf32_hi(float x) {
    return __uint_as_float(__float_as_uint(x) & 0xffffe000u);
}

// ---------------------------------------------------------------------------
// mma_feat: C[M,128] = op(A)[M,128] @ W[128,128] + bias, 3-pass tf32 split,
// node projections fused. Warp tile 32x64 (rw=w>>1, cw=w&1). See R9 notes.
// mode: 0 = plain A, 1 = relu(A), 2 = A := w0*relu(A)+w1*relu(A2)
// ---------------------------------------------------------------------------
__global__ __launch_bounds__(256) void mma_feat_kernel(
    const float* __restrict__ A, const float* __restrict__ A2,
    const float* __restrict__ wbuf, const float* __restrict__ W,
    const float* __restrict__ bias, float* __restrict__ C, int M, int mode,
    int nv, const float* __restrict__ v0, const float* __restrict__ v1,
    const float* __restrict__ v2, const float* __restrict__ v3,
    float* __restrict__ projOut)
{
    extern __shared__ float2 fsm[];
    float2* Asm = fsm;
    float2* Bsm = fsm + 4096;
    const int tid  = threadIdx.x;
    const int w    = tid >> 5, lane = tid & 31;
    const int gid  = lane >> 2, tig = lane & 3;
    const int rw   = w >> 1, cw = w & 1;
    const int m0   = blockIdx.x * 128;

    float cw0 = 0.f, cw1 = 0.f;
    if (mode == 2) { cw0 = wbuf[0]; cw1 = wbuf[1]; }

    float acc[2][8][4];
#pragma unroll
    for (int mt = 0; mt < 2; mt++)
#pragma unroll
        for (int i = 0; i < 8; i++)
#pragma unroll
            for (int j = 0; j < 4; j++) acc[mt][i][j] = 0.f;

    for (int kc = 0; kc < 128; kc += 32) {
        for (int i = tid; i < 1024; i += 256) {
            int r  = i >> 3;
            int c4 = (i & 7) << 2;
            float4 v = make_float4(0.f, 0.f, 0.f, 0.f);
            if (m0 + r < M) {
                v = *(const float4*)(A + (size_t)(m0 + r) * 128 + kc + c4);
                if (mode == 1) {
                    v.x = fmaxf(v.x, 0.f); v.y = fmaxf(v.y, 0.f);
                    v.z = fmaxf(v.z, 0.f); v.w = fmaxf(v.w, 0.f);
                } else if (mode == 2) {
                    float4 u = *(const float4*)(A2 + (size_t)(m0 + r) * 128 + kc + c4);
                    v.x = cw0 * fmaxf(v.x, 0.f) + cw1 * fmaxf(u.x, 0.f);
                    v.y = cw0 * fmaxf(v.y, 0.f) + cw1 * fmaxf(u.y, 0.f);
                    v.z = cw0 * fmaxf(v.z, 0.f) + cw1 * fmaxf(u.z, 0.f);
                    v.w = cw0 * fmaxf(v.w, 0.f) + cw1 * fmaxf(u.w, 0.f);
                }
            }
            float e[4] = {v.x, v.y, v.z, v.w};
            int rot = (r & 7) << 2;
#pragma unroll
            for (int j = 0; j < 4; j++) {
                float hi = tf32_hi(e[j]);
                float lo = __uint_as_float(to_tf32(e[j] - hi));
                Asm[r * 32 + (((c4 + j) + rot) & 31)] = make_float2(hi, lo);
            }
        }
        for (int i = tid; i < 4096; i += 256) {
            int n = i & 127, k = i >> 7;
            float x = W[(size_t)(kc + k) * 128 + n];
            float hi = tf32_hi(x);
            float lo = __uint_as_float(to_tf32(x - hi));
            Bsm[n * 32 + ((k + ((n & 7) << 2)) & 31)] = make_float2(hi, lo);
        }
        __syncthreads();

#pragma unroll
        for (int ks = 0; ks < 4; ks++) {
            int k0 = ks * 8;
            int rot = gid << 2;
            uint32_t ah[2][4], al[2][4];
#pragma unroll
            for (int mt = 0; mt < 2; mt++) {
                int ra = rw * 32 + mt * 16 + gid;
                float2 A0 = Asm[ra * 32 + ((k0 + tig + rot) & 31)];
                float2 A1 = Asm[(ra + 8) * 32 + ((k0 + tig + rot) & 31)];
                float2 A2r = Asm[ra * 32 + ((k0 + tig + 4 + rot) & 31)];
                float2 A3 = Asm[(ra + 8) * 32 + ((k0 + tig + 4 + rot) & 31)];
                ah[mt][0] = __float_as_uint(A0.x); al[mt][0] = __float_as_uint(A0.y);
                ah[mt][1] = __float_as_uint(A1.x); al[mt][1] = __float_as_uint(A1.y);
                ah[mt][2] = __float_as_uint(A2r.x); al[mt][2] = __float_as_uint(A2r.y);
                ah[mt][3] = __float_as_uint(A3.x); al[mt][3] = __float_as_uint(A3.y);
            }
#pragma unroll
            for (int nt = 0; nt < 8; nt++) {
                int n = cw * 64 + nt * 8 + gid;
                float2 B0 = Bsm[n * 32 + ((k0 + tig + rot) & 31)];
                float2 B1 = Bsm[n * 32 + ((k0 + tig + 4 + rot) & 31)];
                uint32_t bh0 = __float_as_uint(B0.x), bh1 = __float_as_uint(B1.x);
                uint32_t bl0 = __float_as_uint(B0.y), bl1 = __float_as_uint(B1.y);
#pragma unroll
                for (int mt = 0; mt < 2; mt++) {
                    mma8(acc[mt][nt], ah[mt][0], ah[mt][1], ah[mt][2], ah[mt][3], bh0, bh1);
                    mma8(acc[mt][nt], ah[mt][0], ah[mt][1], ah[mt][2], ah[mt][3], bl0, bl1);
                    mma8(acc[mt][nt], al[mt][0], al[mt][1], al[mt][2], al[mt][3], bh0, bh1);
                }
            }
        }
        __syncthreads();
    }

    int r0 = m0 + rw * 32 + gid;
#pragma unroll
    for (int mt = 0; mt < 2; mt++) {
        int rA = r0 + mt * 16;
#pragma unroll
        for (int nt = 0; nt < 8; nt++) {
            int col = cw * 64 + nt * 8 + (tig << 1);
            float2 b2 = *(const float2*)(bias + col);
            acc[mt][nt][0] += b2.x; acc[mt][nt][1] += b2.y;
            acc[mt][nt][2] += b2.x; acc[mt][nt][3] += b2.y;
            if (rA < M)
                *(float2*)(C + (size_t)rA * 128 + col) =
                    make_float2(acc[mt][nt][0], acc[mt][nt][1]);
            if (rA + 8 < M)
                *(float2*)(C + (size_t)(rA + 8) * 128 + col) =
                    make_float2(acc[mt][nt][2], acc[mt][nt][3]);
        }
    }

    {
        const float* vs[4] = {v0, v1, v2, v3};
#pragma unroll
        for (int v = 0; v < 4; v++) {
            if (v >= nv) break;
            const float* vv = vs[v];
            float p[4] = {0.f, 0.f, 0.f, 0.f};
#pragma unroll
            for (int mt = 0; mt < 2; mt++)
#pragma unroll
                for (int nt = 0; nt < 8; nt++) {
                    int col = cw * 64 + nt * 8 + (tig << 1);
                    float2 vvc = *(const float2*)(vv + col);
                    p[2 * mt + 0] += acc[mt][nt][0] * vvc.x + acc[mt][nt][1] * vvc.y;
                    p[2 * mt + 1] += acc[mt][nt][2] * vvc.x + acc[mt][nt][3] * vvc.y;
                }
#pragma unroll
            for (int j = 0; j < 4; j++) {
                p[j] += __shfl_xor_sync(0xffffffffu, p[j], 1);
                p[j] += __shfl_xor_sync(0xffffffffu, p[j], 2);
            }
            if (tig == 0) {
#pragma unroll
                for (int j = 0; j < 4; j++) {
                    int row = r0 + j * 8;
                    if (row < M)
                        projOut[((size_t)v * M + row) * 2 + cw] = p[j];
                }
            }
        }
    }
}

// ---------------------------------------------------------------------------
// mma_score: score[blockIdx.y] += sum q[n]*tanh((relu(A_y)@Wk + bk)[m,n])
// ---------------------------------------------------------------------------
__global__ __launch_bounds__(256) void mma_score_kernel(
    const float* __restrict__ Aa, const float* __restrict__ Ab,
    const float* __restrict__ W, const float* __restrict__ bias,
    const float* __restrict__ q, int M, double* __restrict__ outScore)
{
    __shared__ uint32_t As[128 * 32];
    __shared__ uint32_t Bs[128 * 32];
    __shared__ float red[8];
    const float* A = (blockIdx.y == 0) ? Aa : Ab;
    const int tid = threadIdx.x;
    const int w   = tid >> 5, lane = tid & 31;
    const int gid = lane >> 2, tig = lane & 3;
    const int rw  = w >> 1, cw = w & 1;
    const int m0  = blockIdx.x * 128;

    float acc[2][8][4];
#pragma unroll
    for (int mt = 0; mt < 2; mt++)
#pragma unroll
        for (int i = 0; i < 8; i++)
#pragma unroll
            for (int j = 0; j < 4; j++) acc[mt][i][j] = 0.f;

    for (int kc = 0; kc < 128; kc += 32) {
        for (int i = tid; i < 1024; i += 256) {
            int r  = i >> 3;
            int c4 = (i & 7) << 2;
            float4 v = make_float4(0.f, 0.f, 0.f, 0.f);
            if (m0 + r < M)
                v = *(const float4*)(A + (size_t)(m0 + r) * 128 + kc + c4);
            float e[4] = {fmaxf(v.x, 0.f), fmaxf(v.y, 0.f),
                          fmaxf(v.z, 0.f), fmaxf(v.w, 0.f)};
            int rot = (r & 7) << 2;
#pragma unroll
            for (int j = 0; j < 4; j++)
                As[r * 32 + (((c4 + j) + rot) & 31)] = to_tf32(e[j]);
        }
        for (int i = tid; i < 4096; i += 256) {
            int n = i & 127, k = i >> 7;
            Bs[n * 32 + ((k + ((n & 7) << 2)) & 31)] =
                to_tf32(W[(size_t)(kc + k) * 128 + n]);
        }
        __syncthreads();

#pragma unroll
        for (int ks = 0; ks < 4; ks++) {
            int k0 = ks * 8;
            int rot = gid << 2;
            uint32_t a[2][4];
#pragma unroll
            for (int mt = 0; mt < 2; mt++) {
                int ra = rw * 32 + mt * 16 + gid;
                a[mt][0] = As[ra * 32 + ((k0 + tig + rot) & 31)];
                a[mt][1] = As[(ra + 8) * 32 + ((k0 + tig + rot) & 31)];
                a[mt][2] = As[ra * 32 + ((k0 + tig + 4 + rot) & 31)];
                a[mt][3] = As[(ra + 8) * 32 + ((k0 + tig + 4 + rot) & 31)];
            }
#pragma unroll
            for (int nt = 0; nt < 8; nt++) {
                int n = cw * 64 + nt * 8 + gid;
                uint32_t b0 = Bs[n * 32 + ((k0 + tig + rot) & 31)];
                uint32_t b1 = Bs[n * 32 + ((k0 + tig + 4 + rot) & 31)];
#pragma unroll
                for (int mt = 0; mt < 2; mt++)
                    mma8(acc[mt][nt], a[mt][0], a[mt][1], a[mt][2], a[mt][3], b0, b1);
            }
        }
        __syncthreads();
    }

    float local = 0.f;
    int r0 = m0 + rw * 32 + gid;
#pragma unroll
    for (int mt = 0; mt < 2; mt++) {
        int rA = r0 + mt * 16;
#pragma unroll
        for (int nt = 0; nt < 8; nt++) {
            int col = cw * 64 + nt * 8 + (tig << 1);
            float2 b2 = *(const float2*)(bias + col);
            float2 q2 = *(const float2*)(q + col);
            if (rA < M) {
                local += q2.x * tanhf(acc[mt][nt][0] + b2.x);
                local += q2.y * tanhf(acc[mt][nt][1] + b2.y);
            }
            if (rA + 8 < M) {
                local += q2.x * tanhf(acc[mt][nt][2] + b2.x);
                local += q2.y * tanhf(acc[mt][nt][3] + b2.y);
            }
        }
    }
#pragma unroll
    for (int o = 16; o > 0; o >>= 1)
        local += __shfl_xor_sync(0xffffffffu, local, o);
    if (lane == 0) red[w] = local;
    __syncthreads();
    if (tid == 0) {
        double s = 0.0;
        for (int i = 0; i < 8; i++) s += (double)red[i];
        atomicAdd(outScore + blockIdx.y, s);
    }
}

// ---------------------------------------------------------------------------
// CSR build: hist -> block sums -> scan of block sums -> local scan -> scatter
// ---------------------------------------------------------------------------
__global__ __launch_bounds__(256) void hist_kernel(
    const int* d0, const int* d1, const int* d2,
    int E0, int E1, int E2, int* __restrict__ cnt)
{
    int t = blockIdx.y;
    const int* d = t == 0 ? d0 : (t == 1 ? d1 : d2);
    int E = t == 0 ? E0 : (t == 1 ? E1 : E2);
    int e = blockIdx.x * blockDim.x + threadIdx.x;
    if (e < E) atomicAdd(cnt + t * MAXNO + d[e], 1);
}

__global__ __launch_bounds__(256) void blocksum_kernel(
    const int* __restrict__ cnt, int* __restrict__ bsum,
    int N0, int N1, int N2)
{
    int t = blockIdx.y, b = blockIdx.x;
    int N = t == 0 ? N0 : (t == 1 ? N1 : N2);
    int base = b * 1024;
    int ssum = 0;
    for (int i = threadIdx.x; i < 1024; i += 256) {
        int idx = base + i;
        if (idx < N) ssum += cnt[t * MAXNO + idx];
    }
    __shared__ int red[256];
    red[threadIdx.x] = ssum; __syncthreads();
    for (int o = 128; o > 0; o >>= 1) {
        if (threadIdx.x < o) red[threadIdx.x] += red[threadIdx.x + o];
        __syncthreads();
    }
    if (threadIdx.x == 0) bsum[t * NBMAX + b] = red[0];
}

__global__ __launch_bounds__(128) void scanb_kernel(
    int* __restrict__ bsum, int* __restrict__ rowptr,
    int N0, int N1, int N2, int E0, int E1, int E2)
{
    __shared__ int sm[NBMAX];
    int tid = threadIdx.x;
    for (int t = 0; t < 3; t++) {
        int v = bsum[t * NBMAX + tid];
        sm[tid] = v; __syncthreads();
        for (int o = 1; o < NBMAX; o <<= 1) {
            int y = (tid >= o) ? sm[tid - o] : 0;
            __syncthreads();
            sm[tid] += y;
            __syncthreads();
        }
        bsum[t * NBMAX + tid] = sm[tid] - v;   // exclusive
        __syncthreads();
    }
    if (tid == 0) {
        rowptr[0 * (MAXNO + 1) + N0] = E0;
        rowptr[1 * (MAXNO + 1) + N1] = E1;
        rowptr[2 * (MAXNO + 1) + N2] = E2;
    }
}

__global__ __launch_bounds__(256) void scanc_kernel(
    const int* __restrict__ cnt, const int* __restrict__ bsum,
    int* __restrict__ rowptr, int N0, int N1, int N2)
{
    int t = blockIdx.y, b = blockIdx.x;
    int N = t == 0 ? N0 : (t == 1 ? N1 : N2);
    int tid = threadIdx.x;
    int idx0 = b * 1024 + tid * 4;
    int c[4]; int ssum = 0;
#pragma unroll
    for (int j = 0; j < 4; j++) {
        int idx = idx0 + j;
        c[j] = (idx < N) ? cnt[t * MAXNO + idx] : 0;
        ssum += c[j];
    }
    __shared__ int sm[256];
    sm[tid] = ssum; __syncthreads();
    for (int o = 1; o < 256; o <<= 1) {
        int y = (tid >= o) ? sm[tid - o] : 0;
        __syncthreads();
        sm[tid] += y;
        __syncthreads();
    }
    int off = bsum[t * NBMAX + b] + (tid > 0 ? sm[tid - 1] : 0);
#pragma unroll
    for (int j = 0; j < 4; j++) {
        int idx = idx0 + j;
        if (idx < N) rowptr[t * (MAXNO + 1) + idx] = off;
        off += c[j];
    }
}

__global__ __launch_bounds__(256) void scatter_kernel(
    const int* s0, const int* d0, const int* s1, const int* d1,
    const int* s2, const int* d2, int E0, int E1, int E2,
    const int* __restrict__ rowptr, int* __restrict__ cur,
    int* __restrict__ csrc)
{
    int t = blockIdx.y;
    const int* s = t == 0 ? s0 : (t == 1 ? s1 : s2);
    const int* d = t == 0 ? d0 : (t == 1 ? d1 : d2);
    int E = t == 0 ? E0 : (t == 1 ? E1 : E2);
    int e = blockIdx.x * blockDim.x + threadIdx.x;
    if (e >= E) return;
    int dn = d[e];
    int pos = rowptr[t * (MAXNO + 1) + dn] + atomicAdd(cur + t * MAXNO + dn, 1);
    csrc[t * MAXE + pos] = s[e];
}

// ---------------------------------------------------------------------------
// Fused edge kernel: warp per dst node. Phase 1: softmax denominator.
// Phase 2: weighted gather of h rows, single coalesced store. No atomics.
// ---------------------------------------------------------------------------
__global__ __launch_bounds__(256) void edge_fused_kernel(CsrBatch cb)
{
    int t = blockIdx.y;
    int node = (blockIdx.x * 256 + threadIdx.x) >> 5;
    if (node >= cb.N[t]) return;
    int lane = threadIdx.x & 31;
    const int* rp = cb.rowptr[t];
    int beg = rp[node], end = rp[node + 1];
    const float2* ps = (const float2*)cb.psrc[t];
    float2 pdv = ((const float2*)cb.pdst[t])[node];

    // phase 1: denominators
    float s0 = 0.f, s1 = 0.f;
    for (int b = beg; b < end; b += 32) {
        int i = b + lane;
        float e0 = 0.f, e1 = 0.f;
        if (i < end) {
            int sn = cb.csrc[t][i];
            float2 p = ps[sn];
            float a0 = p.x + pdv.x; a0 = a0 > 0.f ? a0 : 0.2f * a0;
            float a1 = p.y + pdv.y; a1 = a1 > 0.f ? a1 : 0.2f * a1;
            e0 = expf(a0); e1 = expf(a1);
        }
#pragma unroll
        for (int o = 16; o > 0; o >>= 1) {
            e0 += __shfl_xor_sync(0xffffffffu, e0, o);
            e1 += __shfl_xor_sync(0xffffffffu, e1, o);
        }
        s0 += e0; s1 += e1;
    }
    int head = lane >> 4;
    float inv = (head ? 1.f / (s1 + 1e-16f) : 1.f / (s0 + 1e-16f));

    // phase 2: weighted gather
    float4 acc = make_float4(0.f, 0.f, 0.f, 0.f);
    for (int b = beg; b < end; b += 32) {
        int i = b + lane;
        int sn = 0; float e0 = 0.f, e1 = 0.f;
        if (i < end) {
            sn = cb.csrc[t][i];
            float2 p = ps[sn];
            float a0 = p.x + pdv.x; a0 = a0 > 0.f ? a0 : 0.2f * a0;
            float a1 = p.y + pdv.y; a1 = a1 > 0.f ? a1 : 0.2f * a1;
            e0 = expf(a0); e1 = expf(a1);
        }
        int cntj = end - b; if (cntj > 32) cntj = 32;
        for (int j = 0; j < cntj; j++) {
            int   sj  = __shfl_sync(0xffffffffu, sn, j);
            float e0j = __shfl_sync(0xffffffffu, e0, j);
            float e1j = __shfl_sync(0xffffffffu, e1, j);
            float wj  = (head ? e1j : e0j) * inv;
            float4 v = *(const float4*)(cb.hsrc[t] + (size_t)sj * 128 + lane * 4);
            acc.x += wj * v.x; acc.y += wj * v.y;
            acc.z += wj * v.z; acc.w += wj * v.w;
        }
    }
    *(float4*)(cb.outp[t] + (size_t)node * 128 + lane * 4) = acc;
}

// ---------------------------------------------------------------------------
// Semantic attention tail + MLP
// ---------------------------------------------------------------------------
__global__ void softmax2_kernel(const double* __restrict__ sc,
                                float* __restrict__ w, double invN)
{
    double s0 = sc[0] * invN, s1 = sc[1] * invN;
    double mx = s0 > s1 ? s0 : s1;
    double e0 = exp(s0 - mx), e1 = exp(s1 - mx);
    double sum = e0 + e1;
    w[0] = (float)(e0 / sum);
    w[1] = (float)(e1 / sum);
}

__global__ __launch_bounds__(256) void precompute_kernel(
    const float* __restrict__ Wl1, const float* __restrict__ bl1,
    const float* __restrict__ Wl2, const float* __restrict__ bl2,
    const float* __restrict__ Wl3, const float* __restrict__ bl3,
    float* __restrict__ W123, float* __restrict__ bfin)
{
    __shared__ float W23[256 * 8];
    __shared__ float t1s[128];
    int tid = threadIdx.x;
    for (int i = tid; i < 2048; i += 256) {
        int r = i >> 3, j = i & 7;
        float a = 0.f;
        for (int c = 0; c < 128; c++) a += Wl2[r * 128 + c] * Wl3[c * 8 + j];
        W23[i] = a;
    }
    for (int n = tid; n < 128; n += 256) {
        float a = bl2[n];
        for (int k = 0; k < 256; k++) a += bl1[k] * Wl2[k * 128 + n];
        t1s[n] = a;
    }
    __syncthreads();
    for (int i = tid; i < 1024; i += 256) {
        int k = i >> 3, j = i & 7;
        float a = 0.f;
        for (int r = 0; r < 256; r++) a += Wl1[k * 256 + r] * W23[r * 8 + j];
        W123[i] = a;
    }
    if (tid < 8) {
        float a = bl3[tid];
        for (int c = 0; c < 128; c++) a += t1s[c] * Wl3[c * 8 + tid];
        bfin[tid] = a;
    }
}

__global__ __launch_bounds__(256) void mlp_final_kernel(
    const float* __restrict__ o0, const float* __restrict__ o1,
    const float* __restrict__ wbuf, const float* __restrict__ W123,
    const float* __restrict__ bfin, float* __restrict__ out, int No)
{
    __shared__ float Ws[128 * 8];
    __shared__ float bs[8];
    for (int i = threadIdx.x; i < 128 * 8; i += blockDim.x) Ws[i] = W123[i];
    if (threadIdx.x < 8) bs[threadIdx.x] = bfin[threadIdx.x];
    __syncthreads();
    float w0 = wbuf[0], w1 = wbuf[1];
    int gid = blockIdx.x * blockDim.x + threadIdx.x;
    int row = gid >> 3, j = gid & 7;
    if (row >= No) return;
    const float* r0 = o0 + (size_t)row * 128;
    const float* r1 = o1 + (size_t)row * 128;
    float acc = 0.f;
#pragma unroll
    for (int k = 0; k < 128; k += 4) {
        float4 a = *(const float4*)(r0 + k);
        float4 b = *(const float4*)(r1 + k);
        float x0 = w0 * fmaxf(a.x, 0.f) + w1 * fmaxf(b.x, 0.f);
        float x1 = w0 * fmaxf(a.y, 0.f) + w1 * fmaxf(b.y, 0.f);
        float x2 = w0 * fmaxf(a.z, 0.f) + w1 * fmaxf(b.z, 0.f);
        float x3 = w0 * fmaxf(a.w, 0.f) + w1 * fmaxf(b.w, 0.f);
        acc += x0 * Ws[(k + 0) * 8 + j];
        acc += x1 * Ws[(k + 1) * 8 + j];
        acc += x2 * Ws[(k + 2) * 8 + j];
        acc += x3 * Ws[(k + 3) * 8 + j];
    }
    float x = acc + bs[j];
    out[(size_t)row * 8 + j] = 1.f / (1.f + expf(-x));
}

// ---------------------------------------------------------------------------
// Host orchestration
// ---------------------------------------------------------------------------
static inline int ceil_div(int a, int b) { return (a + b - 1) / b; }

extern "C" void kernel_launch(void* const* d_in, const int* in_sizes, int n_in,
                              void* d_out, int out_size)
{
    const float* xo  = (const float*)d_in[0];
    const float* xa  = (const float*)d_in[1];
    const int*   eoo = (const int*)d_in[2];
    const int*   eoa = (const int*)d_in[3];
    const int*   eao = (const int*)d_in[4];
    const int No  = in_sizes[0] / 128;
    const int Na  = in_sizes[1] / 128;
    const int Eoo = in_sizes[2] / 2;
    const int Eoa = in_sizes[3] / 2;
    const int Eao = in_sizes[4] / 2;

    float *ho, *ha, *o0, *o1, *oa, *pobj, *patt, *w, *W123, *bfin;
    int *cnt, *rowptr, *csrc, *bsum;
    double* score;
    cudaGetSymbolAddress((void**)&ho,     g_ho);
    cudaGetSymbolAddress((void**)&ha,     g_ha);
    cudaGetSymbolAddress((void**)&o0,     g_o0);
    cudaGetSymbolAddress((void**)&o1,     g_o1);
    cudaGetSymbolAddress((void**)&oa,     g_oa);
    cudaGetSymbolAddress((void**)&pobj,   g_pobj);
    cudaGetSymbolAddress((void**)&patt,   g_patt);
    cudaGetSymbolAddress((void**)&score,  g_score);
    cudaGetSymbolAddress((void**)&w,      g_w);
    cudaGetSymbolAddress((void**)&W123,   g_W123);
    cudaGetSymbolAddress((void**)&bfin,   g_bfin);
    cudaGetSymbolAddress((void**)&cnt,    g_cnt);
    cudaGetSymbolAddress((void**)&rowptr, g_rowptr);
    cudaGetSymbolAddress((void**)&csrc,   g_csrc);
    cudaGetSymbolAddress((void**)&bsum,   g_bsum);

    const int FEAT_SMEM = 65536;
    cudaFuncSetAttribute(mma_feat_kernel,
                         cudaFuncAttributeMaxDynamicSharedMemorySize, FEAT_SMEM);

    const int tilesNo = ceil_div(No, 128);
    const int tilesNa = ceil_div(Na, 128);
    const int maxE = (Eoo > Eao ? (Eoo > Eoa ? Eoo : Eoa) : (Eao > Eoa ? Eao : Eoa));

    // ---- CSR build (dst-lists are launch-constant; types: 0=oo,1=ao,2=oa) ----
    const int* dst0 = eoo + Eoo;   // over No
    const int* dst1 = eao + Eao;   // over No
    const int* dst2 = eoa + Eoa;   // over Na
    cudaMemsetAsync(cnt, 0, 3 * MAXNO * sizeof(int));
    hist_kernel<<<dim3(ceil_div(maxE, 256), 3), 256>>>(
        dst0, dst1, dst2, Eoo, Eao, Eoa, cnt);
    blocksum_kernel<<<dim3(NBMAX, 3), 256>>>(cnt, bsum, No, No, Na);
    scanb_kernel<<<1, NBMAX>>>(bsum, rowptr, No, No, Na, Eoo, Eao, Eoa);
    scanc_kernel<<<dim3(ceil_div(No, 1024), 3), 256>>>(cnt, bsum, rowptr, No, No, Na);
    cudaMemsetAsync(cnt, 0, 3 * MAXNO * sizeof(int));
    scatter_kernel<<<dim3(ceil_div(maxE, 256), 3), 256>>>(
        eoo, dst0, eao, dst1, eoa, dst2, Eoo, Eao, Eoa, rowptr, cnt, csrc);

    precompute_kernel<<<1, 256>>>(
        (const float*)d_in[23], (const float*)d_in[24], (const float*)d_in[25],
        (const float*)d_in[26], (const float*)d_in[27], (const float*)d_in[28],
        W123, bfin);

    for (int layer = 0; layer < 2; layer++) {
        const int base = 5 + 9 * layer;
        const float* Wo   = (const float*)d_in[base + 0];
        const float* bo   = (const float*)d_in[base + 1];
        const float* Wa   = (const float*)d_in[base + 2];
        const float* ba   = (const float*)d_in[base + 3];
        const float* asrc = (const float*)d_in[base + 4];
        const float* adst = (const float*)d_in[base + 5];
        const float* Wk   = (const float*)d_in[base + 6];
        const float* bk   = (const float*)d_in[base + 7];
        const float* q    = (const float*)d_in[base + 8];

        if (layer == 0) {
            mma_feat_kernel<<<tilesNo, 256, FEAT_SMEM>>>(
                xo, xo, w, Wo, bo, ho, No, 0,
                4, asrc + 0, asrc + 128, adst + 0, adst + 256, pobj);
            mma_feat_kernel<<<tilesNa, 256, FEAT_SMEM>>>(
                xa, xa, w, Wa, ba, ha, Na, 0,
                2, asrc + 256, adst + 128, asrc, asrc, patt);
        } else {
            mma_feat_kernel<<<tilesNo, 256, FEAT_SMEM>>>(
                o0, o1, w, Wo, bo, ho, No, 2,
                4, asrc + 0, asrc + 128, adst + 0, adst + 256, pobj);
            mma_feat_kernel<<<tilesNa, 256, FEAT_SMEM>>>(
                oa, oa, w, Wa, ba, ha, Na, 1,
                2, asrc + 256, adst + 128, asrc, asrc, patt);
        }

        const int ntypes = (layer == 0) ? 3 : 2;

        CsrBatch cb;
        // type 0: oo  (dst over No, out o0, h = ho)
        cb.csrc[0] = csrc;               cb.rowptr[0] = rowptr;
        cb.psrc[0] = pobj + 0;           cb.pdst[0] = pobj + (size_t)2 * No * 2;
        cb.hsrc[0] = ho;                 cb.outp[0] = o0;  cb.N[0] = No;
        // type 1: ao  (dst over No, out o1, h = ha)
        cb.csrc[1] = csrc + MAXE;        cb.rowptr[1] = rowptr + (MAXNO + 1);
        cb.psrc[1] = patt + 0;           cb.pdst[1] = pobj + (size_t)3 * No * 2;
        cb.hsrc[1] = ha;                 cb.outp[1] = o1;  cb.N[1] = No;
        // type 2: oa  (dst over Na, out oa, h = ho) — layer 0 only
        cb.csrc[2] = csrc + 2 * MAXE;    cb.rowptr[2] = rowptr + 2 * (MAXNO + 1);
        cb.psrc[2] = pobj + (size_t)1 * No * 2;
        cb.pdst[2] = patt + (size_t)1 * Na * 2;
        cb.hsrc[2] = ho;                 cb.outp[2] = oa;
        cb.N[2] = (layer == 0) ? Na : 0;

        edge_fused_kernel<<<dim3(ceil_div(No * 32, 256), ntypes), 256>>>(cb);

        cudaMemsetAsync(score, 0, 2 * sizeof(double));
        mma_score_kernel<<<dim3(tilesNo, 2), 256>>>(o0, o1, Wk, bk, q, No, score);
        softmax2_kernel<<<1, 1>>>(score, w, 1.0 / (double)No);
    }

    mlp_final_kernel<<<ceil_div(No * 8, 256), 256>>>(
        o0, o1, w, W123, bfin, (float*)d_out, No);
}

// round 11
// speedup vs baseline: 2.3744x; 1.1440x over previous
#include <cuda_runtime.h>
#include <math.h>
#include <stdint.h>

// ============================================================================
// HAN: 2-layer heterogeneous GAT + semantic attention + collapsed MLP head.
// R11: GEMMs switched tf32(m16n8k8, 3-pass) -> bf16x2 split (m16n8k16,
//      3 products hi*hi+hi*lo+lo*hi): half the mma instructions and half the
//      smem traffic at ~1e-5 accuracy. Score GEMM: single-pass bf16.
// Edge aggregation (CSR, warp-per-node) and the rest unchanged from R10.
// ============================================================================

#define MAXNO 100096
#define MAXNA 50048
#define MAXE  500224
#define NBMAX 128

__device__ float  g_ho[MAXNO * 128];
__device__ float  g_ha[MAXNA * 128];
__device__ float  g_o0[MAXNO * 128];
__device__ float  g_o1[MAXNO * 128];
__device__ float  g_oa[MAXNA * 128];
__device__ float  g_pobj[4 * MAXNO * 2];
__device__ float  g_patt[2 * MAXNA * 2];
__device__ double g_score[2];
__device__ float  g_w[2];
__device__ float  g_W123[128 * 8];
__device__ float  g_bfin[8];
// CSR scratch
__device__ int    g_cnt[3 * MAXNO];
__device__ int    g_rowptr[3 * (MAXNO + 1)];
__device__ int    g_csrc[3 * MAXE];
__device__ int    g_bsum[3 * NBMAX];

struct CsrBatch {
    const int*   csrc[3];
    const int*   rowptr[3];
    const float* psrc[3];
    const float* pdst[3];
    const float* hsrc[3];
    float*       outp[3];
    int          N[3];
};

// ---------------------------------------------------------------------------
// bf16 mma helpers
// ---------------------------------------------------------------------------
__device__ __forceinline__ void mma16(float* c,
                                      uint32_t a0, uint32_t a1, uint32_t a2, uint32_t a3,
                                      uint32_t b0, uint32_t b1)
{
    asm volatile(
        "mma.sync.aligned.m16n8k16.row.col.f32.bf16.bf16.f32 "
        "{%0,%1,%2,%3}, {%4,%5,%6,%7}, {%8,%9}, {%0,%1,%2,%3};"
        : "+f"(c[0]), "+f"(c[1]), "+f"(c[2]), "+f"(c[3])
        : "r"(a0), "r"(a1), "r"(a2), "r"(a3), "r"(b0), "r"(b1));
}

// round-to-nearest-even bf16 "hi" part kept as fp32
__device__ __forceinline__ float bf16_hi(float x) {
    uint32_t u = __float_as_uint(x);
    u = (u + 0x7FFFu + ((u >> 16) & 1u)) & 0xFFFF0000u;
    return __uint_as_float(u);
}
// pack top-16-bits of two fp32 (already bf16-exact) -> bf16x2 word (x in low)
__device__ __forceinline__ uint32_t pack_hi16(float x, float y) {
    return __byte_perm(__float_as_uint(x), __float_as_uint(y), 0x7632);
}
// rn-pack two arbitrary fp32 -> bf16x2 word (x in low)
__device__ __forceinline__ uint32_t pack_bf16x2(float x, float y) {
    uint32_t r;
    asm("cvt.rn.bf16x2.f32 %0, %1, %2;" : "=r"(r) : "f"(y), "f"(x));
    return r;
}

// ---------------------------------------------------------------------------
// mma_feat: C[M,128] = op(A)[M,128] @ W[128,128] + bias, bf16x2 split
// (hi*hi + hi*lo + lo*hi), node projections fused into epilogue.
// Warp tile 32x64 (rw=w>>1, cw=w&1). K chunked by 32 (16 kpairs).
// smem: uint2 {hiWord, loWord} per (row, kpair-slot), slot=(kp+2*(r&7))&15.
// mode: 0 = plain A, 1 = relu(A), 2 = A := w0*relu(A)+w1*relu(A2)
// ---------------------------------------------------------------------------
__global__ __launch_bounds__(256) void mma_feat_kernel(
    const float* __restrict__ A, const float* __restrict__ A2,
    const float* __restrict__ wbuf, const float* __restrict__ W,
    const float* __restrict__ bias, float* __restrict__ C, int M, int mode,
    int nv, const float* __restrict__ v0, const float* __restrict__ v1,
    const float* __restrict__ v2, const float* __restrict__ v3,
    float* __restrict__ projOut)
{
    extern __shared__ uint2 usm[];         // [0,2048) A, [2048,4096) B
    uint2* Asm = usm;
    uint2* Bsm = usm + 2048;
    const int tid  = threadIdx.x;
    const int w    = tid >> 5, lane = tid & 31;
    const int gid  = lane >> 2, tig = lane & 3;
    const int rw   = w >> 1, cw = w & 1;
    const int m0   = blockIdx.x * 128;

    float cw0 = 0.f, cw1 = 0.f;
    if (mode == 2) { cw0 = wbuf[0]; cw1 = wbuf[1]; }

    float acc[2][8][4];
#pragma unroll
    for (int mt = 0; mt < 2; mt++)
#pragma unroll
        for (int i = 0; i < 8; i++)
#pragma unroll
            for (int j = 0; j < 4; j++) acc[mt][i][j] = 0.f;

    for (int kc = 0; kc < 128; kc += 32) {
        // ---- A chunk: 128 rows x 32 k (16 kpairs), split hi/lo bf16 ----
        for (int i = tid; i < 1024; i += 256) {
            int r   = i >> 3;
            int c4  = (i & 7) << 2;        // element offset (2 kpairs)
            int kp0 = c4 >> 1;
            float4 v = make_float4(0.f, 0.f, 0.f, 0.f);
            if (m0 + r < M) {
                v = *(const float4*)(A + (size_t)(m0 + r) * 128 + kc + c4);
                if (mode == 1) {
                    v.x = fmaxf(v.x, 0.f); v.y = fmaxf(v.y, 0.f);
                    v.z = fmaxf(v.z, 0.f); v.w = fmaxf(v.w, 0.f);
                } else if (mode == 2) {
                    float4 u = *(const float4*)(A2 + (size_t)(m0 + r) * 128 + kc + c4);
                    v.x = cw0 * fmaxf(v.x, 0.f) + cw1 * fmaxf(u.x, 0.f);
                    v.y = cw0 * fmaxf(v.y, 0.f) + cw1 * fmaxf(u.y, 0.f);
                    v.z = cw0 * fmaxf(v.z, 0.f) + cw1 * fmaxf(u.z, 0.f);
                    v.w = cw0 * fmaxf(v.w, 0.f) + cw1 * fmaxf(u.w, 0.f);
                }
            }
            float hx = bf16_hi(v.x), hy = bf16_hi(v.y);
            float hz = bf16_hi(v.z), hw = bf16_hi(v.w);
            uint2 w0, w1;
            w0.x = pack_hi16(hx, hy);
            w0.y = pack_bf16x2(v.x - hx, v.y - hy);
            w1.x = pack_hi16(hz, hw);
            w1.y = pack_bf16x2(v.z - hz, v.w - hw);
            int rot = (r & 7) << 1;
            Asm[r * 16 + ((kp0 + rot) & 15)]     = w0;
            Asm[r * 16 + ((kp0 + 1 + rot) & 15)] = w1;
        }
        // ---- B chunk: Bt[n][kpair] from W[kc+k][n], split hi/lo ----
        for (int i = tid; i < 2048; i += 256) {
            int n = i & 127, kp = i >> 7;
            float x0 = W[(size_t)(kc + 2 * kp) * 128 + n];
            float x1 = W[(size_t)(kc + 2 * kp + 1) * 128 + n];
            float h0 = bf16_hi(x0), h1 = bf16_hi(x1);
            uint2 wv;
            wv.x = pack_hi16(h0, h1);
            wv.y = pack_bf16x2(x0 - h0, x1 - h1);
            Bsm[n * 16 + ((kp + ((n & 7) << 1)) & 15)] = wv;
        }
        __syncthreads();

#pragma unroll
        for (int ks = 0; ks < 2; ks++) {     // two 16-K steps per chunk
            int base = ks * 8;
            int rot = gid << 1;
            uint32_t ah[2][4], al[2][4];
#pragma unroll
            for (int mt = 0; mt < 2; mt++) {
                int ra = rw * 32 + mt * 16 + gid;
                uint2 u0 = Asm[ra * 16 + ((base + tig + rot) & 15)];
                uint2 u1 = Asm[(ra + 8) * 16 + ((base + tig + rot) & 15)];
                uint2 u2 = Asm[ra * 16 + ((base + 4 + tig + rot) & 15)];
                uint2 u3 = Asm[(ra + 8) * 16 + ((base + 4 + tig + rot) & 15)];
                ah[mt][0] = u0.x; al[mt][0] = u0.y;
                ah[mt][1] = u1.x; al[mt][1] = u1.y;
                ah[mt][2] = u2.x; al[mt][2] = u2.y;
                ah[mt][3] = u3.x; al[mt][3] = u3.y;
            }
#pragma unroll
            for (int nt = 0; nt < 8; nt++) {
                int n = cw * 64 + nt * 8 + gid;
                uint2 b0 = Bsm[n * 16 + ((base + tig + rot) & 15)];
                uint2 b1 = Bsm[n * 16 + ((base + 4 + tig + rot) & 15)];
#pragma unroll
                for (int mt = 0; mt < 2; mt++) {
                    mma16(acc[mt][nt], ah[mt][0], ah[mt][1], ah[mt][2], ah[mt][3], b0.x, b1.x);
                    mma16(acc[mt][nt], ah[mt][0], ah[mt][1], ah[mt][2], ah[mt][3], b0.y, b1.y);
                    mma16(acc[mt][nt], al[mt][0], al[mt][1], al[mt][2], al[mt][3], b0.x, b1.x);
                }
            }
        }
        __syncthreads();
    }

    // ---- epilogue: bias + store ----
    int r0 = m0 + rw * 32 + gid;
#pragma unroll
    for (int mt = 0; mt < 2; mt++) {
        int rA = r0 + mt * 16;
#pragma unroll
        for (int nt = 0; nt < 8; nt++) {
            int col = cw * 64 + nt * 8 + (tig << 1);
            float2 b2 = *(const float2*)(bias + col);
            acc[mt][nt][0] += b2.x; acc[mt][nt][1] += b2.y;
            acc[mt][nt][2] += b2.x; acc[mt][nt][3] += b2.y;
            if (rA < M)
                *(float2*)(C + (size_t)rA * 128 + col) =
                    make_float2(acc[mt][nt][0], acc[mt][nt][1]);
            if (rA + 8 < M)
                *(float2*)(C + (size_t)(rA + 8) * 128 + col) =
                    make_float2(acc[mt][nt][2], acc[mt][nt][3]);
        }
    }

    // ---- fused projections: this warp's cols == head cw entirely ----
    {
        const float* vs[4] = {v0, v1, v2, v3};
#pragma unroll
        for (int v = 0; v < 4; v++) {
            if (v >= nv) break;
            const float* vv = vs[v];
            float p[4] = {0.f, 0.f, 0.f, 0.f};
#pragma unroll
            for (int mt = 0; mt < 2; mt++)
#pragma unroll
                for (int nt = 0; nt < 8; nt++) {
                    int col = cw * 64 + nt * 8 + (tig << 1);
                    float2 vvc = *(const float2*)(vv + col);
                    p[2 * mt + 0] += acc[mt][nt][0] * vvc.x + acc[mt][nt][1] * vvc.y;
                    p[2 * mt + 1] += acc[mt][nt][2] * vvc.x + acc[mt][nt][3] * vvc.y;
                }
#pragma unroll
            for (int j = 0; j < 4; j++) {
                p[j] += __shfl_xor_sync(0xffffffffu, p[j], 1);
                p[j] += __shfl_xor_sync(0xffffffffu, p[j], 2);
            }
            if (tig == 0) {
#pragma unroll
                for (int j = 0; j < 4; j++) {
                    int row = r0 + j * 8;
                    if (row < M)
                        projOut[((size_t)v * M + row) * 2 + cw] = p[j];
                }
            }
        }
    }
}

// ---------------------------------------------------------------------------
// mma_score: score[blockIdx.y] += sum q[n]*tanh((relu(A_y)@Wk + bk)[m,n])
// single-pass bf16, warp tile 32x64.
// ---------------------------------------------------------------------------
__global__ __launch_bounds__(256) void mma_score_kernel(
    const float* __restrict__ Aa, const float* __restrict__ Ab,
    const float* __restrict__ W, const float* __restrict__ bias,
    const float* __restrict__ q, int M, double* __restrict__ outScore)
{
    __shared__ uint32_t As[128 * 16];
    __shared__ uint32_t Bs[128 * 16];
    __shared__ float red[8];
    const float* A = (blockIdx.y == 0) ? Aa : Ab;
    const int tid = threadIdx.x;
    const int w   = tid >> 5, lane = tid & 31;
    const int gid = lane >> 2, tig = lane & 3;
    const int rw  = w >> 1, cw = w & 1;
    const int m0  = blockIdx.x * 128;

    float acc[2][8][4];
#pragma unroll
    for (int mt = 0; mt < 2; mt++)
#pragma unroll
        for (int i = 0; i < 8; i++)
#pragma unroll
            for (int j = 0; j < 4; j++) acc[mt][i][j] = 0.f;

    for (int kc = 0; kc < 128; kc += 32) {
        for (int i = tid; i < 1024; i += 256) {
            int r   = i >> 3;
            int c4  = (i & 7) << 2;
            int kp0 = c4 >> 1;
            float4 v = make_float4(0.f, 0.f, 0.f, 0.f);
            if (m0 + r < M)
                v = *(const float4*)(A + (size_t)(m0 + r) * 128 + kc + c4);
            int rot = (r & 7) << 1;
            As[r * 16 + ((kp0 + rot) & 15)] =
                pack_bf16x2(fmaxf(v.x, 0.f), fmaxf(v.y, 0.f));
            As[r * 16 + ((kp0 + 1 + rot) & 15)] =
                pack_bf16x2(fmaxf(v.z, 0.f), fmaxf(v.w, 0.f));
        }
        for (int i = tid; i < 2048; i += 256) {
            int n = i & 127, kp = i >> 7;
            float x0 = W[(size_t)(kc + 2 * kp) * 128 + n];
            float x1 = W[(size_t)(kc + 2 * kp + 1) * 128 + n];
            Bs[n * 16 + ((kp + ((n & 7) << 1)) & 15)] = pack_bf16x2(x0, x1);
        }
        __syncthreads();

#pragma unroll
        for (int ks = 0; ks < 2; ks++) {
            int base = ks * 8;
            int rot = gid << 1;
            uint32_t a[2][4];
#pragma unroll
            for (int mt = 0; mt < 2; mt++) {
                int ra = rw * 32 + mt * 16 + gid;
                a[mt][0] = As[ra * 16 + ((base + tig + rot) & 15)];
                a[mt][1] = As[(ra + 8) * 16 + ((base + tig + rot) & 15)];
                a[mt][2] = As[ra * 16 + ((base + 4 + tig + rot) & 15)];
                a[mt][3] = As[(ra + 8) * 16 + ((base + 4 + tig + rot) & 15)];
            }
#pragma unroll
            for (int nt = 0; nt < 8; nt++) {
                int n = cw * 64 + nt * 8 + gid;
                uint32_t b0 = Bs[n * 16 + ((base + tig + rot) & 15)];
                uint32_t b1 = Bs[n * 16 + ((base + 4 + tig + rot) & 15)];
#pragma unroll
                for (int mt = 0; mt < 2; mt++)
                    mma16(acc[mt][nt], a[mt][0], a[mt][1], a[mt][2], a[mt][3], b0, b1);
            }
        }
        __syncthreads();
    }

    float local = 0.f;
    int r0 = m0 + rw * 32 + gid;
#pragma unroll
    for (int mt = 0; mt < 2; mt++) {
        int rA = r0 + mt * 16;
#pragma unroll
        for (int nt = 0; nt < 8; nt++) {
            int col = cw * 64 + nt * 8 + (tig << 1);
            float2 b2 = *(const float2*)(bias + col);
            float2 q2 = *(const float2*)(q + col);
            if (rA < M) {
                local += q2.x * tanhf(acc[mt][nt][0] + b2.x);
                local += q2.y * tanhf(acc[mt][nt][1] + b2.y);
            }
            if (rA + 8 < M) {
                local += q2.x * tanhf(acc[mt][nt][2] + b2.x);
                local += q2.y * tanhf(acc[mt][nt][3] + b2.y);
            }
        }
    }
#pragma unroll
    for (int o = 16; o > 0; o >>= 1)
        local += __shfl_xor_sync(0xffffffffu, local, o);
    if (lane == 0) red[w] = local;
    __syncthreads();
    if (tid == 0) {
        double s = 0.0;
        for (int i = 0; i < 8; i++) s += (double)red[i];
        atomicAdd(outScore + blockIdx.y, s);
    }
}

// ---------------------------------------------------------------------------
// CSR build: hist -> block sums -> scan of block sums -> local scan -> scatter
// ---------------------------------------------------------------------------
__global__ __launch_bounds__(256) void hist_kernel(
    const int* d0, const int* d1, const int* d2,
    int E0, int E1, int E2, int* __restrict__ cnt)
{
    int t = blockIdx.y;
    const int* d = t == 0 ? d0 : (t == 1 ? d1 : d2);
    int E = t == 0 ? E0 : (t == 1 ? E1 : E2);
    int e = blockIdx.x * blockDim.x + threadIdx.x;
    if (e < E) atomicAdd(cnt + t * MAXNO + d[e], 1);
}

__global__ __launch_bounds__(256) void blocksum_kernel(
    const int* __restrict__ cnt, int* __restrict__ bsum,
    int N0, int N1, int N2)
{
    int t = blockIdx.y, b = blockIdx.x;
    int N = t == 0 ? N0 : (t == 1 ? N1 : N2);
    int base = b * 1024;
    int ssum = 0;
    for (int i = threadIdx.x; i < 1024; i += 256) {
        int idx = base + i;
        if (idx < N) ssum += cnt[t * MAXNO + idx];
    }
    __shared__ int red[256];
    red[threadIdx.x] = ssum; __syncthreads();
    for (int o = 128; o > 0; o >>= 1) {
        if (threadIdx.x < o) red[threadIdx.x] += red[threadIdx.x + o];
        __syncthreads();
    }
    if (threadIdx.x == 0) bsum[t * NBMAX + b] = red[0];
}

__global__ __launch_bounds__(128) void scanb_kernel(
    int* __restrict__ bsum, int* __restrict__ rowptr,
    int N0, int N1, int N2, int E0, int E1, int E2)
{
    __shared__ int sm[NBMAX];
    int tid = threadIdx.x;
    for (int t = 0; t < 3; t++) {
        int v = bsum[t * NBMAX + tid];
        sm[tid] = v; __syncthreads();
        for (int o = 1; o < NBMAX; o <<= 1) {
            int y = (tid >= o) ? sm[tid - o] : 0;
            __syncthreads();
            sm[tid] += y;
            __syncthreads();
        }
        bsum[t * NBMAX + tid] = sm[tid] - v;
        __syncthreads();
    }
    if (tid == 0) {
        rowptr[0 * (MAXNO + 1) + N0] = E0;
        rowptr[1 * (MAXNO + 1) + N1] = E1;
        rowptr[2 * (MAXNO + 1) + N2] = E2;
    }
}

__global__ __launch_bounds__(256) void scanc_kernel(
    const int* __restrict__ cnt, const int* __restrict__ bsum,
    int* __restrict__ rowptr, int N0, int N1, int N2)
{
    int t = blockIdx.y, b = blockIdx.x;
    int N = t == 0 ? N0 : (t == 1 ? N1 : N2);
    int tid = threadIdx.x;
    int idx0 = b * 1024 + tid * 4;
    int c[4]; int ssum = 0;
#pragma unroll
    for (int j = 0; j < 4; j++) {
        int idx = idx0 + j;
        c[j] = (idx < N) ? cnt[t * MAXNO + idx] : 0;
        ssum += c[j];
    }
    __shared__ int sm[256];
    sm[tid] = ssum; __syncthreads();
    for (int o = 1; o < 256; o <<= 1) {
        int y = (tid >= o) ? sm[tid - o] : 0;
        __syncthreads();
        sm[tid] += y;
        __syncthreads();
    }
    int off = bsum[t * NBMAX + b] + (tid > 0 ? sm[tid - 1] : 0);
#pragma unroll
    for (int j = 0; j < 4; j++) {
        int idx = idx0 + j;
        if (idx < N) rowptr[t * (MAXNO + 1) + idx] = off;
        off += c[j];
    }
}

__global__ __launch_bounds__(256) void scatter_kernel(
    const int* s0, const int* d0, const int* s1, const int* d1,
    const int* s2, const int* d2, int E0, int E1, int E2,
    const int* __restrict__ rowptr, int* __restrict__ cur,
    int* __restrict__ csrc)
{
    int t = blockIdx.y;
    const int* s = t == 0 ? s0 : (t == 1 ? s1 : s2);
    const int* d = t == 0 ? d0 : (t == 1 ? d1 : d2);
    int E = t == 0 ? E0 : (t == 1 ? E1 : E2);
    int e = blockIdx.x * blockDim.x + threadIdx.x;
    if (e >= E) return;
    int dn = d[e];
    int pos = rowptr[t * (MAXNO + 1) + dn] + atomicAdd(cur + t * MAXNO + dn, 1);
    csrc[t * MAXE + pos] = s[e];
}

// ---------------------------------------------------------------------------
// Fused edge kernel: warp per dst node (denominator + gather + single store)
// ---------------------------------------------------------------------------
__global__ __launch_bounds__(256) void edge_fused_kernel(CsrBatch cb)
{
    int t = blockIdx.y;
    int node = (blockIdx.x * 256 + threadIdx.x) >> 5;
    if (node >= cb.N[t]) return;
    int lane = threadIdx.x & 31;
    const int* rp = cb.rowptr[t];
    int beg = rp[node], end = rp[node + 1];
    const float2* ps = (const float2*)cb.psrc[t];
    float2 pdv = ((const float2*)cb.pdst[t])[node];

    float s0 = 0.f, s1 = 0.f;
    for (int b = beg; b < end; b += 32) {
        int i = b + lane;
        float e0 = 0.f, e1 = 0.f;
        if (i < end) {
            int sn = cb.csrc[t][i];
            float2 p = ps[sn];
            float a0 = p.x + pdv.x; a0 = a0 > 0.f ? a0 : 0.2f * a0;
            float a1 = p.y + pdv.y; a1 = a1 > 0.f ? a1 : 0.2f * a1;
            e0 = expf(a0); e1 = expf(a1);
        }
#pragma unroll
        for (int o = 16; o > 0; o >>= 1) {
            e0 += __shfl_xor_sync(0xffffffffu, e0, o);
            e1 += __shfl_xor_sync(0xffffffffu, e1, o);
        }
        s0 += e0; s1 += e1;
    }
    int head = lane >> 4;
    float inv = (head ? 1.f / (s1 + 1e-16f) : 1.f / (s0 + 1e-16f));

    float4 acc = make_float4(0.f, 0.f, 0.f, 0.f);
    for (int b = beg; b < end; b += 32) {
        int i = b + lane;
        int sn = 0; float e0 = 0.f, e1 = 0.f;
        if (i < end) {
            sn = cb.csrc[t][i];
            float2 p = ps[sn];
            float a0 = p.x + pdv.x; a0 = a0 > 0.f ? a0 : 0.2f * a0;
            float a1 = p.y + pdv.y; a1 = a1 > 0.f ? a1 : 0.2f * a1;
            e0 = expf(a0); e1 = expf(a1);
        }
        int cntj = end - b; if (cntj > 32) cntj = 32;
        for (int j = 0; j < cntj; j++) {
            int   sj  = __shfl_sync(0xffffffffu, sn, j);
            float e0j = __shfl_sync(0xffffffffu, e0, j);
            float e1j = __shfl_sync(0xffffffffu, e1, j);
            float wj  = (head ? e1j : e0j) * inv;
            float4 v = *(const float4*)(cb.hsrc[t] + (size_t)sj * 128 + lane * 4);
            acc.x += wj * v.x; acc.y += wj * v.y;
            acc.z += wj * v.z; acc.w += wj * v.w;
        }
    }
    *(float4*)(cb.outp[t] + (size_t)node * 128 + lane * 4) = acc;
}

// ---------------------------------------------------------------------------
// Semantic attention tail + MLP
// ---------------------------------------------------------------------------
__global__ void softmax2_kernel(const double* __restrict__ sc,
                                float* __restrict__ w, double invN)
{
    double s0 = sc[0] * invN, s1 = sc[1] * invN;
    double mx = s0 > s1 ? s0 : s1;
    double e0 = exp(s0 - mx), e1 = exp(s1 - mx);
    double sum = e0 + e1;
    w[0] = (float)(e0 / sum);
    w[1] = (float)(e1 / sum);
}

__global__ __launch_bounds__(256) void precompute_kernel(
    const float* __restrict__ Wl1, const float* __restrict__ bl1,
    const float* __restrict__ Wl2, const float* __restrict__ bl2,
    const float* __restrict__ Wl3, const float* __restrict__ bl3,
    float* __restrict__ W123, float* __restrict__ bfin)
{
    __shared__ float W23[256 * 8];
    __shared__ float t1s[128];
    int tid = threadIdx.x;
    for (int i = tid; i < 2048; i += 256) {
        int r = i >> 3, j = i & 7;
        float a = 0.f;
        for (int c = 0; c < 128; c++) a += Wl2[r * 128 + c] * Wl3[c * 8 + j];
        W23[i] = a;
    }
    for (int n = tid; n < 128; n += 256) {
        float a = bl2[n];
        for (int k = 0; k < 256; k++) a += bl1[k] * Wl2[k * 128 + n];
        t1s[n] = a;
    }
    __syncthreads();
    for (int i = tid; i < 1024; i += 256) {
        int k = i >> 3, j = i & 7;
        float a = 0.f;
        for (int r = 0; r < 256; r++) a += Wl1[k * 256 + r] * W23[r * 8 + j];
        W123[i] = a;
    }
    if (tid < 8) {
        float a = bl3[tid];
        for (int c = 0; c < 128; c++) a += t1s[c] * Wl3[c * 8 + tid];
        bfin[tid] = a;
    }
}

__global__ __launch_bounds__(256) void mlp_final_kernel(
    const float* __restrict__ o0, const float* __restrict__ o1,
    const float* __restrict__ wbuf, const float* __restrict__ W123,
    const float* __restrict__ bfin, float* __restrict__ out, int No)
{
    __shared__ float Ws[128 * 8];
    __shared__ float bs[8];
    for (int i = threadIdx.x; i < 128 * 8; i += blockDim.x) Ws[i] = W123[i];
    if (threadIdx.x < 8) bs[threadIdx.x] = bfin[threadIdx.x];
    __syncthreads();
    float w0 = wbuf[0], w1 = wbuf[1];
    int gid = blockIdx.x * blockDim.x + threadIdx.x;
    int row = gid >> 3, j = gid & 7;
    if (row >= No) return;
    const float* r0 = o0 + (size_t)row * 128;
    const float* r1 = o1 + (size_t)row * 128;
    float acc = 0.f;
#pragma unroll
    for (int k = 0; k < 128; k += 4) {
        float4 a = *(const float4*)(r0 + k);
        float4 b = *(const float4*)(r1 + k);
        float x0 = w0 * fmaxf(a.x, 0.f) + w1 * fmaxf(b.x, 0.f);
        float x1 = w0 * fmaxf(a.y, 0.f) + w1 * fmaxf(b.y, 0.f);
        float x2 = w0 * fmaxf(a.z, 0.f) + w1 * fmaxf(b.z, 0.f);
        float x3 = w0 * fmaxf(a.w, 0.f) + w1 * fmaxf(b.w, 0.f);
        acc += x0 * Ws[(k + 0) * 8 + j];
        acc += x1 * Ws[(k + 1) * 8 + j];
        acc += x2 * Ws[(k + 2) * 8 + j];
        acc += x3 * Ws[(k + 3) * 8 + j];
    }
    float x = acc + bs[j];
    out[(size_t)row * 8 + j] = 1.f / (1.f + expf(-x));
}

// ---------------------------------------------------------------------------
// Host orchestration
// ---------------------------------------------------------------------------
static inline int ceil_div(int a, int b) { return (a + b - 1) / b; }

extern "C" void kernel_launch(void* const* d_in, const int* in_sizes, int n_in,
                              void* d_out, int out_size)
{
    const float* xo  = (const float*)d_in[0];
    const float* xa  = (const float*)d_in[1];
    const int*   eoo = (const int*)d_in[2];
    const int*   eoa = (const int*)d_in[3];
    const int*   eao = (const int*)d_in[4];
    const int No  = in_sizes[0] / 128;
    const int Na  = in_sizes[1] / 128;
    const int Eoo = in_sizes[2] / 2;
    const int Eoa = in_sizes[3] / 2;
    const int Eao = in_sizes[4] / 2;

    float *ho, *ha, *o0, *o1, *oa, *pobj, *patt, *w, *W123, *bfin;
    int *cnt, *rowptr, *csrc, *bsum;
    double* score;
    cudaGetSymbolAddress((void**)&ho,     g_ho);
    cudaGetSymbolAddress((void**)&ha,     g_ha);
    cudaGetSymbolAddress((void**)&o0,     g_o0);
    cudaGetSymbolAddress((void**)&o1,     g_o1);
    cudaGetSymbolAddress((void**)&oa,     g_oa);
    cudaGetSymbolAddress((void**)&pobj,   g_pobj);
    cudaGetSymbolAddress((void**)&patt,   g_patt);
    cudaGetSymbolAddress((void**)&score,  g_score);
    cudaGetSymbolAddress((void**)&w,      g_w);
    cudaGetSymbolAddress((void**)&W123,   g_W123);
    cudaGetSymbolAddress((void**)&bfin,   g_bfin);
    cudaGetSymbolAddress((void**)&cnt,    g_cnt);
    cudaGetSymbolAddress((void**)&rowptr, g_rowptr);
    cudaGetSymbolAddress((void**)&csrc,   g_csrc);
    cudaGetSymbolAddress((void**)&bsum,   g_bsum);

    const int FEAT_SMEM = 32768;
    cudaFuncSetAttribute(mma_feat_kernel,
                         cudaFuncAttributeMaxDynamicSharedMemorySize, FEAT_SMEM);

    const int tilesNo = ceil_div(No, 128);
    const int tilesNa = ceil_div(Na, 128);
    const int maxE = (Eoo > Eao ? (Eoo > Eoa ? Eoo : Eoa) : (Eao > Eoa ? Eao : Eoa));

    // ---- CSR build (types: 0=oo, 1=ao, 2=oa) ----
    const int* dst0 = eoo + Eoo;
    const int* dst1 = eao + Eao;
    const int* dst2 = eoa + Eoa;
    cudaMemsetAsync(cnt, 0, 3 * MAXNO * sizeof(int));
    hist_kernel<<<dim3(ceil_div(maxE, 256), 3), 256>>>(
        dst0, dst1, dst2, Eoo, Eao, Eoa, cnt);
    blocksum_kernel<<<dim3(NBMAX, 3), 256>>>(cnt, bsum, No, No, Na);
    scanb_kernel<<<1, NBMAX>>>(bsum, rowptr, No, No, Na, Eoo, Eao, Eoa);
    scanc_kernel<<<dim3(ceil_div(No, 1024), 3), 256>>>(cnt, bsum, rowptr, No, No, Na);
    cudaMemsetAsync(cnt, 0, 3 * MAXNO * sizeof(int));
    scatter_kernel<<<dim3(ceil_div(maxE, 256), 3), 256>>>(
        eoo, dst0, eao, dst1, eoa, dst2, Eoo, Eao, Eoa, rowptr, cnt, csrc);

    precompute_kernel<<<1, 256>>>(
        (const float*)d_in[23], (const float*)d_in[24], (const float*)d_in[25],
        (const float*)d_in[26], (const float*)d_in[27], (const float*)d_in[28],
        W123, bfin);

    for (int layer = 0; layer < 2; layer++) {
        const int base = 5 + 9 * layer;
        const float* Wo   = (const float*)d_in[base + 0];
        const float* bo   = (const float*)d_in[base + 1];
        const float* Wa   = (const float*)d_in[base + 2];
        const float* ba   = (const float*)d_in[base + 3];
        const float* asrc = (const float*)d_in[base + 4];
        const float* adst = (const float*)d_in[base + 5];
        const float* Wk   = (const float*)d_in[base + 6];
        const float* bk   = (const float*)d_in[base + 7];
        const float* q    = (const float*)d_in[base + 8];

        if (layer == 0) {
            mma_feat_kernel<<<tilesNo, 256, FEAT_SMEM>>>(
                xo, xo, w, Wo, bo, ho, No, 0,
                4, asrc + 0, asrc + 128, adst + 0, adst + 256, pobj);
            mma_feat_kernel<<<tilesNa, 256, FEAT_SMEM>>>(
                xa, xa, w, Wa, ba, ha, Na, 0,
                2, asrc + 256, adst + 128, asrc, asrc, patt);
        } else {
            mma_feat_kernel<<<tilesNo, 256, FEAT_SMEM>>>(
                o0, o1, w, Wo, bo, ho, No, 2,
                4, asrc + 0, asrc + 128, adst + 0, adst + 256, pobj);
            mma_feat_kernel<<<tilesNa, 256, FEAT_SMEM>>>(
                oa, oa, w, Wa, ba, ha, Na, 1,
                2, asrc + 256, adst + 128, asrc, asrc, patt);
        }

        const int ntypes = (layer == 0) ? 3 : 2;

        CsrBatch cb;
        cb.csrc[0] = csrc;               cb.rowptr[0] = rowptr;
        cb.psrc[0] = pobj + 0;           cb.pdst[0] = pobj + (size_t)2 * No * 2;
        cb.hsrc[0] = ho;                 cb.outp[0] = o0;  cb.N[0] = No;
        cb.csrc[1] = csrc + MAXE;        cb.rowptr[1] = rowptr + (MAXNO + 1);
        cb.psrc[1] = patt + 0;           cb.pdst[1] = pobj + (size_t)3 * No * 2;
        cb.hsrc[1] = ha;                 cb.outp[1] = o1;  cb.N[1] = No;
        cb.csrc[2] = csrc + 2 * MAXE;    cb.rowptr[2] = rowptr + 2 * (MAXNO + 1);
        cb.psrc[2] = pobj + (size_t)1 * No * 2;
        cb.pdst[2] = patt + (size_t)1 * Na * 2;
        cb.hsrc[2] = ho;                 cb.outp[2] = oa;
        cb.N[2] = (layer == 0) ? Na : 0;

        edge_fused_kernel<<<dim3(ceil_div(No * 32, 256), ntypes), 256>>>(cb);

        cudaMemsetAsync(score, 0, 2 * sizeof(double));
        mma_score_kernel<<<dim3(tilesNo, 2), 256>>>(o0, o1, Wk, bk, q, No, score);
        softmax2_kernel<<<1, 1>>>(score, w, 1.0 / (double)No);
    }

    mlp_final_kernel<<<ceil_div(No * 8, 256), 256>>>(
        o0, o1, w, W123, bfin, (float*)d_out, No);
}

// round 15
// speedup vs baseline: 2.5006x; 1.0531x over previous
#include <cuda_runtime.h>
#include <math.h>
#include <stdint.h>

// ============================================================================
// HAN: 2-layer heterogeneous GAT + semantic attention + collapsed MLP head.
// R12: - edge phase-2 register cache (deg<=32 common case: no recompute)
//      - scanc zeros cnt in-place (one less memset launch)
//      - both feature GEMMs of a layer merged into one launch (grid.y)
// Else identical to R11 (bf16x2-split mma GEMMs, CSR warp-per-node edges).
// ============================================================================

#define MAXNO 100096
#define MAXNA 50048
#define MAXE  500224
#define NBMAX 128

__device__ float  g_ho[MAXNO * 128];
__device__ float  g_ha[MAXNA * 128];
__device__ float  g_o0[MAXNO * 128];
__device__ float  g_o1[MAXNO * 128];
__device__ float  g_oa[MAXNA * 128];
__device__ float  g_pobj[4 * MAXNO * 2];
__device__ float  g_patt[2 * MAXNA * 2];
__device__ double g_score[2];
__device__ float  g_w[2];
__device__ float  g_W123[128 * 8];
__device__ float  g_bfin[8];
// CSR scratch
__device__ int    g_cnt[3 * MAXNO];
__device__ int    g_rowptr[3 * (MAXNO + 1)];
__device__ int    g_csrc[3 * MAXE];
__device__ int    g_bsum[3 * NBMAX];

struct CsrBatch {
    const int*   csrc[3];
    const int*   rowptr[3];
    const float* psrc[3];
    const float* pdst[3];
    const float* hsrc[3];
    float*       outp[3];
    int          N[3];
};

struct FeatPair {
    const float* A[2];
    const float* A2[2];
    const float* W[2];
    const float* bias[2];
    float*       C[2];
    float*       proj[2];
    const float* v[2][4];
    const float* wbuf;
    int          M[2];
    int          mode[2];
    int          nv[2];
};

// ---------------------------------------------------------------------------
// bf16 mma helpers
// ---------------------------------------------------------------------------
__device__ __forceinline__ void mma16(float* c,
                                      uint32_t a0, uint32_t a1, uint32_t a2, uint32_t a3,
                                      uint32_t b0, uint32_t b1)
{
    asm volatile(
        "mma.sync.aligned.m16n8k16.row.col.f32.bf16.bf16.f32 "
        "{%0,%1,%2,%3}, {%4,%5,%6,%7}, {%8,%9}, {%0,%1,%2,%3};"
        : "+f"(c[0]), "+f"(c[1]), "+f"(c[2]), "+f"(c[3])
        : "r"(a0), "r"(a1), "r"(a2), "r"(a3), "r"(b0), "r"(b1));
}

__device__ __forceinline__ float bf16_hi(float x) {
    uint32_t u = __float_as_uint(x);
    u = (u + 0x7FFFu + ((u >> 16) & 1u)) & 0xFFFF0000u;
    return __uint_as_float(u);
}
__device__ __forceinline__ uint32_t pack_hi16(float x, float y) {
    return __byte_perm(__float_as_uint(x), __float_as_uint(y), 0x7632);
}
__device__ __forceinline__ uint32_t pack_bf16x2(float x, float y) {
    uint32_t r;
    asm("cvt.rn.bf16x2.f32 %0, %1, %2;" : "=r"(r) : "f"(y), "f"(x));
    return r;
}

// ---------------------------------------------------------------------------
// mma_feat2: both feature GEMMs of a layer in one launch; grid.y = problem.
// C[M,128] = op(A)[M,128] @ W[128,128] + bias, bf16x2 split
// (hi*hi + hi*lo + lo*hi), node projections fused into epilogue.
// Warp tile 32x64. mode: 0 plain, 1 relu, 2 w0*relu(A)+w1*relu(A2).
// ---------------------------------------------------------------------------
__global__ __launch_bounds__(256) void mma_feat2_kernel(FeatPair fp)
{
    const int P = blockIdx.y;
    const int M = fp.M[P];
    const int m0 = blockIdx.x * 128;
    if (m0 >= M) return;

    extern __shared__ uint2 usm[];
    uint2* Asm = usm;
    uint2* Bsm = usm + 2048;
    const int tid  = threadIdx.x;
    const int w    = tid >> 5, lane = tid & 31;
    const int gid  = lane >> 2, tig = lane & 3;
    const int rw   = w >> 1, cw = w & 1;

    const float* __restrict__ A    = fp.A[P];
    const float* __restrict__ A2   = fp.A2[P];
    const float* __restrict__ W    = fp.W[P];
    const float* __restrict__ bias = fp.bias[P];
    float* __restrict__ C          = fp.C[P];
    float* __restrict__ projOut    = fp.proj[P];
    const int mode = fp.mode[P];
    const int nv   = fp.nv[P];

    float cw0 = 0.f, cw1 = 0.f;
    if (mode == 2) { cw0 = fp.wbuf[0]; cw1 = fp.wbuf[1]; }

    float acc[2][8][4];
#pragma unroll
    for (int mt = 0; mt < 2; mt++)
#pragma unroll
        for (int i = 0; i < 8; i++)
#pragma unroll
            for (int j = 0; j < 4; j++) acc[mt][i][j] = 0.f;

    for (int kc = 0; kc < 128; kc += 32) {
        for (int i = tid; i < 1024; i += 256) {
            int r   = i >> 3;
            int c4  = (i & 7) << 2;
            int kp0 = c4 >> 1;
            float4 v = make_float4(0.f, 0.f, 0.f, 0.f);
            if (m0 + r < M) {
                v = *(const float4*)(A + (size_t)(m0 + r) * 128 + kc + c4);
                if (mode == 1) {
                    v.x = fmaxf(v.x, 0.f); v.y = fmaxf(v.y, 0.f);
                    v.z = fmaxf(v.z, 0.f); v.w = fmaxf(v.w, 0.f);
                } else if (mode == 2) {
                    float4 u = *(const float4*)(A2 + (size_t)(m0 + r) * 128 + kc + c4);
                    v.x = cw0 * fmaxf(v.x, 0.f) + cw1 * fmaxf(u.x, 0.f);
                    v.y = cw0 * fmaxf(v.y, 0.f) + cw1 * fmaxf(u.y, 0.f);
                    v.z = cw0 * fmaxf(v.z, 0.f) + cw1 * fmaxf(u.z, 0.f);
                    v.w = cw0 * fmaxf(v.w, 0.f) + cw1 * fmaxf(u.w, 0.f);
                }
            }
            float hx = bf16_hi(v.x), hy = bf16_hi(v.y);
            float hz = bf16_hi(v.z), hw = bf16_hi(v.w);
            uint2 w0, w1;
            w0.x = pack_hi16(hx, hy);
            w0.y = pack_bf16x2(v.x - hx, v.y - hy);
            w1.x = pack_hi16(hz, hw);
            w1.y = pack_bf16x2(v.z - hz, v.w - hw);
            int rot = (r & 7) << 1;
            Asm[r * 16 + ((kp0 + rot) & 15)]     = w0;
            Asm[r * 16 + ((kp0 + 1 + rot) & 15)] = w1;
        }
        for (int i = tid; i < 2048; i += 256) {
            int n = i & 127, kp = i >> 7;
            float x0 = W[(size_t)(kc + 2 * kp) * 128 + n];
            float x1 = W[(size_t)(kc + 2 * kp + 1) * 128 + n];
            float h0 = bf16_hi(x0), h1 = bf16_hi(x1);
            uint2 wv;
            wv.x = pack_hi16(h0, h1);
            wv.y = pack_bf16x2(x0 - h0, x1 - h1);
            Bsm[n * 16 + ((kp + ((n & 7) << 1)) & 15)] = wv;
        }
        __syncthreads();

#pragma unroll
        for (int ks = 0; ks < 2; ks++) {
            int base = ks * 8;
            int rot = gid << 1;
            uint32_t ah[2][4], al[2][4];
#pragma unroll
            for (int mt = 0; mt < 2; mt++) {
                int ra = rw * 32 + mt * 16 + gid;
                uint2 u0 = Asm[ra * 16 + ((base + tig + rot) & 15)];
                uint2 u1 = Asm[(ra + 8) * 16 + ((base + tig + rot) & 15)];
                uint2 u2 = Asm[ra * 16 + ((base + 4 + tig + rot) & 15)];
                uint2 u3 = Asm[(ra + 8) * 16 + ((base + 4 + tig + rot) & 15)];
                ah[mt][0] = u0.x; al[mt][0] = u0.y;
                ah[mt][1] = u1.x; al[mt][1] = u1.y;
                ah[mt][2] = u2.x; al[mt][2] = u2.y;
                ah[mt][3] = u3.x; al[mt][3] = u3.y;
            }
#pragma unroll
            for (int nt = 0; nt < 8; nt++) {
                int n = cw * 64 + nt * 8 + gid;
                uint2 b0 = Bsm[n * 16 + ((base + tig + rot) & 15)];
                uint2 b1 = Bsm[n * 16 + ((base + 4 + tig + rot) & 15)];
#pragma unroll
                for (int mt = 0; mt < 2; mt++) {
                    mma16(acc[mt][nt], ah[mt][0], ah[mt][1], ah[mt][2], ah[mt][3], b0.x, b1.x);
                    mma16(acc[mt][nt], ah[mt][0], ah[mt][1], ah[mt][2], ah[mt][3], b0.y, b1.y);
                    mma16(acc[mt][nt], al[mt][0], al[mt][1], al[mt][2], al[mt][3], b0.x, b1.x);
                }
            }
        }
        __syncthreads();
    }

    int r0 = m0 + rw * 32 + gid;
#pragma unroll
    for (int mt = 0; mt < 2; mt++) {
        int rA = r0 + mt * 16;
#pragma unroll
        for (int nt = 0; nt < 8; nt++) {
            int col = cw * 64 + nt * 8 + (tig << 1);
            float2 b2 = *(const float2*)(bias + col);
            acc[mt][nt][0] += b2.x; acc[mt][nt][1] += b2.y;
            acc[mt][nt][2] += b2.x; acc[mt][nt][3] += b2.y;
            if (rA < M)
                *(float2*)(C + (size_t)rA * 128 + col) =
                    make_float2(acc[mt][nt][0], acc[mt][nt][1]);
            if (rA + 8 < M)
                *(float2*)(C + (size_t)(rA + 8) * 128 + col) =
                    make_float2(acc[mt][nt][2], acc[mt][nt][3]);
        }
    }

    {
#pragma unroll
        for (int v = 0; v < 4; v++) {
            if (v >= nv) break;
            const float* vv = fp.v[P][v];
            float p[4] = {0.f, 0.f, 0.f, 0.f};
#pragma unroll
            for (int mt = 0; mt < 2; mt++)
#pragma unroll
                for (int nt = 0; nt < 8; nt++) {
                    int col = cw * 64 + nt * 8 + (tig << 1);
                    float2 vvc = *(const float2*)(vv + col);
                    p[2 * mt + 0] += acc[mt][nt][0] * vvc.x + acc[mt][nt][1] * vvc.y;
                    p[2 * mt + 1] += acc[mt][nt][2] * vvc.x + acc[mt][nt][3] * vvc.y;
                }
#pragma unroll
            for (int j = 0; j < 4; j++) {
                p[j] += __shfl_xor_sync(0xffffffffu, p[j], 1);
                p[j] += __shfl_xor_sync(0xffffffffu, p[j], 2);
            }
            if (tig == 0) {
#pragma unroll
                for (int j = 0; j < 4; j++) {
                    int row = r0 + j * 8;
                    if (row < M)
                        projOut[((size_t)v * M + row) * 2 + cw] = p[j];
                }
            }
        }
    }
}

// ---------------------------------------------------------------------------
// mma_score: score[blockIdx.y] += sum q[n]*tanh((relu(A_y)@Wk + bk)[m,n])
// single-pass bf16, warp tile 32x64.
// ---------------------------------------------------------------------------
__global__ __launch_bounds__(256) void mma_score_kernel(
    const float* __restrict__ Aa, const float* __restrict__ Ab,
    const float* __restrict__ W, const float* __restrict__ bias,
    const float* __restrict__ q, int M, double* __restrict__ outScore)
{
    __shared__ uint32_t As[128 * 16];
    __shared__ uint32_t Bs[128 * 16];
    __shared__ float red[8];
    const float* A = (blockIdx.y == 0) ? Aa : Ab;
    const int tid = threadIdx.x;
    const int w   = tid >> 5, lane = tid & 31;
    const int gid = lane >> 2, tig = lane & 3;
    const int rw  = w >> 1, cw = w & 1;
    const int m0  = blockIdx.x * 128;

    float acc[2][8][4];
#pragma unroll
    for (int mt = 0; mt < 2; mt++)
#pragma unroll
        for (int i = 0; i < 8; i++)
#pragma unroll
            for (int j = 0; j < 4; j++) acc[mt][i][j] = 0.f;

    for (int kc = 0; kc < 128; kc += 32) {
        for (int i = tid; i < 1024; i += 256) {
            int r   = i >> 3;
            int c4  = (i & 7) << 2;
            int kp0 = c4 >> 1;
            float4 v = make_float4(0.f, 0.f, 0.f, 0.f);
            if (m0 + r < M)
                v = *(const float4*)(A + (size_t)(m0 + r) * 128 + kc + c4);
            int rot = (r & 7) << 1;
            As[r * 16 + ((kp0 + rot) & 15)] =
                pack_bf16x2(fmaxf(v.x, 0.f), fmaxf(v.y, 0.f));
            As[r * 16 + ((kp0 + 1 + rot) & 15)] =
                pack_bf16x2(fmaxf(v.z, 0.f), fmaxf(v.w, 0.f));
        }
        for (int i = tid; i < 2048; i += 256) {
            int n = i & 127, kp = i >> 7;
            float x0 = W[(size_t)(kc + 2 * kp) * 128 + n];
            float x1 = W[(size_t)(kc + 2 * kp + 1) * 128 + n];
            Bs[n * 16 + ((kp + ((n & 7) << 1)) & 15)] = pack_bf16x2(x0, x1);
        }
        __syncthreads();

#pragma unroll
        for (int ks = 0; ks < 2; ks++) {
            int base = ks * 8;
            int rot = gid << 1;
            uint32_t a[2][4];
#pragma unroll
            for (int mt = 0; mt < 2; mt++) {
                int ra = rw * 32 + mt * 16 + gid;
                a[mt][0] = As[ra * 16 + ((base + tig + rot) & 15)];
                a[mt][1] = As[(ra + 8) * 16 + ((base + tig + rot) & 15)];
                a[mt][2] = As[ra * 16 + ((base + 4 + tig + rot) & 15)];
                a[mt][3] = As[(ra + 8) * 16 + ((base + 4 + tig + rot) & 15)];
            }
#pragma unroll
            for (int nt = 0; nt < 8; nt++) {
                int n = cw * 64 + nt * 8 + gid;
                uint32_t b0 = Bs[n * 16 + ((base + tig + rot) & 15)];
                uint32_t b1 = Bs[n * 16 + ((base + 4 + tig + rot) & 15)];
#pragma unroll
                for (int mt = 0; mt < 2; mt++)
                    mma16(acc[mt][nt], a[mt][0], a[mt][1], a[mt][2], a[mt][3], b0, b1);
            }
        }
        __syncthreads();
    }

    float local = 0.f;
    int r0 = m0 + rw * 32 + gid;
#pragma unroll
    for (int mt = 0; mt < 2; mt++) {
        int rA = r0 + mt * 16;
#pragma unroll
        for (int nt = 0; nt < 8; nt++) {
            int col = cw * 64 + nt * 8 + (tig << 1);
            float2 b2 = *(const float2*)(bias + col);
            float2 q2 = *(const float2*)(q + col);
            if (rA < M) {
                local += q2.x * tanhf(acc[mt][nt][0] + b2.x);
                local += q2.y * tanhf(acc[mt][nt][1] + b2.y);
            }
            if (rA + 8 < M) {
                local += q2.x * tanhf(acc[mt][nt][2] + b2.x);
                local += q2.y * tanhf(acc[mt][nt][3] + b2.y);
            }
        }
    }
#pragma unroll
    for (int o = 16; o > 0; o >>= 1)
        local += __shfl_xor_sync(0xffffffffu, local, o);
    if (lane == 0) red[w] = local;
    __syncthreads();
    if (tid == 0) {
        double s = 0.0;
        for (int i = 0; i < 8; i++) s += (double)red[i];
        atomicAdd(outScore + blockIdx.y, s);
    }
}

// ---------------------------------------------------------------------------
// CSR build
// ---------------------------------------------------------------------------
__global__ __launch_bounds__(256) void hist_kernel(
    const int* d0, const int* d1, const int* d2,
    int E0, int E1, int E2, int* __restrict__ cnt)
{
    int t = blockIdx.y;
    const int* d = t == 0 ? d0 : (t == 1 ? d1 : d2);
    int E = t == 0 ? E0 : (t == 1 ? E1 : E2);
    int e = blockIdx.x * blockDim.x + threadIdx.x;
    if (e < E) atomicAdd(cnt + t * MAXNO + d[e], 1);
}

__global__ __launch_bounds__(256) void blocksum_kernel(
    const int* __restrict__ cnt, int* __restrict__ bsum,
    int N0, int N1, int N2)
{
    int t = blockIdx.y, b = blockIdx.x;
    int N = t == 0 ? N0 : (t == 1 ? N1 : N2);
    int base = b * 1024;
    int ssum = 0;
    for (int i = threadIdx.x; i < 1024; i += 256) {
        int idx = base + i;
        if (idx < N) ssum += cnt[t * MAXNO + idx];
    }
    __shared__ int red[256];
    red[threadIdx.x] = ssum; __syncthreads();
    for (int o = 128; o > 0; o >>= 1) {
        if (threadIdx.x < o) red[threadIdx.x] += red[threadIdx.x + o];
        __syncthreads();
    }
    if (threadIdx.x == 0) bsum[t * NBMAX + b] = red[0];
}

__global__ __launch_bounds__(128) void scanb_kernel(
    int* __restrict__ bsum, int* __restrict__ rowptr,
    int N0, int N1, int N2, int E0, int E1, int E2)
{
    __shared__ int sm[NBMAX];
    int tid = threadIdx.x;
    for (int t = 0; t < 3; t++) {
        int v = bsum[t * NBMAX + tid];
        sm[tid] = v; __syncthreads();
        for (int o = 1; o < NBMAX; o <<= 1) {
            int y = (tid >= o) ? sm[tid - o] : 0;
            __syncthreads();
            sm[tid] += y;
            __syncthreads();
        }
        bsum[t * NBMAX + tid] = sm[tid] - v;
        __syncthreads();
    }
    if (tid == 0) {
        rowptr[0 * (MAXNO + 1) + N0] = E0;
        rowptr[1 * (MAXNO + 1) + N1] = E1;
        rowptr[2 * (MAXNO + 1) + N2] = E2;
    }
}

// local scan; also zeroes cnt in place (each element read exactly once here)
__global__ __launch_bounds__(256) void scanc_kernel(
    int* __restrict__ cnt, const int* __restrict__ bsum,
    int* __restrict__ rowptr, int N0, int N1, int N2)
{
    int t = blockIdx.y, b = blockIdx.x;
    int N = t == 0 ? N0 : (t == 1 ? N1 : N2);
    int tid = threadIdx.x;
    int idx0 = b * 1024 + tid * 4;
    int c[4]; int ssum = 0;
#pragma unroll
    for (int j = 0; j < 4; j++) {
        int idx = idx0 + j;
        c[j] = (idx < N) ? cnt[t * MAXNO + idx] : 0;
        if (idx < N) cnt[t * MAXNO + idx] = 0;
        ssum += c[j];
    }
    __shared__ int sm[256];
    sm[tid] = ssum; __syncthreads();
    for (int o = 1; o < 256; o <<= 1) {
        int y = (tid >= o) ? sm[tid - o] : 0;
        __syncthreads();
        sm[tid] += y;
        __syncthreads();
    }
    int off = bsum[t * NBMAX + b] + (tid > 0 ? sm[tid - 1] : 0);
#pragma unroll
    for (int j = 0; j < 4; j++) {
        int idx = idx0 + j;
        if (idx < N) rowptr[t * (MAXNO + 1) + idx] = off;
        off += c[j];
    }
}

__global__ __launch_bounds__(256) void scatter_kernel(
    const int* s0, const int* d0, const int* s1, const int* d1,
    const int* s2, const int* d2, int E0, int E1, int E2,
    const int* __restrict__ rowptr, int* __restrict__ cur,
    int* __restrict__ csrc)
{
    int t = blockIdx.y;
    const int* s = t == 0 ? s0 : (t == 1 ? s1 : s2);
    const int* d = t == 0 ? d0 : (t == 1 ? d1 : d2);
    int E = t == 0 ? E0 : (t == 1 ? E1 : E2);
    int e = blockIdx.x * blockDim.x + threadIdx.x;
    if (e >= E) return;
    int dn = d[e];
    int pos = rowptr[t * (MAXNO + 1) + dn] + atomicAdd(cur + t * MAXNO + dn, 1);
    csrc[t * MAXE + pos] = s[e];
}

// ---------------------------------------------------------------------------
// Fused edge kernel: warp per dst node. deg<=32 fast path caches sn/e0/e1
// in registers across both phases (no second ps gather / exp).
// ---------------------------------------------------------------------------
__global__ __launch_bounds__(256) void edge_fused_kernel(CsrBatch cb)
{
    int t = blockIdx.y;
    int node = (blockIdx.x * 256 + threadIdx.x) >> 5;
    if (node >= cb.N[t]) return;
    int lane = threadIdx.x & 31;
    const int* rp = cb.rowptr[t];
    int beg = rp[node], end = rp[node + 1];
    int deg = end - beg;
    const float2* ps = (const float2*)cb.psrc[t];
    float2 pdv = ((const float2*)cb.pdst[t])[node];
    int head = lane >> 4;

    // first block (cached)
    int sn0 = 0; float ce0 = 0.f, ce1 = 0.f;
    {
        int i = beg + lane;
        if (i < end) {
            sn0 = cb.csrc[t][i];
            float2 p = ps[sn0];
            float a0 = p.x + pdv.x; a0 = a0 > 0.f ? a0 : 0.2f * a0;
            float a1 = p.y + pdv.y; a1 = a1 > 0.f ? a1 : 0.2f * a1;
            ce0 = expf(a0); ce1 = expf(a1);
        }
    }
    float s0 = ce0, s1 = ce1;
#pragma unroll
    for (int o = 16; o > 0; o >>= 1) {
        s0 += __shfl_xor_sync(0xffffffffu, s0, o);
        s1 += __shfl_xor_sync(0xffffffffu, s1, o);
    }
    // rare tail blocks for denominator
    for (int b = beg + 32; b < end; b += 32) {
        int i = b + lane;
        float e0 = 0.f, e1 = 0.f;
        if (i < end) {
            int sn = cb.csrc[t][i];
            float2 p = ps[sn];
            float a0 = p.x + pdv.x; a0 = a0 > 0.f ? a0 : 0.2f * a0;
            float a1 = p.y + pdv.y; a1 = a1 > 0.f ? a1 : 0.2f * a1;
            e0 = expf(a0); e1 = expf(a1);
        }
#pragma unroll
        for (int o = 16; o > 0; o >>= 1) {
            e0 += __shfl_xor_sync(0xffffffffu, e0, o);
            e1 += __shfl_xor_sync(0xffffffffu, e1, o);
        }
        s0 += e0; s1 += e1;
    }
    float inv = (head ? 1.f / (s1 + 1e-16f) : 1.f / (s0 + 1e-16f));

    // phase 2: first block from cached regs
    float4 acc = make_float4(0.f, 0.f, 0.f, 0.f);
    {
        int cnt0 = deg < 32 ? deg : 32;
        for (int j = 0; j < cnt0; j++) {
            int   sj  = __shfl_sync(0xffffffffu, sn0, j);
            float e0j = __shfl_sync(0xffffffffu, ce0, j);
            float e1j = __shfl_sync(0xffffffffu, ce1, j);
            float wj  = (head ? e1j : e0j) * inv;
            float4 v = *(const float4*)(cb.hsrc[t] + (size_t)sj * 128 + lane * 4);
            acc.x += wj * v.x; acc.y += wj * v.y;
            acc.z += wj * v.z; acc.w += wj * v.w;
        }
    }
    // rare tail blocks (recompute)
    for (int b = beg + 32; b < end; b += 32) {
        int i = b + lane;
        int sn = 0; float e0 = 0.f, e1 = 0.f;
        if (i < end) {
            sn = cb.csrc[t][i];
            float2 p = ps[sn];
            float a0 = p.x + pdv.x; a0 = a0 > 0.f ? a0 : 0.2f * a0;
            float a1 = p.y + pdv.y; a1 = a1 > 0.f ? a1 : 0.2f * a1;
            e0 = expf(a0); e1 = expf(a1);
        }
        int cntj = end - b; if (cntj > 32) cntj = 32;
        for (int j = 0; j < cntj; j++) {
            int   sj  = __shfl_sync(0xffffffffu, sn, j);
            float e0j = __shfl_sync(0xffffffffu, e0, j);
            float e1j = __shfl_sync(0xffffffffu, e1, j);
            float wj  = (head ? e1j : e0j) * inv;
            float4 v = *(const float4*)(cb.hsrc[t] + (size_t)sj * 128 + lane * 4);
            acc.x += wj * v.x; acc.y += wj * v.y;
            acc.z += wj * v.z; acc.w += wj * v.w;
        }
    }
    *(float4*)(cb.outp[t] + (size_t)node * 128 + lane * 4) = acc;
}

// ---------------------------------------------------------------------------
// Semantic attention tail + MLP
// ---------------------------------------------------------------------------
__global__ void softmax2_kernel(const double* __restrict__ sc,
                                float* __restrict__ w, double invN)
{
    double s0 = sc[0] * invN, s1 = sc[1] * invN;
    double mx = s0 > s1 ? s0 : s1;
    double e0 = exp(s0 - mx), e1 = exp(s1 - mx);
    double sum = e0 + e1;
    w[0] = (float)(e0 / sum);
    w[1] = (float)(e1 / sum);
}

__global__ __launch_bounds__(256) void precompute_kernel(
    const float* __restrict__ Wl1, const float* __restrict__ bl1,
    const float* __restrict__ Wl2, const float* __restrict__ bl2,
    const float* __restrict__ Wl3, const float* __restrict__ bl3,
    float* __restrict__ W123, float* __restrict__ bfin)
{
    __shared__ float W23[256 * 8];
    __shared__ float t1s[128];
    int tid = threadIdx.x;
    for (int i = tid; i < 2048; i += 256) {
        int r = i >> 3, j = i & 7;
        float a = 0.f;
        for (int c = 0; c < 128; c++) a += Wl2[r * 128 + c] * Wl3[c * 8 + j];
        W23[i] = a;
    }
    for (int n = tid; n < 128; n += 256) {
        float a = bl2[n];
        for (int k = 0; k < 256; k++) a += bl1[k] * Wl2[k * 128 + n];
        t1s[n] = a;
    }
    __syncthreads();
    for (int i = tid; i < 1024; i += 256) {
        int k = i >> 3, j = i & 7;
        float a = 0.f;
        for (int r = 0; r < 256; r++) a += Wl1[k * 256 + r] * W23[r * 8 + j];
        W123[i] = a;
    }
    if (tid < 8) {
        float a = bl3[tid];
        for (int c = 0; c < 128; c++) a += t1s[c] * Wl3[c * 8 + tid];
        bfin[tid] = a;
    }
}

__global__ __launch_bounds__(256) void mlp_final_kernel(
    const float* __restrict__ o0, const float* __restrict__ o1,
    const float* __restrict__ wbuf, const float* __restrict__ W123,
    const float* __restrict__ bfin, float* __restrict__ out, int No)
{
    __shared__ float Ws[128 * 8];
    __shared__ float bs[8];
    for (int i = threadIdx.x; i < 128 * 8; i += blockDim.x) Ws[i] = W123[i];
    if (threadIdx.x < 8) bs[threadIdx.x] = bfin[threadIdx.x];
    __syncthreads();
    float w0 = wbuf[0], w1 = wbuf[1];
    int gid = blockIdx.x * blockDim.x + threadIdx.x;
    int row = gid >> 3, j = gid & 7;
    if (row >= No) return;
    const float* r0 = o0 + (size_t)row * 128;
    const float* r1 = o1 + (size_t)row * 128;
    float acc = 0.f;
#pragma unroll
    for (int k = 0; k < 128; k += 4) {
        float4 a = *(const float4*)(r0 + k);
        float4 b = *(const float4*)(r1 + k);
        float x0 = w0 * fmaxf(a.x, 0.f) + w1 * fmaxf(b.x, 0.f);
        float x1 = w0 * fmaxf(a.y, 0.f) + w1 * fmaxf(b.y, 0.f);
        float x2 = w0 * fmaxf(a.z, 0.f) + w1 * fmaxf(b.z, 0.f);
        float x3 = w0 * fmaxf(a.w, 0.f) + w1 * fmaxf(b.w, 0.f);
        acc += x0 * Ws[(k + 0) * 8 + j];
        acc += x1 * Ws[(k + 1) * 8 + j];
        acc += x2 * Ws[(k + 2) * 8 + j];
        acc += x3 * Ws[(k + 3) * 8 + j];
    }
    float x = acc + bs[j];
    out[(size_t)row * 8 + j] = 1.f / (1.f + expf(-x));
}

// ---------------------------------------------------------------------------
// Host orchestration
// ---------------------------------------------------------------------------
static inline int ceil_div(int a, int b) { return (a + b - 1) / b; }

extern "C" void kernel_launch(void* const* d_in, const int* in_sizes, int n_in,
                              void* d_out, int out_size)
{
    const float* xo  = (const float*)d_in[0];
    const float* xa  = (const float*)d_in[1];
    const int*   eoo = (const int*)d_in[2];
    const int*   eoa = (const int*)d_in[3];
    const int*   eao = (const int*)d_in[4];
    const int No  = in_sizes[0] / 128;
    const int Na  = in_sizes[1] / 128;
    const int Eoo = in_sizes[2] / 2;
    const int Eoa = in_sizes[3] / 2;
    const int Eao = in_sizes[4] / 2;

    float *ho, *ha, *o0, *o1, *oa, *pobj, *patt, *w, *W123, *bfin;
    int *cnt, *rowptr, *csrc, *bsum;
    double* score;
    cudaGetSymbolAddress((void**)&ho,     g_ho);
    cudaGetSymbolAddress((void**)&ha,     g_ha);
    cudaGetSymbolAddress((void**)&o0,     g_o0);
    cudaGetSymbolAddress((void**)&o1,     g_o1);
    cudaGetSymbolAddress((void**)&oa,     g_oa);
    cudaGetSymbolAddress((void**)&pobj,   g_pobj);
    cudaGetSymbolAddress((void**)&patt,   g_patt);
    cudaGetSymbolAddress((void**)&score,  g_score);
    cudaGetSymbolAddress((void**)&w,      g_w);
    cudaGetSymbolAddress((void**)&W123,   g_W123);
    cudaGetSymbolAddress((void**)&bfin,   g_bfin);
    cudaGetSymbolAddress((void**)&cnt,    g_cnt);
    cudaGetSymbolAddress((void**)&rowptr, g_rowptr);
    cudaGetSymbolAddress((void**)&csrc,   g_csrc);
    cudaGetSymbolAddress((void**)&bsum,   g_bsum);

    const int FEAT_SMEM = 32768;
    cudaFuncSetAttribute(mma_feat2_kernel,
                         cudaFuncAttributeMaxDynamicSharedMemorySize, FEAT_SMEM);

    const int tilesNo = ceil_div(No, 128);
    const int maxE = (Eoo > Eao ? (Eoo > Eoa ? Eoo : Eoa) : (Eao > Eoa ? Eao : Eoa));

    // ---- CSR build (types: 0=oo, 1=ao, 2=oa) ----
    const int* dst0 = eoo + Eoo;
    const int* dst1 = eao + Eao;
    const int* dst2 = eoa + Eoa;
    cudaMemsetAsync(cnt, 0, 3 * MAXNO * sizeof(int));
    hist_kernel<<<dim3(ceil_div(maxE, 256), 3), 256>>>(
        dst0, dst1, dst2, Eoo, Eao, Eoa, cnt);
    blocksum_kernel<<<dim3(NBMAX, 3), 256>>>(cnt, bsum, No, No, Na);
    scanb_kernel<<<1, NBMAX>>>(bsum, rowptr, No, No, Na, Eoo, Eao, Eoa);
    scanc_kernel<<<dim3(ceil_div(No, 1024), 3), 256>>>(cnt, bsum, rowptr, No, No, Na);
    scatter_kernel<<<dim3(ceil_div(maxE, 256), 3), 256>>>(
        eoo, dst0, eao, dst1, eoa, dst2, Eoo, Eao, Eoa, rowptr, cnt, csrc);

    precompute_kernel<<<1, 256>>>(
        (const float*)d_in[23], (const float*)d_in[24], (const float*)d_in[25],
        (const float*)d_in[26], (const float*)d_in[27], (const float*)d_in[28],
        W123, bfin);

    for (int layer = 0; layer < 2; layer++) {
        const int base = 5 + 9 * layer;
        const float* Wo   = (const float*)d_in[base + 0];
        const float* bo   = (const float*)d_in[base + 1];
        const float* Wa   = (const float*)d_in[base + 2];
        const float* ba   = (const float*)d_in[base + 3];
        const float* asrc = (const float*)d_in[base + 4];
        const float* adst = (const float*)d_in[base + 5];
        const float* Wk   = (const float*)d_in[base + 6];
        const float* bk   = (const float*)d_in[base + 7];
        const float* q    = (const float*)d_in[base + 8];

        FeatPair fp;
        fp.wbuf = w;
        // problem 0: object features
        fp.W[0] = Wo; fp.bias[0] = bo; fp.C[0] = ho; fp.proj[0] = pobj;
        fp.M[0] = No; fp.nv[0] = 4;
        fp.v[0][0] = asrc + 0;   fp.v[0][1] = asrc + 128;
        fp.v[0][2] = adst + 0;   fp.v[0][3] = adst + 256;
        // problem 1: attribute features
        fp.W[1] = Wa; fp.bias[1] = ba; fp.C[1] = ha; fp.proj[1] = patt;
        fp.M[1] = Na; fp.nv[1] = 2;
        fp.v[1][0] = asrc + 256; fp.v[1][1] = adst + 128;
        fp.v[1][2] = asrc;       fp.v[1][3] = asrc;
        if (layer == 0) {
            fp.A[0] = xo; fp.A2[0] = xo; fp.mode[0] = 0;
            fp.A[1] = xa; fp.A2[1] = xa; fp.mode[1] = 0;
        } else {
            fp.A[0] = o0; fp.A2[0] = o1; fp.mode[0] = 2;
            fp.A[1] = oa; fp.A2[1] = oa; fp.mode[1] = 1;
        }
        mma_feat2_kernel<<<dim3(tilesNo, 2), 256, FEAT_SMEM>>>(fp);

        const int ntypes = (layer == 0) ? 3 : 2;

        CsrBatch cb;
        cb.csrc[0] = csrc;               cb.rowptr[0] = rowptr;
        cb.psrc[0] = pobj + 0;           cb.pdst[0] = pobj + (size_t)2 * No * 2;
        cb.hsrc[0] = ho;                 cb.outp[0] = o0;  cb.N[0] = No;
        cb.csrc[1] = csrc + MAXE;        cb.rowptr[1] = rowptr + (MAXNO + 1);
        cb.psrc[1] = patt + 0;           cb.pdst[1] = pobj + (size_t)3 * No * 2;
        cb.hsrc[1] = ha;                 cb.outp[1] = o1;  cb.N[1] = No;
        cb.csrc[2] = csrc + 2 * MAXE;    cb.rowptr[2] = rowptr + 2 * (MAXNO + 1);
        cb.psrc[2] = pobj + (size_t)1 * No * 2;
        cb.pdst[2] = patt + (size_t)1 * Na * 2;
        cb.hsrc[2] = ho;                 cb.outp[2] = oa;
        cb.N[2] = (layer == 0) ? Na : 0;

        edge_fused_kernel<<<dim3(ceil_div(No * 32, 256), ntypes), 256>>>(cb);

        cudaMemsetAsync(score, 0, 2 * sizeof(double));
        mma_score_kernel<<<dim3(tilesNo, 2), 256>>>(o0, o1, Wk, bk, q, No, score);
        softmax2_kernel<<<1, 1>>>(score, w, 1.0 / (double)No);
    }

    mlp_final_kernel<<<ceil_div(No * 8, 256), 256>>>(
        o0, o1, w, W123, bfin, (float*)d_out, No);
}

// round 16
// speedup vs baseline: 2.7227x; 1.0888x over previous
#include <cuda_runtime.h>
#include <cuda_fp16.h>
#include <math.h>
#include <stdint.h>

// ============================================================================
// HAN: 2-layer heterogeneous GAT + semantic attention + collapsed MLP head.
// R16: h (ho/ha) stored as fp16 half2 straight from the GEMM epilogue; the
//      edge gather (largest L2 stream) and GEMM C writes halve. h feeds ONLY
//      edge_fused, so no other path changes. score zeroing folded into
//      precompute/softmax2 (2 fewer memset launches).
// Else identical to R12 (bf16x2-split mma GEMMs, CSR warp-per-node edges).
// ============================================================================

#define MAXNO 100096
#define MAXNA 50048
#define MAXE  500224
#define NBMAX 128

__device__ uint32_t g_ho16[MAXNO * 64];   // h as half2, 64 words/row
__device__ uint32_t g_ha16[MAXNA * 64];
__device__ float  g_o0[MAXNO * 128];
__device__ float  g_o1[MAXNO * 128];
__device__ float  g_oa[MAXNA * 128];
__device__ float  g_pobj[4 * MAXNO * 2];
__device__ float  g_patt[2 * MAXNA * 2];
__device__ double g_score[2];
__device__ float  g_w[2];
__device__ float  g_W123[128 * 8];
__device__ float  g_bfin[8];
// CSR scratch
__device__ int    g_cnt[3 * MAXNO];
__device__ int    g_rowptr[3 * (MAXNO + 1)];
__device__ int    g_csrc[3 * MAXE];
__device__ int    g_bsum[3 * NBMAX];

struct CsrBatch {
    const int*      csrc[3];
    const int*      rowptr[3];
    const float*    psrc[3];
    const float*    pdst[3];
    const uint32_t* hsrc[3];    // half2 rows, 64 words each
    float*          outp[3];
    int             N[3];
};

struct FeatPair {
    const float* A[2];
    const float* A2[2];
    const float* W[2];
    const float* bias[2];
    uint32_t*    C[2];          // half2 output
    float*       proj[2];
    const float* v[2][4];
    const float* wbuf;
    int          M[2];
    int          mode[2];
    int          nv[2];
};

// ---------------------------------------------------------------------------
// mma / packing helpers
// ---------------------------------------------------------------------------
__device__ __forceinline__ void mma16(float* c,
                                      uint32_t a0, uint32_t a1, uint32_t a2, uint32_t a3,
                                      uint32_t b0, uint32_t b1)
{
    asm volatile(
        "mma.sync.aligned.m16n8k16.row.col.f32.bf16.bf16.f32 "
        "{%0,%1,%2,%3}, {%4,%5,%6,%7}, {%8,%9}, {%0,%1,%2,%3};"
        : "+f"(c[0]), "+f"(c[1]), "+f"(c[2]), "+f"(c[3])
        : "r"(a0), "r"(a1), "r"(a2), "r"(a3), "r"(b0), "r"(b1));
}

__device__ __forceinline__ float bf16_hi(float x) {
    uint32_t u = __float_as_uint(x);
    u = (u + 0x7FFFu + ((u >> 16) & 1u)) & 0xFFFF0000u;
    return __uint_as_float(u);
}
__device__ __forceinline__ uint32_t pack_hi16(float x, float y) {
    return __byte_perm(__float_as_uint(x), __float_as_uint(y), 0x7632);
}
__device__ __forceinline__ uint32_t pack_bf16x2(float x, float y) {
    uint32_t r;
    asm("cvt.rn.bf16x2.f32 %0, %1, %2;" : "=r"(r) : "f"(y), "f"(x));
    return r;
}
__device__ __forceinline__ uint32_t pack_half2(float lo, float hi) {
    uint32_t r;
    asm("cvt.rn.f16x2.f32 %0, %1, %2;" : "=r"(r) : "f"(hi), "f"(lo));
    return r;
}

// ---------------------------------------------------------------------------
// mma_feat2: both feature GEMMs of a layer in one launch; grid.y = problem.
// C(half2)[M,64w] = op(A)[M,128] @ W[128,128] + bias, bf16x2 split,
// node projections fused into epilogue. Warp tile 32x64.
// mode: 0 plain, 1 relu, 2 w0*relu(A)+w1*relu(A2).
// ---------------------------------------------------------------------------
__global__ __launch_bounds__(256) void mma_feat2_kernel(FeatPair fp)
{
    const int P = blockIdx.y;
    const int M = fp.M[P];
    const int m0 = blockIdx.x * 128;
    if (m0 >= M) return;

    extern __shared__ uint2 usm[];
    uint2* Asm = usm;
    uint2* Bsm = usm + 2048;
    const int tid  = threadIdx.x;
    const int w    = tid >> 5, lane = tid & 31;
    const int gid  = lane >> 2, tig = lane & 3;
    const int rw   = w >> 1, cw = w & 1;

    const float* __restrict__ A    = fp.A[P];
    const float* __restrict__ A2   = fp.A2[P];
    const float* __restrict__ W    = fp.W[P];
    const float* __restrict__ bias = fp.bias[P];
    uint32_t* __restrict__ C       = fp.C[P];
    float* __restrict__ projOut    = fp.proj[P];
    const int mode = fp.mode[P];
    const int nv   = fp.nv[P];

    float cw0 = 0.f, cw1 = 0.f;
    if (mode == 2) { cw0 = fp.wbuf[0]; cw1 = fp.wbuf[1]; }

    float acc[2][8][4];
#pragma unroll
    for (int mt = 0; mt < 2; mt++)
#pragma unroll
        for (int i = 0; i < 8; i++)
#pragma unroll
            for (int j = 0; j < 4; j++) acc[mt][i][j] = 0.f;

    for (int kc = 0; kc < 128; kc += 32) {
        for (int i = tid; i < 1024; i += 256) {
            int r   = i >> 3;
            int c4  = (i & 7) << 2;
            int kp0 = c4 >> 1;
            float4 v = make_float4(0.f, 0.f, 0.f, 0.f);
            if (m0 + r < M) {
                v = *(const float4*)(A + (size_t)(m0 + r) * 128 + kc + c4);
                if (mode == 1) {
                    v.x = fmaxf(v.x, 0.f); v.y = fmaxf(v.y, 0.f);
                    v.z = fmaxf(v.z, 0.f); v.w = fmaxf(v.w, 0.f);
                } else if (mode == 2) {
                    float4 u = *(const float4*)(A2 + (size_t)(m0 + r) * 128 + kc + c4);
                    v.x = cw0 * fmaxf(v.x, 0.f) + cw1 * fmaxf(u.x, 0.f);
                    v.y = cw0 * fmaxf(v.y, 0.f) + cw1 * fmaxf(u.y, 0.f);
                    v.z = cw0 * fmaxf(v.z, 0.f) + cw1 * fmaxf(u.z, 0.f);
                    v.w = cw0 * fmaxf(v.w, 0.f) + cw1 * fmaxf(u.w, 0.f);
                }
            }
            float hx = bf16_hi(v.x), hy = bf16_hi(v.y);
            float hz = bf16_hi(v.z), hw = bf16_hi(v.w);
            uint2 w0, w1;
            w0.x = pack_hi16(hx, hy);
            w0.y = pack_bf16x2(v.x - hx, v.y - hy);
            w1.x = pack_hi16(hz, hw);
            w1.y = pack_bf16x2(v.z - hz, v.w - hw);
            int rot = (r & 7) << 1;
            Asm[r * 16 + ((kp0 + rot) & 15)]     = w0;
            Asm[r * 16 + ((kp0 + 1 + rot) & 15)] = w1;
        }
        for (int i = tid; i < 2048; i += 256) {
            int n = i & 127, kp = i >> 7;
            float x0 = W[(size_t)(kc + 2 * kp) * 128 + n];
            float x1 = W[(size_t)(kc + 2 * kp + 1) * 128 + n];
            float h0 = bf16_hi(x0), h1 = bf16_hi(x1);
            uint2 wv;
            wv.x = pack_hi16(h0, h1);
            wv.y = pack_bf16x2(x0 - h0, x1 - h1);
            Bsm[n * 16 + ((kp + ((n & 7) << 1)) & 15)] = wv;
        }
        __syncthreads();

#pragma unroll
        for (int ks = 0; ks < 2; ks++) {
            int base = ks * 8;
            int rot = gid << 1;
            uint32_t ah[2][4], al[2][4];
#pragma unroll
            for (int mt = 0; mt < 2; mt++) {
                int ra = rw * 32 + mt * 16 + gid;
                uint2 u0 = Asm[ra * 16 + ((base + tig + rot) & 15)];
                uint2 u1 = Asm[(ra + 8) * 16 + ((base + tig + rot) & 15)];
                uint2 u2 = Asm[ra * 16 + ((base + 4 + tig + rot) & 15)];
                uint2 u3 = Asm[(ra + 8) * 16 + ((base + 4 + tig + rot) & 15)];
                ah[mt][0] = u0.x; al[mt][0] = u0.y;
                ah[mt][1] = u1.x; al[mt][1] = u1.y;
                ah[mt][2] = u2.x; al[mt][2] = u2.y;
                ah[mt][3] = u3.x; al[mt][3] = u3.y;
            }
#pragma unroll
            for (int nt = 0; nt < 8; nt++) {
                int n = cw * 64 + nt * 8 + gid;
                uint2 b0 = Bsm[n * 16 + ((base + tig + rot) & 15)];
                uint2 b1 = Bsm[n * 16 + ((base + 4 + tig + rot) & 15)];
#pragma unroll
                for (int mt = 0; mt < 2; mt++) {
                    mma16(acc[mt][nt], ah[mt][0], ah[mt][1], ah[mt][2], ah[mt][3], b0.x, b1.x);
                    mma16(acc[mt][nt], ah[mt][0], ah[mt][1], ah[mt][2], ah[mt][3], b0.y, b1.y);
                    mma16(acc[mt][nt], al[mt][0], al[mt][1], al[mt][2], al[mt][3], b0.x, b1.x);
                }
            }
        }
        __syncthreads();
    }

    // ---- epilogue: bias + fp16 store ----
    int r0 = m0 + rw * 32 + gid;
#pragma unroll
    for (int mt = 0; mt < 2; mt++) {
        int rA = r0 + mt * 16;
#pragma unroll
        for (int nt = 0; nt < 8; nt++) {
            int col = cw * 64 + nt * 8 + (tig << 1);
            float2 b2 = *(const float2*)(bias + col);
            acc[mt][nt][0] += b2.x; acc[mt][nt][1] += b2.y;
            acc[mt][nt][2] += b2.x; acc[mt][nt][3] += b2.y;
            if (rA < M)
                C[(size_t)rA * 64 + (col >> 1)] =
                    pack_half2(acc[mt][nt][0], acc[mt][nt][1]);
            if (rA + 8 < M)
                C[(size_t)(rA + 8) * 64 + (col >> 1)] =
                    pack_half2(acc[mt][nt][2], acc[mt][nt][3]);
        }
    }

    // ---- fused projections (head == colgroup cw) ----
    {
#pragma unroll
        for (int v = 0; v < 4; v++) {
            if (v >= nv) break;
            const float* vv = fp.v[P][v];
            float p[4] = {0.f, 0.f, 0.f, 0.f};
#pragma unroll
            for (int mt = 0; mt < 2; mt++)
#pragma unroll
                for (int nt = 0; nt < 8; nt++) {
                    int col = cw * 64 + nt * 8 + (tig << 1);
                    float2 vvc = *(const float2*)(vv + col);
                    p[2 * mt + 0] += acc[mt][nt][0] * vvc.x + acc[mt][nt][1] * vvc.y;
                    p[2 * mt + 1] += acc[mt][nt][2] * vvc.x + acc[mt][nt][3] * vvc.y;
                }
#pragma unroll
            for (int j = 0; j < 4; j++) {
                p[j] += __shfl_xor_sync(0xffffffffu, p[j], 1);
                p[j] += __shfl_xor_sync(0xffffffffu, p[j], 2);
            }
            if (tig == 0) {
#pragma unroll
                for (int j = 0; j < 4; j++) {
                    int row = r0 + j * 8;
                    if (row < M)
                        projOut[((size_t)v * M + row) * 2 + cw] = p[j];
                }
            }
        }
    }
}

// ---------------------------------------------------------------------------
// mma_score: score[blockIdx.y] += sum q[n]*tanh((relu(A_y)@Wk + bk)[m,n])
// single-pass bf16, warp tile 32x64. (A inputs o0/o1 stay fp32.)
// ---------------------------------------------------------------------------
__global__ __launch_bounds__(256) void mma_score_kernel(
    const float* __restrict__ Aa, const float* __restrict__ Ab,
    const float* __restrict__ W, const float* __restrict__ bias,
    const float* __restrict__ q, int M, double* __restrict__ outScore)
{
    __shared__ uint32_t As[128 * 16];
    __shared__ uint32_t Bs[128 * 16];
    __shared__ float red[8];
    const float* A = (blockIdx.y == 0) ? Aa : Ab;
    const int tid = threadIdx.x;
    const int w   = tid >> 5, lane = tid & 31;
    const int gid = lane >> 2, tig = lane & 3;
    const int rw  = w >> 1, cw = w & 1;
    const int m0  = blockIdx.x * 128;

    float acc[2][8][4];
#pragma unroll
    for (int mt = 0; mt < 2; mt++)
#pragma unroll
        for (int i = 0; i < 8; i++)
#pragma unroll
            for (int j = 0; j < 4; j++) acc[mt][i][j] = 0.f;

    for (int kc = 0; kc < 128; kc += 32) {
        for (int i = tid; i < 1024; i += 256) {
            int r   = i >> 3;
            int c4  = (i & 7) << 2;
            int kp0 = c4 >> 1;
            float4 v = make_float4(0.f, 0.f, 0.f, 0.f);
            if (m0 + r < M)
                v = *(const float4*)(A + (size_t)(m0 + r) * 128 + kc + c4);
            int rot = (r & 7) << 1;
            As[r * 16 + ((kp0 + rot) & 15)] =
                pack_bf16x2(fmaxf(v.x, 0.f), fmaxf(v.y, 0.f));
            As[r * 16 + ((kp0 + 1 + rot) & 15)] =
                pack_bf16x2(fmaxf(v.z, 0.f), fmaxf(v.w, 0.f));
        }
        for (int i = tid; i < 2048; i += 256) {
            int n = i & 127, kp = i >> 7;
            float x0 = W[(size_t)(kc + 2 * kp) * 128 + n];
            float x1 = W[(size_t)(kc + 2 * kp + 1) * 128 + n];
            Bs[n * 16 + ((kp + ((n & 7) << 1)) & 15)] = pack_bf16x2(x0, x1);
        }
        __syncthreads();

#pragma unroll
        for (int ks = 0; ks < 2; ks++) {
            int base = ks * 8;
            int rot = gid << 1;
            uint32_t a[2][4];
#pragma unroll
            for (int mt = 0; mt < 2; mt++) {
                int ra = rw * 32 + mt * 16 + gid;
                a[mt][0] = As[ra * 16 + ((base + tig + rot) & 15)];
                a[mt][1] = As[(ra + 8) * 16 + ((base + tig + rot) & 15)];
                a[mt][2] = As[ra * 16 + ((base + 4 + tig + rot) & 15)];
                a[mt][3] = As[(ra + 8) * 16 + ((base + 4 + tig + rot) & 15)];
            }
#pragma unroll
            for (int nt = 0; nt < 8; nt++) {
                int n = cw * 64 + nt * 8 + gid;
                uint32_t b0 = Bs[n * 16 + ((base + tig + rot) & 15)];
                uint32_t b1 = Bs[n * 16 + ((base + 4 + tig + rot) & 15)];
#pragma unroll
                for (int mt = 0; mt < 2; mt++)
                    mma16(acc[mt][nt], a[mt][0], a[mt][1], a[mt][2], a[mt][3], b0, b1);
            }
        }
        __syncthreads();
    }

    float local = 0.f;
    int r0 = m0 + rw * 32 + gid;
#pragma unroll
    for (int mt = 0; mt < 2; mt++) {
        int rA = r0 + mt * 16;
#pragma unroll
        for (int nt = 0; nt < 8; nt++) {
            int col = cw * 64 + nt * 8 + (tig << 1);
            float2 b2 = *(const float2*)(bias + col);
            float2 q2 = *(const float2*)(q + col);
            if (rA < M) {
                local += q2.x * tanhf(acc[mt][nt][0] + b2.x);
                local += q2.y * tanhf(acc[mt][nt][1] + b2.y);
            }
            if (rA + 8 < M) {
                local += q2.x * tanhf(acc[mt][nt][2] + b2.x);
                local += q2.y * tanhf(acc[mt][nt][3] + b2.y);
            }
        }
    }
#pragma unroll
    for (int o = 16; o > 0; o >>= 1)
        local += __shfl_xor_sync(0xffffffffu, local, o);
    if (lane == 0) red[w] = local;
    __syncthreads();
    if (tid == 0) {
        double s = 0.0;
        for (int i = 0; i < 8; i++) s += (double)red[i];
        atomicAdd(outScore + blockIdx.y, s);
    }
}

// ---------------------------------------------------------------------------
// CSR build
// ---------------------------------------------------------------------------
__global__ __launch_bounds__(256) void hist_kernel(
    const int* d0, const int* d1, const int* d2,
    int E0, int E1, int E2, int* __restrict__ cnt)
{
    int t = blockIdx.y;
    const int* d = t == 0 ? d0 : (t == 1 ? d1 : d2);
    int E = t == 0 ? E0 : (t == 1 ? E1 : E2);
    int e = blockIdx.x * blockDim.x + threadIdx.x;
    if (e < E) atomicAdd(cnt + t * MAXNO + d[e], 1);
}

__global__ __launch_bounds__(256) void blocksum_kernel(
    const int* __restrict__ cnt, int* __restrict__ bsum,
    int N0, int N1, int N2)
{
    int t = blockIdx.y, b = blockIdx.x;
    int N = t == 0 ? N0 : (t == 1 ? N1 : N2);
    int base = b * 1024;
    int ssum = 0;
    for (int i = threadIdx.x; i < 1024; i += 256) {
        int idx = base + i;
        if (idx < N) ssum += cnt[t * MAXNO + idx];
    }
    __shared__ int red[256];
    red[threadIdx.x] = ssum; __syncthreads();
    for (int o = 128; o > 0; o >>= 1) {
        if (threadIdx.x < o) red[threadIdx.x] += red[threadIdx.x + o];
        __syncthreads();
    }
    if (threadIdx.x == 0) bsum[t * NBMAX + b] = red[0];
}

__global__ __launch_bounds__(128) void scanb_kernel(
    int* __restrict__ bsum, int* __restrict__ rowptr,
    int N0, int N1, int N2, int E0, int E1, int E2)
{
    __shared__ int sm[NBMAX];
    int tid = threadIdx.x;
    for (int t = 0; t < 3; t++) {
        int v = bsum[t * NBMAX + tid];
        sm[tid] = v; __syncthreads();
        for (int o = 1; o < NBMAX; o <<= 1) {
            int y = (tid >= o) ? sm[tid - o] : 0;
            __syncthreads();
            sm[tid] += y;
            __syncthreads();
        }
        bsum[t * NBMAX + tid] = sm[tid] - v;
        __syncthreads();
    }
    if (tid == 0) {
        rowptr[0 * (MAXNO + 1) + N0] = E0;
        rowptr[1 * (MAXNO + 1) + N1] = E1;
        rowptr[2 * (MAXNO + 1) + N2] = E2;
    }
}

__global__ __launch_bounds__(256) void scanc_kernel(
    int* __restrict__ cnt, const int* __restrict__ bsum,
    int* __restrict__ rowptr, int N0, int N1, int N2)
{
    int t = blockIdx.y, b = blockIdx.x;
    int N = t == 0 ? N0 : (t == 1 ? N1 : N2);
    int tid = threadIdx.x;
    int idx0 = b * 1024 + tid * 4;
    int c[4]; int ssum = 0;
#pragma unroll
    for (int j = 0; j < 4; j++) {
        int idx = idx0 + j;
        c[j] = (idx < N) ? cnt[t * MAXNO + idx] : 0;
        if (idx < N) cnt[t * MAXNO + idx] = 0;
        ssum += c[j];
    }
    __shared__ int sm[256];
    sm[tid] = ssum; __syncthreads();
    for (int o = 1; o < 256; o <<= 1) {
        int y = (tid >= o) ? sm[tid - o] : 0;
        __syncthreads();
        sm[tid] += y;
        __syncthreads();
    }
    int off = bsum[t * NBMAX + b] + (tid > 0 ? sm[tid - 1] : 0);
#pragma unroll
    for (int j = 0; j < 4; j++) {
        int idx = idx0 + j;
        if (idx < N) rowptr[t * (MAXNO + 1) + idx] = off;
        off += c[j];
    }
}

__global__ __launch_bounds__(256) void scatter_kernel(
    const int* s0, const int* d0, const int* s1, const int* d1,
    const int* s2, const int* d2, int E0, int E1, int E2,
    const int* __restrict__ rowptr, int* __restrict__ cur,
    int* __restrict__ csrc)
{
    int t = blockIdx.y;
    const int* s = t == 0 ? s0 : (t == 1 ? s1 : s2);
    const int* d = t == 0 ? d0 : (t == 1 ? d1 : d2);
    int E = t == 0 ? E0 : (t == 1 ? E1 : E2);
    int e = blockIdx.x * blockDim.x + threadIdx.x;
    if (e >= E) return;
    int dn = d[e];
    int pos = rowptr[t * (MAXNO + 1) + dn] + atomicAdd(cur + t * MAXNO + dn, 1);
    csrc[t * MAXE + pos] = s[e];
}

// ---------------------------------------------------------------------------
// Fused edge kernel: warp per dst node. deg<=32 fast path caches sn/e0/e1.
// h rows are half2 (64 words); lane loads uint2 = 4 halves = its 4 cols.
// ---------------------------------------------------------------------------
__global__ __launch_bounds__(256) void edge_fused_kernel(CsrBatch cb)
{
    int t = blockIdx.y;
    int node = (blockIdx.x * 256 + threadIdx.x) >> 5;
    if (node >= cb.N[t]) return;
    int lane = threadIdx.x & 31;
    const int* rp = cb.rowptr[t];
    int beg = rp[node], end = rp[node + 1];
    int deg = end - beg;
    const float2* ps = (const float2*)cb.psrc[t];
    float2 pdv = ((const float2*)cb.pdst[t])[node];
    int head = lane >> 4;
    const uint32_t* hsrc = cb.hsrc[t];

    int sn0 = 0; float ce0 = 0.f, ce1 = 0.f;
    {
        int i = beg + lane;
        if (i < end) {
            sn0 = cb.csrc[t][i];
            float2 p = ps[sn0];
            float a0 = p.x + pdv.x; a0 = a0 > 0.f ? a0 : 0.2f * a0;
            float a1 = p.y + pdv.y; a1 = a1 > 0.f ? a1 : 0.2f * a1;
            ce0 = expf(a0); ce1 = expf(a1);
        }
    }
    float s0 = ce0, s1 = ce1;
#pragma unroll
    for (int o = 16; o > 0; o >>= 1) {
        s0 += __shfl_xor_sync(0xffffffffu, s0, o);
        s1 += __shfl_xor_sync(0xffffffffu, s1, o);
    }
    for (int b = beg + 32; b < end; b += 32) {
        int i = b + lane;
        float e0 = 0.f, e1 = 0.f;
        if (i < end) {
            int sn = cb.csrc[t][i];
            float2 p = ps[sn];
            float a0 = p.x + pdv.x; a0 = a0 > 0.f ? a0 : 0.2f * a0;
            float a1 = p.y + pdv.y; a1 = a1 > 0.f ? a1 : 0.2f * a1;
            e0 = expf(a0); e1 = expf(a1);
        }
#pragma unroll
        for (int o = 16; o > 0; o >>= 1) {
            e0 += __shfl_xor_sync(0xffffffffu, e0, o);
            e1 += __shfl_xor_sync(0xffffffffu, e1, o);
        }
        s0 += e0; s1 += e1;
    }
    float inv = (head ? 1.f / (s1 + 1e-16f) : 1.f / (s0 + 1e-16f));

    float4 acc = make_float4(0.f, 0.f, 0.f, 0.f);
    {
        int cnt0 = deg < 32 ? deg : 32;
        for (int j = 0; j < cnt0; j++) {
            int   sj  = __shfl_sync(0xffffffffu, sn0, j);
            float e0j = __shfl_sync(0xffffffffu, ce0, j);
            float e1j = __shfl_sync(0xffffffffu, ce1, j);
            float wj  = (head ? e1j : e0j) * inv;
            uint2 hv = *(const uint2*)(hsrc + (size_t)sj * 64 + lane * 2);
            float2 f0 = __half22float2(*(__half2*)&hv.x);
            float2 f1 = __half22float2(*(__half2*)&hv.y);
            acc.x += wj * f0.x; acc.y += wj * f0.y;
            acc.z += wj * f1.x; acc.w += wj * f1.y;
        }
    }
    for (int b = beg + 32; b < end; b += 32) {
        int i = b + lane;
        int sn = 0; float e0 = 0.f, e1 = 0.f;
        if (i < end) {
            sn = cb.csrc[t][i];
            float2 p = ps[sn];
            float a0 = p.x + pdv.x; a0 = a0 > 0.f ? a0 : 0.2f * a0;
            float a1 = p.y + pdv.y; a1 = a1 > 0.f ? a1 : 0.2f * a1;
            e0 = expf(a0); e1 = expf(a1);
        }
        int cntj = end - b; if (cntj > 32) cntj = 32;
        for (int j = 0; j < cntj; j++) {
            int   sj  = __shfl_sync(0xffffffffu, sn, j);
            float e0j = __shfl_sync(0xffffffffu, e0, j);
            float e1j = __shfl_sync(0xffffffffu, e1, j);
            float wj  = (head ? e1j : e0j) * inv;
            uint2 hv = *(const uint2*)(hsrc + (size_t)sj * 64 + lane * 2);
            float2 f0 = __half22float2(*(__half2*)&hv.x);
            float2 f1 = __half22float2(*(__half2*)&hv.y);
            acc.x += wj * f0.x; acc.y += wj * f0.y;
            acc.z += wj * f1.x; acc.w += wj * f1.y;
        }
    }
    *(float4*)(cb.outp[t] + (size_t)node * 128 + lane * 4) = acc;
}

// ---------------------------------------------------------------------------
// Semantic attention tail + MLP
// ---------------------------------------------------------------------------
__global__ void softmax2_kernel(double* __restrict__ sc,
                                float* __restrict__ w, double invN)
{
    double s0 = sc[0] * invN, s1 = sc[1] * invN;
    double mx = s0 > s1 ? s0 : s1;
    double e0 = exp(s0 - mx), e1 = exp(s1 - mx);
    double sum = e0 + e1;
    w[0] = (float)(e0 / sum);
    w[1] = (float)(e1 / sum);
    sc[0] = 0.0; sc[1] = 0.0;    // re-zero for the next layer / replay
}

__global__ __launch_bounds__(256) void precompute_kernel(
    const float* __restrict__ Wl1, const float* __restrict__ bl1,
    const float* __restrict__ Wl2, const float* __restrict__ bl2,
    const float* __restrict__ Wl3, const float* __restrict__ bl3,
    float* __restrict__ W123, float* __restrict__ bfin,
    double* __restrict__ score)
{
    __shared__ float W23[256 * 8];
    __shared__ float t1s[128];
    int tid = threadIdx.x;
    if (tid < 2) score[tid] = 0.0;
    for (int i = tid; i < 2048; i += 256) {
        int r = i >> 3, j = i & 7;
        float a = 0.f;
        for (int c = 0; c < 128; c++) a += Wl2[r * 128 + c] * Wl3[c * 8 + j];
        W23[i] = a;
    }
    for (int n = tid; n < 128; n += 256) {
        float a = bl2[n];
        for (int k = 0; k < 256; k++) a += bl1[k] * Wl2[k * 128 + n];
        t1s[n] = a;
    }
    __syncthreads();
    for (int i = tid; i < 1024; i += 256) {
        int k = i >> 3, j = i & 7;
        float a = 0.f;
        for (int r = 0; r < 256; r++) a += Wl1[k * 256 + r] * W23[r * 8 + j];
        W123[i] = a;
    }
    if (tid < 8) {
        float a = bl3[tid];
        for (int c = 0; c < 128; c++) a += t1s[c] * Wl3[c * 8 + tid];
        bfin[tid] = a;
    }
}

__global__ __launch_bounds__(256) void mlp_final_kernel(
    const float* __restrict__ o0, const float* __restrict__ o1,
    const float* __restrict__ wbuf, const float* __restrict__ W123,
    const float* __restrict__ bfin, float* __restrict__ out, int No)
{
    __shared__ float Ws[128 * 8];
    __shared__ float bs[8];
    for (int i = threadIdx.x; i < 128 * 8; i += blockDim.x) Ws[i] = W123[i];
    if (threadIdx.x < 8) bs[threadIdx.x] = bfin[threadIdx.x];
    __syncthreads();
    float w0 = wbuf[0], w1 = wbuf[1];
    int gid = blockIdx.x * blockDim.x + threadIdx.x;
    int row = gid >> 3, j = gid & 7;
    if (row >= No) return;
    const float* r0 = o0 + (size_t)row * 128;
    const float* r1 = o1 + (size_t)row * 128;
    float acc = 0.f;
#pragma unroll
    for (int k = 0; k < 128; k += 4) {
        float4 a = *(const float4*)(r0 + k);
        float4 b = *(const float4*)(r1 + k);
        float x0 = w0 * fmaxf(a.x, 0.f) + w1 * fmaxf(b.x, 0.f);
        float x1 = w0 * fmaxf(a.y, 0.f) + w1 * fmaxf(b.y, 0.f);
        float x2 = w0 * fmaxf(a.z, 0.f) + w1 * fmaxf(b.z, 0.f);
        float x3 = w0 * fmaxf(a.w, 0.f) + w1 * fmaxf(b.w, 0.f);
        acc += x0 * Ws[(k + 0) * 8 + j];
        acc += x1 * Ws[(k + 1) * 8 + j];
        acc += x2 * Ws[(k + 2) * 8 + j];
        acc += x3 * Ws[(k + 3) * 8 + j];
    }
    float x = acc + bs[j];
    out[(size_t)row * 8 + j] = 1.f / (1.f + expf(-x));
}

// ---------------------------------------------------------------------------
// Host orchestration
// ---------------------------------------------------------------------------
static inline int ceil_div(int a, int b) { return (a + b - 1) / b; }

extern "C" void kernel_launch(void* const* d_in, const int* in_sizes, int n_in,
                              void* d_out, int out_size)
{
    const float* xo  = (const float*)d_in[0];
    const float* xa  = (const float*)d_in[1];
    const int*   eoo = (const int*)d_in[2];
    const int*   eoa = (const int*)d_in[3];
    const int*   eao = (const int*)d_in[4];
    const int No  = in_sizes[0] / 128;
    const int Na  = in_sizes[1] / 128;
    const int Eoo = in_sizes[2] / 2;
    const int Eoa = in_sizes[3] / 2;
    const int Eao = in_sizes[4] / 2;

    float *o0, *o1, *oa, *pobj, *patt, *w, *W123, *bfin;
    uint32_t *ho16, *ha16;
    int *cnt, *rowptr, *csrc, *bsum;
    double* score;
    cudaGetSymbolAddress((void**)&ho16,   g_ho16);
    cudaGetSymbolAddress((void**)&ha16,   g_ha16);
    cudaGetSymbolAddress((void**)&o0,     g_o0);
    cudaGetSymbolAddress((void**)&o1,     g_o1);
    cudaGetSymbolAddress((void**)&oa,     g_oa);
    cudaGetSymbolAddress((void**)&pobj,   g_pobj);
    cudaGetSymbolAddress((void**)&patt,   g_patt);
    cudaGetSymbolAddress((void**)&score,  g_score);
    cudaGetSymbolAddress((void**)&w,      g_w);
    cudaGetSymbolAddress((void**)&W123,   g_W123);
    cudaGetSymbolAddress((void**)&bfin,   g_bfin);
    cudaGetSymbolAddress((void**)&cnt,    g_cnt);
    cudaGetSymbolAddress((void**)&rowptr, g_rowptr);
    cudaGetSymbolAddress((void**)&csrc,   g_csrc);
    cudaGetSymbolAddress((void**)&bsum,   g_bsum);

    const int FEAT_SMEM = 32768;
    cudaFuncSetAttribute(mma_feat2_kernel,
                         cudaFuncAttributeMaxDynamicSharedMemorySize, FEAT_SMEM);

    const int tilesNo = ceil_div(No, 128);
    const int maxE = (Eoo > Eao ? (Eoo > Eoa ? Eoo : Eoa) : (Eao > Eoa ? Eao : Eoa));

    // ---- CSR build (types: 0=oo, 1=ao, 2=oa) ----
    const int* dst0 = eoo + Eoo;
    const int* dst1 = eao + Eao;
    const int* dst2 = eoa + Eoa;
    cudaMemsetAsync(cnt, 0, 3 * MAXNO * sizeof(int));
    hist_kernel<<<dim3(ceil_div(maxE, 256), 3), 256>>>(
        dst0, dst1, dst2, Eoo, Eao, Eoa, cnt);
    blocksum_kernel<<<dim3(NBMAX, 3), 256>>>(cnt, bsum, No, No, Na);
    scanb_kernel<<<1, NBMAX>>>(bsum, rowptr, No, No, Na, Eoo, Eao, Eoa);
    scanc_kernel<<<dim3(ceil_div(No, 1024), 3), 256>>>(cnt, bsum, rowptr, No, No, Na);
    scatter_kernel<<<dim3(ceil_div(maxE, 256), 3), 256>>>(
        eoo, dst0, eao, dst1, eoa, dst2, Eoo, Eao, Eoa, rowptr, cnt, csrc);

    precompute_kernel<<<1, 256>>>(
        (const float*)d_in[23], (const float*)d_in[24], (const float*)d_in[25],
        (const float*)d_in[26], (const float*)d_in[27], (const float*)d_in[28],
        W123, bfin, score);

    for (int layer = 0; layer < 2; layer++) {
        const int base = 5 + 9 * layer;
        const float* Wo   = (const float*)d_in[base + 0];
        const float* bo   = (const float*)d_in[base + 1];
        const float* Wa   = (const float*)d_in[base + 2];
        const float* ba   = (const float*)d_in[base + 3];
        const float* asrc = (const float*)d_in[base + 4];
        const float* adst = (const float*)d_in[base + 5];
        const float* Wk   = (const float*)d_in[base + 6];
        const float* bk   = (const float*)d_in[base + 7];
        const float* q    = (const float*)d_in[base + 8];

        FeatPair fp;
        fp.wbuf = w;
        fp.W[0] = Wo; fp.bias[0] = bo; fp.C[0] = ho16; fp.proj[0] = pobj;
        fp.M[0] = No; fp.nv[0] = 4;
        fp.v[0][0] = asrc + 0;   fp.v[0][1] = asrc + 128;
        fp.v[0][2] = adst + 0;   fp.v[0][3] = adst + 256;
        fp.W[1] = Wa; fp.bias[1] = ba; fp.C[1] = ha16; fp.proj[1] = patt;
        fp.M[1] = Na; fp.nv[1] = 2;
        fp.v[1][0] = asrc + 256; fp.v[1][1] = adst + 128;
        fp.v[1][2] = asrc;       fp.v[1][3] = asrc;
        if (layer == 0) {
            fp.A[0] = xo; fp.A2[0] = xo; fp.mode[0] = 0;
            fp.A[1] = xa; fp.A2[1] = xa; fp.mode[1] = 0;
        } else {
            fp.A[0] = o0; fp.A2[0] = o1; fp.mode[0] = 2;
            fp.A[1] = oa; fp.A2[1] = oa; fp.mode[1] = 1;
        }
        mma_feat2_kernel<<<dim3(tilesNo, 2), 256, FEAT_SMEM>>>(fp);

        const int ntypes = (layer == 0) ? 3 : 2;

        CsrBatch cb;
        cb.csrc[0] = csrc;               cb.rowptr[0] = rowptr;
        cb.psrc[0] = pobj + 0;           cb.pdst[0] = pobj + (size_t)2 * No * 2;
        cb.hsrc[0] = ho16;               cb.outp[0] = o0;  cb.N[0] = No;
        cb.csrc[1] = csrc + MAXE;        cb.rowptr[1] = rowptr + (MAXNO + 1);
        cb.psrc[1] = patt + 0;           cb.pdst[1] = pobj + (size_t)3 * No * 2;
        cb.hsrc[1] = ha16;               cb.outp[1] = o1;  cb.N[1] = No;
        cb.csrc[2] = csrc + 2 * MAXE;    cb.rowptr[2] = rowptr + 2 * (MAXNO + 1);
        cb.psrc[2] = pobj + (size_t)1 * No * 2;
        cb.pdst[2] = patt + (size_t)1 * Na * 2;
        cb.hsrc[2] = ho16;               cb.outp[2] = oa;
        cb.N[2] = (layer == 0) ? Na : 0;

        edge_fused_kernel<<<dim3(ceil_div(No * 32, 256), ntypes), 256>>>(cb);

        mma_score_kernel<<<dim3(tilesNo, 2), 256>>>(o0, o1, Wk, bk, q, No, score);
        softmax2_kernel<<<1, 1>>>(score, w, 1.0 / (double)No);
    }

    mlp_final_kernel<<<ceil_div(No * 8, 256), 256>>>(
        o0, o1, w, W123, bfin, (float*)d_out, No);
}

// round 17
// speedup vs baseline: 3.0367x; 1.1154x over previous
#include <cuda_runtime.h>
#include <cuda_fp16.h>
#include <math.h>
#include <stdint.h>

// ============================================================================
// HAN: 2-layer heterogeneous GAT + semantic attention + collapsed MLP head.
// R17: o0/o1/oa also stored as fp16 half2 (edge_fused writes, score GEMM /
//      layer-2 GEMM / mlp_final reads all halve). Edge exp -> __expf.
// Else identical to R16 (fp16 h, bf16x2-split GEMMs, CSR edges).
// ============================================================================

#define MAXNO 100096
#define MAXNA 50048
#define MAXE  500224
#define NBMAX 128

__device__ uint32_t g_ho16[MAXNO * 64];   // h as half2, 64 words/row
__device__ uint32_t g_ha16[MAXNA * 64];
__device__ uint32_t g_o0[MAXNO * 64];     // o as half2
__device__ uint32_t g_o1[MAXNO * 64];
__device__ uint32_t g_oa[MAXNA * 64];
__device__ float  g_pobj[4 * MAXNO * 2];
__device__ float  g_patt[2 * MAXNA * 2];
__device__ double g_score[2];
__device__ float  g_w[2];
__device__ float  g_W123[128 * 8];
__device__ float  g_bfin[8];
// CSR scratch
__device__ int    g_cnt[3 * MAXNO];
__device__ int    g_rowptr[3 * (MAXNO + 1)];
__device__ int    g_csrc[3 * MAXE];
__device__ int    g_bsum[3 * NBMAX];

struct CsrBatch {
    const int*      csrc[3];
    const int*      rowptr[3];
    const float*    psrc[3];
    const float*    pdst[3];
    const uint32_t* hsrc[3];
    uint32_t*       outp[3];    // half2 output rows (64 words)
    int             N[3];
};

struct FeatPair {
    const float*    A[2];       // fp32 input (layer 0)
    const uint32_t* A16[2];     // half2 input (layer 1)
    const uint32_t* A16b[2];    // second half2 input (mode 2)
    const float*    W[2];
    const float*    bias[2];
    uint32_t*       C[2];       // half2 output
    float*          proj[2];
    const float*    v[2][4];
    const float*    wbuf;
    int             M[2];
    int             mode[2];    // 0 plain fp32, 1 relu fp16, 2 combine fp16
    int             nv[2];
};

// ---------------------------------------------------------------------------
// mma / packing helpers
// ---------------------------------------------------------------------------
__device__ __forceinline__ void mma16(float* c,
                                      uint32_t a0, uint32_t a1, uint32_t a2, uint32_t a3,
                                      uint32_t b0, uint32_t b1)
{
    asm volatile(
        "mma.sync.aligned.m16n8k16.row.col.f32.bf16.bf16.f32 "
        "{%0,%1,%2,%3}, {%4,%5,%6,%7}, {%8,%9}, {%0,%1,%2,%3};"
        : "+f"(c[0]), "+f"(c[1]), "+f"(c[2]), "+f"(c[3])
        : "r"(a0), "r"(a1), "r"(a2), "r"(a3), "r"(b0), "r"(b1));
}

__device__ __forceinline__ float bf16_hi(float x) {
    uint32_t u = __float_as_uint(x);
    u = (u + 0x7FFFu + ((u >> 16) & 1u)) & 0xFFFF0000u;
    return __uint_as_float(u);
}
__device__ __forceinline__ uint32_t pack_hi16(float x, float y) {
    return __byte_perm(__float_as_uint(x), __float_as_uint(y), 0x7632);
}
__device__ __forceinline__ uint32_t pack_bf16x2(float x, float y) {
    uint32_t r;
    asm("cvt.rn.bf16x2.f32 %0, %1, %2;" : "=r"(r) : "f"(y), "f"(x));
    return r;
}
__device__ __forceinline__ uint32_t pack_half2(float lo, float hi) {
    uint32_t r;
    asm("cvt.rn.f16x2.f32 %0, %1, %2;" : "=r"(r) : "f"(hi), "f"(lo));
    return r;
}
__device__ __forceinline__ float4 unpack_h4(uint2 hv) {
    float2 f0 = __half22float2(*(__half2*)&hv.x);
    float2 f1 = __half22float2(*(__half2*)&hv.y);
    return make_float4(f0.x, f0.y, f1.x, f1.y);
}

// ---------------------------------------------------------------------------
// mma_feat2: both feature GEMMs of a layer in one launch; grid.y = problem.
// C(half2) = op(A)[M,128] @ W[128,128] + bias, bf16x2 split, fused projections.
// ---------------------------------------------------------------------------
__global__ __launch_bounds__(256) void mma_feat2_kernel(FeatPair fp)
{
    const int P = blockIdx.y;
    const int M = fp.M[P];
    const int m0 = blockIdx.x * 128;
    if (m0 >= M) return;

    extern __shared__ uint2 usm[];
    uint2* Asm = usm;
    uint2* Bsm = usm + 2048;
    const int tid  = threadIdx.x;
    const int w    = tid >> 5, lane = tid & 31;
    const int gid  = lane >> 2, tig = lane & 3;
    const int rw   = w >> 1, cw = w & 1;

    const float* __restrict__ W    = fp.W[P];
    const float* __restrict__ bias = fp.bias[P];
    uint32_t* __restrict__ C       = fp.C[P];
    float* __restrict__ projOut    = fp.proj[P];
    const int mode = fp.mode[P];
    const int nv   = fp.nv[P];

    float cw0 = 0.f, cw1 = 0.f;
    if (mode == 2) { cw0 = fp.wbuf[0]; cw1 = fp.wbuf[1]; }

    float acc[2][8][4];
#pragma unroll
    for (int mt = 0; mt < 2; mt++)
#pragma unroll
        for (int i = 0; i < 8; i++)
#pragma unroll
            for (int j = 0; j < 4; j++) acc[mt][i][j] = 0.f;

    for (int kc = 0; kc < 128; kc += 32) {
        for (int i = tid; i < 1024; i += 256) {
            int r   = i >> 3;
            int c4  = (i & 7) << 2;
            int kp0 = c4 >> 1;
            float4 v = make_float4(0.f, 0.f, 0.f, 0.f);
            if (m0 + r < M) {
                if (mode == 0) {
                    v = *(const float4*)(fp.A[P] + (size_t)(m0 + r) * 128 + kc + c4);
                } else if (mode == 1) {
                    uint2 hv = *(const uint2*)(fp.A16[P] + (size_t)(m0 + r) * 64 + ((kc + c4) >> 1));
                    v = unpack_h4(hv);
                    v.x = fmaxf(v.x, 0.f); v.y = fmaxf(v.y, 0.f);
                    v.z = fmaxf(v.z, 0.f); v.w = fmaxf(v.w, 0.f);
                } else {
                    uint2 hv = *(const uint2*)(fp.A16[P] + (size_t)(m0 + r) * 64 + ((kc + c4) >> 1));
                    uint2 hu = *(const uint2*)(fp.A16b[P] + (size_t)(m0 + r) * 64 + ((kc + c4) >> 1));
                    float4 a = unpack_h4(hv), b = unpack_h4(hu);
                    v.x = cw0 * fmaxf(a.x, 0.f) + cw1 * fmaxf(b.x, 0.f);
                    v.y = cw0 * fmaxf(a.y, 0.f) + cw1 * fmaxf(b.y, 0.f);
                    v.z = cw0 * fmaxf(a.z, 0.f) + cw1 * fmaxf(b.z, 0.f);
                    v.w = cw0 * fmaxf(a.w, 0.f) + cw1 * fmaxf(b.w, 0.f);
                }
            }
            float hx = bf16_hi(v.x), hy = bf16_hi(v.y);
            float hz = bf16_hi(v.z), hw = bf16_hi(v.w);
            uint2 w0, w1;
            w0.x = pack_hi16(hx, hy);
            w0.y = pack_bf16x2(v.x - hx, v.y - hy);
            w1.x = pack_hi16(hz, hw);
            w1.y = pack_bf16x2(v.z - hz, v.w - hw);
            int rot = (r & 7) << 1;
            Asm[r * 16 + ((kp0 + rot) & 15)]     = w0;
            Asm[r * 16 + ((kp0 + 1 + rot) & 15)] = w1;
        }
        for (int i = tid; i < 2048; i += 256) {
            int n = i & 127, kp = i >> 7;
            float x0 = W[(size_t)(kc + 2 * kp) * 128 + n];
            float x1 = W[(size_t)(kc + 2 * kp + 1) * 128 + n];
            float h0 = bf16_hi(x0), h1 = bf16_hi(x1);
            uint2 wv;
            wv.x = pack_hi16(h0, h1);
            wv.y = pack_bf16x2(x0 - h0, x1 - h1);
            Bsm[n * 16 + ((kp + ((n & 7) << 1)) & 15)] = wv;
        }
        __syncthreads();

#pragma unroll
        for (int ks = 0; ks < 2; ks++) {
            int base = ks * 8;
            int rot = gid << 1;
            uint32_t ah[2][4], al[2][4];
#pragma unroll
            for (int mt = 0; mt < 2; mt++) {
                int ra = rw * 32 + mt * 16 + gid;
                uint2 u0 = Asm[ra * 16 + ((base + tig + rot) & 15)];
                uint2 u1 = Asm[(ra + 8) * 16 + ((base + tig + rot) & 15)];
                uint2 u2 = Asm[ra * 16 + ((base + 4 + tig + rot) & 15)];
                uint2 u3 = Asm[(ra + 8) * 16 + ((base + 4 + tig + rot) & 15)];
                ah[mt][0] = u0.x; al[mt][0] = u0.y;
                ah[mt][1] = u1.x; al[mt][1] = u1.y;
                ah[mt][2] = u2.x; al[mt][2] = u2.y;
                ah[mt][3] = u3.x; al[mt][3] = u3.y;
            }
#pragma unroll
            for (int nt = 0; nt < 8; nt++) {
                int n = cw * 64 + nt * 8 + gid;
                uint2 b0 = Bsm[n * 16 + ((base + tig + rot) & 15)];
                uint2 b1 = Bsm[n * 16 + ((base + 4 + tig + rot) & 15)];
#pragma unroll
                for (int mt = 0; mt < 2; mt++) {
                    mma16(acc[mt][nt], ah[mt][0], ah[mt][1], ah[mt][2], ah[mt][3], b0.x, b1.x);
                    mma16(acc[mt][nt], ah[mt][0], ah[mt][1], ah[mt][2], ah[mt][3], b0.y, b1.y);
                    mma16(acc[mt][nt], al[mt][0], al[mt][1], al[mt][2], al[mt][3], b0.x, b1.x);
                }
            }
        }
        __syncthreads();
    }

    // ---- epilogue: bias + fp16 store ----
    int r0 = m0 + rw * 32 + gid;
#pragma unroll
    for (int mt = 0; mt < 2; mt++) {
        int rA = r0 + mt * 16;
#pragma unroll
        for (int nt = 0; nt < 8; nt++) {
            int col = cw * 64 + nt * 8 + (tig << 1);
            float2 b2 = *(const float2*)(bias + col);
            acc[mt][nt][0] += b2.x; acc[mt][nt][1] += b2.y;
            acc[mt][nt][2] += b2.x; acc[mt][nt][3] += b2.y;
            if (rA < M)
                C[(size_t)rA * 64 + (col >> 1)] =
                    pack_half2(acc[mt][nt][0], acc[mt][nt][1]);
            if (rA + 8 < M)
                C[(size_t)(rA + 8) * 64 + (col >> 1)] =
                    pack_half2(acc[mt][nt][2], acc[mt][nt][3]);
        }
    }

    // ---- fused projections (head == colgroup cw) ----
    {
#pragma unroll
        for (int v = 0; v < 4; v++) {
            if (v >= nv) break;
            const float* vv = fp.v[P][v];
            float p[4] = {0.f, 0.f, 0.f, 0.f};
#pragma unroll
            for (int mt = 0; mt < 2; mt++)
#pragma unroll
                for (int nt = 0; nt < 8; nt++) {
                    int col = cw * 64 + nt * 8 + (tig << 1);
                    float2 vvc = *(const float2*)(vv + col);
                    p[2 * mt + 0] += acc[mt][nt][0] * vvc.x + acc[mt][nt][1] * vvc.y;
                    p[2 * mt + 1] += acc[mt][nt][2] * vvc.x + acc[mt][nt][3] * vvc.y;
                }
#pragma unroll
            for (int j = 0; j < 4; j++) {
                p[j] += __shfl_xor_sync(0xffffffffu, p[j], 1);
                p[j] += __shfl_xor_sync(0xffffffffu, p[j], 2);
            }
            if (tig == 0) {
#pragma unroll
                for (int j = 0; j < 4; j++) {
                    int row = r0 + j * 8;
                    if (row < M)
                        projOut[((size_t)v * M + row) * 2 + cw] = p[j];
                }
            }
        }
    }
}

// ---------------------------------------------------------------------------
// mma_score: score[blockIdx.y] += sum q[n]*tanh((relu(A_y)@Wk + bk)[m,n])
// A inputs are half2 o buffers. single-pass bf16, warp tile 32x64.
// ---------------------------------------------------------------------------
__global__ __launch_bounds__(256) void mma_score_kernel(
    const uint32_t* __restrict__ Aa, const uint32_t* __restrict__ Ab,
    const float* __restrict__ W, const float* __restrict__ bias,
    const float* __restrict__ q, int M, double* __restrict__ outScore)
{
    __shared__ uint32_t As[128 * 16];
    __shared__ uint32_t Bs[128 * 16];
    __shared__ float red[8];
    const uint32_t* A = (blockIdx.y == 0) ? Aa : Ab;
    const int tid = threadIdx.x;
    const int w   = tid >> 5, lane = tid & 31;
    const int gid = lane >> 2, tig = lane & 3;
    const int rw  = w >> 1, cw = w & 1;
    const int m0  = blockIdx.x * 128;

    float acc[2][8][4];
#pragma unroll
    for (int mt = 0; mt < 2; mt++)
#pragma unroll
        for (int i = 0; i < 8; i++)
#pragma unroll
            for (int j = 0; j < 4; j++) acc[mt][i][j] = 0.f;

    for (int kc = 0; kc < 128; kc += 32) {
        for (int i = tid; i < 1024; i += 256) {
            int r   = i >> 3;
            int c4  = (i & 7) << 2;
            int kp0 = c4 >> 1;
            float4 v = make_float4(0.f, 0.f, 0.f, 0.f);
            if (m0 + r < M) {
                uint2 hv = *(const uint2*)(A + (size_t)(m0 + r) * 64 + ((kc + c4) >> 1));
                v = unpack_h4(hv);
            }
            int rot = (r & 7) << 1;
            As[r * 16 + ((kp0 + rot) & 15)] =
                pack_bf16x2(fmaxf(v.x, 0.f), fmaxf(v.y, 0.f));
            As[r * 16 + ((kp0 + 1 + rot) & 15)] =
                pack_bf16x2(fmaxf(v.z, 0.f), fmaxf(v.w, 0.f));
        }
        for (int i = tid; i < 2048; i += 256) {
            int n = i & 127, kp = i >> 7;
            float x0 = W[(size_t)(kc + 2 * kp) * 128 + n];
            float x1 = W[(size_t)(kc + 2 * kp + 1) * 128 + n];
            Bs[n * 16 + ((kp + ((n & 7) << 1)) & 15)] = pack_bf16x2(x0, x1);
        }
        __syncthreads();

#pragma unroll
        for (int ks = 0; ks < 2; ks++) {
            int base = ks * 8;
            int rot = gid << 1;
            uint32_t a[2][4];
#pragma unroll
            for (int mt = 0; mt < 2; mt++) {
                int ra = rw * 32 + mt * 16 + gid;
                a[mt][0] = As[ra * 16 + ((base + tig + rot) & 15)];
                a[mt][1] = As[(ra + 8) * 16 + ((base + tig + rot) & 15)];
                a[mt][2] = As[ra * 16 + ((base + 4 + tig + rot) & 15)];
                a[mt][3] = As[(ra + 8) * 16 + ((base + 4 + tig + rot) & 15)];
            }
#pragma unroll
            for (int nt = 0; nt < 8; nt++) {
                int n = cw * 64 + nt * 8 + gid;
                uint32_t b0 = Bs[n * 16 + ((base + tig + rot) & 15)];
                uint32_t b1 = Bs[n * 16 + ((base + 4 + tig + rot) & 15)];
#pragma unroll
                for (int mt = 0; mt < 2; mt++)
                    mma16(acc[mt][nt], a[mt][0], a[mt][1], a[mt][2], a[mt][3], b0, b1);
            }
        }
        __syncthreads();
    }

    float local = 0.f;
    int r0 = m0 + rw * 32 + gid;
#pragma unroll
    for (int mt = 0; mt < 2; mt++) {
        int rA = r0 + mt * 16;
#pragma unroll
        for (int nt = 0; nt < 8; nt++) {
            int col = cw * 64 + nt * 8 + (tig << 1);
            float2 b2 = *(const float2*)(bias + col);
            float2 q2 = *(const float2*)(q + col);
            if (rA < M) {
                local += q2.x * tanhf(acc[mt][nt][0] + b2.x);
                local += q2.y * tanhf(acc[mt][nt][1] + b2.y);
            }
            if (rA + 8 < M) {
                local += q2.x * tanhf(acc[mt][nt][2] + b2.x);
                local += q2.y * tanhf(acc[mt][nt][3] + b2.y);
            }
        }
    }
#pragma unroll
    for (int o = 16; o > 0; o >>= 1)
        local += __shfl_xor_sync(0xffffffffu, local, o);
    if (lane == 0) red[w] = local;
    __syncthreads();
    if (tid == 0) {
        double s = 0.0;
        for (int i = 0; i < 8; i++) s += (double)red[i];
        atomicAdd(outScore + blockIdx.y, s);
    }
}

// ---------------------------------------------------------------------------
// CSR build
// ---------------------------------------------------------------------------
__global__ __launch_bounds__(256) void hist_kernel(
    const int* d0, const int* d1, const int* d2,
    int E0, int E1, int E2, int* __restrict__ cnt)
{
    int t = blockIdx.y;
    const int* d = t == 0 ? d0 : (t == 1 ? d1 : d2);
    int E = t == 0 ? E0 : (t == 1 ? E1 : E2);
    int e = blockIdx.x * blockDim.x + threadIdx.x;
    if (e < E) atomicAdd(cnt + t * MAXNO + d[e], 1);
}

__global__ __launch_bounds__(256) void blocksum_kernel(
    const int* __restrict__ cnt, int* __restrict__ bsum,
    int N0, int N1, int N2)
{
    int t = blockIdx.y, b = blockIdx.x;
    int N = t == 0 ? N0 : (t == 1 ? N1 : N2);
    int base = b * 1024;
    int ssum = 0;
    for (int i = threadIdx.x; i < 1024; i += 256) {
        int idx = base + i;
        if (idx < N) ssum += cnt[t * MAXNO + idx];
    }
    __shared__ int red[256];
    red[threadIdx.x] = ssum; __syncthreads();
    for (int o = 128; o > 0; o >>= 1) {
        if (threadIdx.x < o) red[threadIdx.x] += red[threadIdx.x + o];
        __syncthreads();
    }
    if (threadIdx.x == 0) bsum[t * NBMAX + b] = red[0];
}

__global__ __launch_bounds__(128) void scanb_kernel(
    int* __restrict__ bsum, int* __restrict__ rowptr,
    int N0, int N1, int N2, int E0, int E1, int E2)
{
    __shared__ int sm[NBMAX];
    int tid = threadIdx.x;
    for (int t = 0; t < 3; t++) {
        int v = bsum[t * NBMAX + tid];
        sm[tid] = v; __syncthreads();
        for (int o = 1; o < NBMAX; o <<= 1) {
            int y = (tid >= o) ? sm[tid - o] : 0;
            __syncthreads();
            sm[tid] += y;
            __syncthreads();
        }
        bsum[t * NBMAX + tid] = sm[tid] - v;
        __syncthreads();
    }
    if (tid == 0) {
        rowptr[0 * (MAXNO + 1) + N0] = E0;
        rowptr[1 * (MAXNO + 1) + N1] = E1;
        rowptr[2 * (MAXNO + 1) + N2] = E2;
    }
}

__global__ __launch_bounds__(256) void scanc_kernel(
    int* __restrict__ cnt, const int* __restrict__ bsum,
    int* __restrict__ rowptr, int N0, int N1, int N2)
{
    int t = blockIdx.y, b = blockIdx.x;
    int N = t == 0 ? N0 : (t == 1 ? N1 : N2);
    int tid = threadIdx.x;
    int idx0 = b * 1024 + tid * 4;
    int c[4]; int ssum = 0;
#pragma unroll
    for (int j = 0; j < 4; j++) {
        int idx = idx0 + j;
        c[j] = (idx < N) ? cnt[t * MAXNO + idx] : 0;
        if (idx < N) cnt[t * MAXNO + idx] = 0;
        ssum += c[j];
    }
    __shared__ int sm[256];
    sm[tid] = ssum; __syncthreads();
    for (int o = 1; o < 256; o <<= 1) {
        int y = (tid >= o) ? sm[tid - o] : 0;
        __syncthreads();
        sm[tid] += y;
        __syncthreads();
    }
    int off = bsum[t * NBMAX + b] + (tid > 0 ? sm[tid - 1] : 0);
#pragma unroll
    for (int j = 0; j < 4; j++) {
        int idx = idx0 + j;
        if (idx < N) rowptr[t * (MAXNO + 1) + idx] = off;
        off += c[j];
    }
}

__global__ __launch_bounds__(256) void scatter_kernel(
    const int* s0, const int* d0, const int* s1, const int* d1,
    const int* s2, const int* d2, int E0, int E1, int E2,
    const int* __restrict__ rowptr, int* __restrict__ cur,
    int* __restrict__ csrc)
{
    int t = blockIdx.y;
    const int* s = t == 0 ? s0 : (t == 1 ? s1 : s2);
    const int* d = t == 0 ? d0 : (t == 1 ? d1 : d2);
    int E = t == 0 ? E0 : (t == 1 ? E1 : E2);
    int e = blockIdx.x * blockDim.x + threadIdx.x;
    if (e >= E) return;
    int dn = d[e];
    int pos = rowptr[t * (MAXNO + 1) + dn] + atomicAdd(cur + t * MAXNO + dn, 1);
    csrc[t * MAXE + pos] = s[e];
}

// ---------------------------------------------------------------------------
// Fused edge kernel: warp per dst node; fp16 h gather, fp16 o store.
// ---------------------------------------------------------------------------
__global__ __launch_bounds__(256) void edge_fused_kernel(CsrBatch cb)
{
    int t = blockIdx.y;
    int node = (blockIdx.x * 256 + threadIdx.x) >> 5;
    if (node >= cb.N[t]) return;
    int lane = threadIdx.x & 31;
    const int* rp = cb.rowptr[t];
    int beg = rp[node], end = rp[node + 1];
    int deg = end - beg;
    const float2* ps = (const float2*)cb.psrc[t];
    float2 pdv = ((const float2*)cb.pdst[t])[node];
    int head = lane >> 4;
    const uint32_t* hsrc = cb.hsrc[t];

    int sn0 = 0; float ce0 = 0.f, ce1 = 0.f;
    {
        int i = beg + lane;
        if (i < end) {
            sn0 = cb.csrc[t][i];
            float2 p = ps[sn0];
            float a0 = p.x + pdv.x; a0 = a0 > 0.f ? a0 : 0.2f * a0;
            float a1 = p.y + pdv.y; a1 = a1 > 0.f ? a1 : 0.2f * a1;
            ce0 = __expf(a0); ce1 = __expf(a1);
        }
    }
    float s0 = ce0, s1 = ce1;
#pragma unroll
    for (int o = 16; o > 0; o >>= 1) {
        s0 += __shfl_xor_sync(0xffffffffu, s0, o);
        s1 += __shfl_xor_sync(0xffffffffu, s1, o);
    }
    for (int b = beg + 32; b < end; b += 32) {
        int i = b + lane;
        float e0 = 0.f, e1 = 0.f;
        if (i < end) {
            int sn = cb.csrc[t][i];
            float2 p = ps[sn];
            float a0 = p.x + pdv.x; a0 = a0 > 0.f ? a0 : 0.2f * a0;
            float a1 = p.y + pdv.y; a1 = a1 > 0.f ? a1 : 0.2f * a1;
            e0 = __expf(a0); e1 = __expf(a1);
        }
#pragma unroll
        for (int o = 16; o > 0; o >>= 1) {
            e0 += __shfl_xor_sync(0xffffffffu, e0, o);
            e1 += __shfl_xor_sync(0xffffffffu, e1, o);
        }
        s0 += e0; s1 += e1;
    }
    float inv = (head ? 1.f / (s1 + 1e-16f) : 1.f / (s0 + 1e-16f));

    float4 acc = make_float4(0.f, 0.f, 0.f, 0.f);
    {
        int cnt0 = deg < 32 ? deg : 32;
        for (int j = 0; j < cnt0; j++) {
            int   sj  = __shfl_sync(0xffffffffu, sn0, j);
            float e0j = __shfl_sync(0xffffffffu, ce0, j);
            float e1j = __shfl_sync(0xffffffffu, ce1, j);
            float wj  = (head ? e1j : e0j) * inv;
            float4 v = unpack_h4(*(const uint2*)(hsrc + (size_t)sj * 64 + lane * 2));
            acc.x += wj * v.x; acc.y += wj * v.y;
            acc.z += wj * v.z; acc.w += wj * v.w;
        }
    }
    for (int b = beg + 32; b < end; b += 32) {
        int i = b + lane;
        int sn = 0; float e0 = 0.f, e1 = 0.f;
        if (i < end) {
            sn = cb.csrc[t][i];
            float2 p = ps[sn];
            float a0 = p.x + pdv.x; a0 = a0 > 0.f ? a0 : 0.2f * a0;
            float a1 = p.y + pdv.y; a1 = a1 > 0.f ? a1 : 0.2f * a1;
            e0 = __expf(a0); e1 = __expf(a1);
        }
        int cntj = end - b; if (cntj > 32) cntj = 32;
        for (int j = 0; j < cntj; j++) {
            int   sj  = __shfl_sync(0xffffffffu, sn, j);
            float e0j = __shfl_sync(0xffffffffu, e0, j);
            float e1j = __shfl_sync(0xffffffffu, e1, j);
            float wj  = (head ? e1j : e0j) * inv;
            float4 v = unpack_h4(*(const uint2*)(hsrc + (size_t)sj * 64 + lane * 2));
            acc.x += wj * v.x; acc.y += wj * v.y;
            acc.z += wj * v.z; acc.w += wj * v.w;
        }
    }
    uint2 ov;
    ov.x = pack_half2(acc.x, acc.y);
    ov.y = pack_half2(acc.z, acc.w);
    *(uint2*)(cb.outp[t] + (size_t)node * 64 + lane * 2) = ov;
}

// ---------------------------------------------------------------------------
// Semantic attention tail + MLP
// ---------------------------------------------------------------------------
__global__ void softmax2_kernel(double* __restrict__ sc,
                                float* __restrict__ w, double invN)
{
    double s0 = sc[0] * invN, s1 = sc[1] * invN;
    double mx = s0 > s1 ? s0 : s1;
    double e0 = exp(s0 - mx), e1 = exp(s1 - mx);
    double sum = e0 + e1;
    w[0] = (float)(e0 / sum);
    w[1] = (float)(e1 / sum);
    sc[0] = 0.0; sc[1] = 0.0;
}

__global__ __launch_bounds__(256) void precompute_kernel(
    const float* __restrict__ Wl1, const float* __restrict__ bl1,
    const float* __restrict__ Wl2, const float* __restrict__ bl2,
    const float* __restrict__ Wl3, const float* __restrict__ bl3,
    float* __restrict__ W123, float* __restrict__ bfin,
    double* __restrict__ score)
{
    __shared__ float W23[256 * 8];
    __shared__ float t1s[128];
    int tid = threadIdx.x;
    if (tid < 2) score[tid] = 0.0;
    for (int i = tid; i < 2048; i += 256) {
        int r = i >> 3, j = i & 7;
        float a = 0.f;
        for (int c = 0; c < 128; c++) a += Wl2[r * 128 + c] * Wl3[c * 8 + j];
        W23[i] = a;
    }
    for (int n = tid; n < 128; n += 256) {
        float a = bl2[n];
        for (int k = 0; k < 256; k++) a += bl1[k] * Wl2[k * 128 + n];
        t1s[n] = a;
    }
    __syncthreads();
    for (int i = tid; i < 1024; i += 256) {
        int k = i >> 3, j = i & 7;
        float a = 0.f;
        for (int r = 0; r < 256; r++) a += Wl1[k * 256 + r] * W23[r * 8 + j];
        W123[i] = a;
    }
    if (tid < 8) {
        float a = bl3[tid];
        for (int c = 0; c < 128; c++) a += t1s[c] * Wl3[c * 8 + tid];
        bfin[tid] = a;
    }
}

__global__ __launch_bounds__(256) void mlp_final_kernel(
    const uint32_t* __restrict__ o0, const uint32_t* __restrict__ o1,
    const float* __restrict__ wbuf, const float* __restrict__ W123,
    const float* __restrict__ bfin, float* __restrict__ out, int No)
{
    __shared__ float Ws[128 * 8];
    __shared__ float bs[8];
    for (int i = threadIdx.x; i < 128 * 8; i += blockDim.x) Ws[i] = W123[i];
    if (threadIdx.x < 8) bs[threadIdx.x] = bfin[threadIdx.x];
    __syncthreads();
    float w0 = wbuf[0], w1 = wbuf[1];
    int gid = blockIdx.x * blockDim.x + threadIdx.x;
    int row = gid >> 3, j = gid & 7;
    if (row >= No) return;
    const uint32_t* r0 = o0 + (size_t)row * 64;
    const uint32_t* r1 = o1 + (size_t)row * 64;
    float acc = 0.f;
#pragma unroll
    for (int k = 0; k < 128; k += 4) {
        float4 a = unpack_h4(*(const uint2*)(r0 + (k >> 1)));
        float4 b = unpack_h4(*(const uint2*)(r1 + (k >> 1)));
        float x0 = w0 * fmaxf(a.x, 0.f) + w1 * fmaxf(b.x, 0.f);
        float x1 = w0 * fmaxf(a.y, 0.f) + w1 * fmaxf(b.y, 0.f);
        float x2 = w0 * fmaxf(a.z, 0.f) + w1 * fmaxf(b.z, 0.f);
        float x3 = w0 * fmaxf(a.w, 0.f) + w1 * fmaxf(b.w, 0.f);
        acc += x0 * Ws[(k + 0) * 8 + j];
        acc += x1 * Ws[(k + 1) * 8 + j];
        acc += x2 * Ws[(k + 2) * 8 + j];
        acc += x3 * Ws[(k + 3) * 8 + j];
    }
    float x = acc + bs[j];
    out[(size_t)row * 8 + j] = 1.f / (1.f + expf(-x));
}

// ---------------------------------------------------------------------------
// Host orchestration
// ---------------------------------------------------------------------------
static inline int ceil_div(int a, int b) { return (a + b - 1) / b; }

extern "C" void kernel_launch(void* const* d_in, const int* in_sizes, int n_in,
                              void* d_out, int out_size)
{
    const float* xo  = (const float*)d_in[0];
    const float* xa  = (const float*)d_in[1];
    const int*   eoo = (const int*)d_in[2];
    const int*   eoa = (const int*)d_in[3];
    const int*   eao = (const int*)d_in[4];
    const int No  = in_sizes[0] / 128;
    const int Na  = in_sizes[1] / 128;
    const int Eoo = in_sizes[2] / 2;
    const int Eoa = in_sizes[3] / 2;
    const int Eao = in_sizes[4] / 2;

    float *pobj, *patt, *w, *W123, *bfin;
    uint32_t *ho16, *ha16, *o0, *o1, *oa;
    int *cnt, *rowptr, *csrc, *bsum;
    double* score;
    cudaGetSymbolAddress((void**)&ho16,   g_ho16);
    cudaGetSymbolAddress((void**)&ha16,   g_ha16);
    cudaGetSymbolAddress((void**)&o0,     g_o0);
    cudaGetSymbolAddress((void**)&o1,     g_o1);
    cudaGetSymbolAddress((void**)&oa,     g_oa);
    cudaGetSymbolAddress((void**)&pobj,   g_pobj);
    cudaGetSymbolAddress((void**)&patt,   g_patt);
    cudaGetSymbolAddress((void**)&score,  g_score);
    cudaGetSymbolAddress((void**)&w,      g_w);
    cudaGetSymbolAddress((void**)&W123,   g_W123);
    cudaGetSymbolAddress((void**)&bfin,   g_bfin);
    cudaGetSymbolAddress((void**)&cnt,    g_cnt);
    cudaGetSymbolAddress((void**)&rowptr, g_rowptr);
    cudaGetSymbolAddress((void**)&csrc,   g_csrc);
    cudaGetSymbolAddress((void**)&bsum,   g_bsum);

    const int FEAT_SMEM = 32768;
    cudaFuncSetAttribute(mma_feat2_kernel,
                         cudaFuncAttributeMaxDynamicSharedMemorySize, FEAT_SMEM);

    const int tilesNo = ceil_div(No, 128);
    const int maxE = (Eoo > Eao ? (Eoo > Eoa ? Eoo : Eoa) : (Eao > Eoa ? Eao : Eoa));

    // ---- CSR build (types: 0=oo, 1=ao, 2=oa) ----
    const int* dst0 = eoo + Eoo;
    const int* dst1 = eao + Eao;
    const int* dst2 = eoa + Eoa;
    cudaMemsetAsync(cnt, 0, 3 * MAXNO * sizeof(int));
    hist_kernel<<<dim3(ceil_div(maxE, 256), 3), 256>>>(
        dst0, dst1, dst2, Eoo, Eao, Eoa, cnt);
    blocksum_kernel<<<dim3(NBMAX, 3), 256>>>(cnt, bsum, No, No, Na);
    scanb_kernel<<<1, NBMAX>>>(bsum, rowptr, No, No, Na, Eoo, Eao, Eoa);
    scanc_kernel<<<dim3(ceil_div(No, 1024), 3), 256>>>(cnt, bsum, rowptr, No, No, Na);
    scatter_kernel<<<dim3(ceil_div(maxE, 256), 3), 256>>>(
        eoo, dst0, eao, dst1, eoa, dst2, Eoo, Eao, Eoa, rowptr, cnt, csrc);

    precompute_kernel<<<1, 256>>>(
        (const float*)d_in[23], (const float*)d_in[24], (const float*)d_in[25],
        (const float*)d_in[26], (const float*)d_in[27], (const float*)d_in[28],
        W123, bfin, score);

    for (int layer = 0; layer < 2; layer++) {
        const int base = 5 + 9 * layer;
        const float* Wo   = (const float*)d_in[base + 0];
        const float* bo   = (const float*)d_in[base + 1];
        const float* Wa   = (const float*)d_in[base + 2];
        const float* ba   = (const float*)d_in[base + 3];
        const float* asrc = (const float*)d_in[base + 4];
        const float* adst = (const float*)d_in[base + 5];
        const float* Wk   = (const float*)d_in[base + 6];
        const float* bk   = (const float*)d_in[base + 7];
        const float* q    = (const float*)d_in[base + 8];

        FeatPair fp;
        fp.wbuf = w;
        fp.W[0] = Wo; fp.bias[0] = bo; fp.C[0] = ho16; fp.proj[0] = pobj;
        fp.M[0] = No; fp.nv[0] = 4;
        fp.v[0][0] = asrc + 0;   fp.v[0][1] = asrc + 128;
        fp.v[0][2] = adst + 0;   fp.v[0][3] = adst + 256;
        fp.W[1] = Wa; fp.bias[1] = ba; fp.C[1] = ha16; fp.proj[1] = patt;
        fp.M[1] = Na; fp.nv[1] = 2;
        fp.v[1][0] = asrc + 256; fp.v[1][1] = adst + 128;
        fp.v[1][2] = asrc;       fp.v[1][3] = asrc;
        if (layer == 0) {
            fp.A[0] = xo; fp.A16[0] = o0; fp.A16b[0] = o1; fp.mode[0] = 0;
            fp.A[1] = xa; fp.A16[1] = oa; fp.A16b[1] = oa; fp.mode[1] = 0;
        } else {
            fp.A[0] = xo; fp.A16[0] = o0; fp.A16b[0] = o1; fp.mode[0] = 2;
            fp.A[1] = xa; fp.A16[1] = oa; fp.A16b[1] = oa; fp.mode[1] = 1;
        }
        mma_feat2_kernel<<<dim3(tilesNo, 2), 256, FEAT_SMEM>>>(fp);

        const int ntypes = (layer == 0) ? 3 : 2;

        CsrBatch cb;
        cb.csrc[0] = csrc;               cb.rowptr[0] = rowptr;
        cb.psrc[0] = pobj + 0;           cb.pdst[0] = pobj + (size_t)2 * No * 2;
        cb.hsrc[0] = ho16;               cb.outp[0] = o0;  cb.N[0] = No;
        cb.csrc[1] = csrc + MAXE;        cb.rowptr[1] = rowptr + (MAXNO + 1);
        cb.psrc[1] = patt + 0;           cb.pdst[1] = pobj + (size_t)3 * No * 2;
        cb.hsrc[1] = ha16;               cb.outp[1] = o1;  cb.N[1] = No;
        cb.csrc[2] = csrc + 2 * MAXE;    cb.rowptr[2] = rowptr + 2 * (MAXNO + 1);
        cb.psrc[2] = pobj + (size_t)1 * No * 2;
        cb.pdst[2] = patt + (size_t)1 * Na * 2;
        cb.hsrc[2] = ho16;               cb.outp[2] = oa;
        cb.N[2] = (layer == 0) ? Na : 0;

        edge_fused_kernel<<<dim3(ceil_div(No * 32, 256), ntypes), 256>>>(cb);

        mma_score_kernel<<<dim3(tilesNo, 2), 256>>>(o0, o1, Wk, bk, q, No, score);
        softmax2_kernel<<<1, 1>>>(score, w, 1.0 / (double)No);
    }

    mlp_final_kernel<<<ceil_div(No * 8, 256), 256>>>(
        o0, o1, w, W123, bfin, (float*)d_out, No);
}